// round 9
// baseline (speedup 1.0000x reference)
#include <cuda_runtime.h>
#include <cuda_bf16.h>
#include <cstdint>
#include <cstddef>

// ---------------------------------------------------------------------------
// Problem constants
// ---------------------------------------------------------------------------
#define cB 32
#define cS 2304
#define cD 1280
#define cDEPTH 6
#define cH 16
#define cHD 96
#define cL 64
#define cI 5120
#define cT (cS + cL)      /* 2368 */
#define cHHD (cH * cHD)   /* 1536 */
#define cEPS 1e-5f
#define cMCTX (cB * cS)   /* 73728 ctx rows */
#define cML (cB * cL)     /* 2048 latent rows */

typedef __nv_bfloat16 bf16;

// ---------------------------------------------------------------------------
// Scratch (device globals: allocation-free rule)
// ---------------------------------------------------------------------------
__device__ bf16 g_ctx_hi[(size_t)cMCTX * cD];
__device__ bf16 g_ctx_lo[(size_t)cMCTX * cD];
__device__ bf16 g_latln_hi[cML * cD];
__device__ bf16 g_latln_lo[cML * cD];
__device__ bf16 g_att_hi[cML * cHHD];
__device__ bf16 g_att_lo[cML * cHHD];
__device__ bf16 g_mlp_hi[(size_t)cML * cI];
__device__ bf16 g_mlp_lo[(size_t)cML * cI];
__device__ bf16 g_Q_hi[cML * cHHD], g_Q_lo[cML * cHHD];
__device__ bf16 g_K_hi[(size_t)cB * cT * cHHD], g_K_lo[(size_t)cB * cT * cHHD];
__device__ bf16 g_V_hi[(size_t)cB * cT * cHHD], g_V_lo[(size_t)cB * cT * cHHD];
__device__ bf16 g_P_hi[(size_t)cB * cH * cL * cT];
__device__ bf16 g_P_lo[(size_t)cB * cH * cL * cT];
__device__ bf16 g_wq_hi[cHHD * cD],  g_wq_lo[cHHD * cD];
__device__ bf16 g_wkc_hi[cHHD * cD], g_wkc_lo[cHHD * cD];
__device__ bf16 g_wkl_hi[cHHD * cD], g_wkl_lo[cHHD * cD];
__device__ bf16 g_wvc_hi[cHHD * cD], g_wvc_lo[cHHD * cD];
__device__ bf16 g_wvl_hi[cHHD * cD], g_wvl_lo[cHHD * cD];
__device__ bf16 g_wo_hi[cD * cHHD],  g_wo_lo[cD * cHHD];
__device__ bf16 g_wfc_hi[(size_t)cI * cD], g_wfc_lo[(size_t)cI * cD];
__device__ bf16 g_wcp_hi[(size_t)cD * cI], g_wcp_lo[(size_t)cD * cI];
__device__ float g_biasQ[cHHD], g_biasKc[cHHD], g_biasKl[cHHD];
__device__ float g_biasVc[cHHD], g_biasVl[cHHD], g_biasFc[cI];
__device__ float g_lat[cML * cD];
__device__ float g_Q[cML * cHHD];
__device__ float g_K[(size_t)cB * cT * cHHD];
__device__ float g_scores[(size_t)cB * cH * cL * cT];

// ---------------------------------------------------------------------------
// MMA helpers (base-PTX: ldmatrix + mma.sync, sm_80+)
// ---------------------------------------------------------------------------
__device__ __forceinline__ uint32_t smem_u32(const void* p) {
  uint32_t a;
  asm("{ .reg .u64 t; cvta.to.shared.u64 t, %1; cvt.u32.u64 %0, t; }"
      : "=r"(a) : "l"(p));
  return a;
}
__device__ __forceinline__ void cp_async16(uint32_t saddr, const void* gptr) {
  asm volatile("cp.async.cg.shared.global [%0], [%1], 16;" ::"r"(saddr),
               "l"(gptr)
               : "memory");
}
#define CP_COMMIT() asm volatile("cp.async.commit_group;" ::: "memory")
#define CP_WAIT(N) asm volatile("cp.async.wait_group %0;" ::"n"(N) : "memory")

__device__ __forceinline__ void ldsm_x4(uint32_t* d, uint32_t addr) {
  asm volatile("ldmatrix.sync.aligned.m8n8.x4.shared.b16 {%0,%1,%2,%3},[%4];"
               : "=r"(d[0]), "=r"(d[1]), "=r"(d[2]), "=r"(d[3])
               : "r"(addr));
}
__device__ __forceinline__ void ldsm_x2(uint32_t* d, uint32_t addr) {
  asm volatile("ldmatrix.sync.aligned.m8n8.x2.shared.b16 {%0,%1},[%2];"
               : "=r"(d[0]), "=r"(d[1])
               : "r"(addr));
}
__device__ __forceinline__ void ldsm_x2_trans(uint32_t* d, uint32_t addr) {
  asm volatile("ldmatrix.sync.aligned.m8n8.x2.trans.shared.b16 {%0,%1},[%2];"
               : "=r"(d[0]), "=r"(d[1])
               : "r"(addr));
}
__device__ __forceinline__ void mma16816(float* c, const uint32_t* a,
                                         const uint32_t* b) {
  asm volatile(
      "mma.sync.aligned.m16n8k16.row.col.f32.bf16.bf16.f32 "
      "{%0,%1,%2,%3},{%4,%5,%6,%7},{%8,%9},{%0,%1,%2,%3};"
      : "+f"(c[0]), "+f"(c[1]), "+f"(c[2]), "+f"(c[3])
      : "r"(a[0]), "r"(a[1]), "r"(a[2]), "r"(a[3]), "r"(b[0]), "r"(b[1]));
}

// Fast exp on the FMA pipe (degree-6 2^f poly; rel err ~8e-6).
__device__ __forceinline__ float fexp(float x) {
  x = fmaxf(x, -87.0f);
  float t = x * 1.4426950408889634f;
  float fi = floorf(t);
  float f = t - fi;
  float p = 1.54035304e-4f;
  p = fmaf(p, f, 1.33335581e-3f);
  p = fmaf(p, f, 9.61812911e-3f);
  p = fmaf(p, f, 5.55041087e-2f);
  p = fmaf(p, f, 2.40226507e-1f);
  p = fmaf(p, f, 6.93147181e-1f);
  p = fmaf(p, f, 1.0f);
  int i = (int)fi;
  return p * __int_as_float((i + 127) << 23);
}

// ---------------------------------------------------------------------------
// Fused K+V bf16-split GEMM (R6 inner structure — B via ldsm_x2 interleaved)
// ---------------------------------------------------------------------------
#define FK_BK 32
#define FK_NC (cD / FK_BK) /* 40 */
#define FK_STRIDE 40
#define FK_ARR (128 * FK_STRIDE * 2) /* 10240 */
#define FK_STAGE (6 * FK_ARR)        /* 61440 */
#define FK_SMEM (3 * FK_STAGE)       /* 184320 */

__global__ __launch_bounds__(512) void fused_kv_gemm(
    const bf16* __restrict__ Ahi, const bf16* __restrict__ Alo,
    const bf16* __restrict__ Bkh, const bf16* __restrict__ Bkl,
    const bf16* __restrict__ Bvh, const bf16* __restrict__ Bvl,
    const float* __restrict__ biasK, const float* __restrict__ biasV,
    float* __restrict__ Kout, bf16* __restrict__ Vhi, bf16* __restrict__ Vlo,
    int rpbIn, int rpbOut, int rowOff) {
  extern __shared__ char sm[];
  const uint32_t sb = smem_u32(sm);
  const int tid = threadIdx.x, lane = tid & 31, wid = tid >> 5;
  const int grp = wid >> 3;  // 0=K, 1=V
  const int gw = wid & 7;
  const int wm = gw & 1, wn = gw >> 1;
  const int m0 = blockIdx.y * 128, n0 = blockIdx.x * 128;

  const bf16* gA0 = Ahi + (size_t)m0 * cD;
  const bf16* gA1 = Alo + (size_t)m0 * cD;
  const bf16* gK0 = Bkh + (size_t)n0 * cD;
  const bf16* gK1 = Bkl + (size_t)n0 * cD;
  const bf16* gV0 = Bvh + (size_t)n0 * cD;
  const bf16* gV1 = Bvl + (size_t)n0 * cD;

  float acc[4][4][4];
#pragma unroll
  for (int mt = 0; mt < 4; mt++)
#pragma unroll
    for (int nt = 0; nt < 4; nt++)
#pragma unroll
      for (int j = 0; j < 4; j++) acc[mt][nt][j] = 0.f;

  const int lr = tid >> 2;
  const int lu = tid & 3;
  auto load_chunk = [&](int c, int buf) {
    int kk = c * FK_BK;
    uint32_t base = sb + buf * FK_STAGE;
    uint32_t so = lr * (FK_STRIDE * 2) + lu * 16;
    size_t go = (size_t)lr * cD + kk + lu * 8;
    cp_async16(base + 0 * FK_ARR + so, gA0 + go);
    cp_async16(base + 1 * FK_ARR + so, gA1 + go);
    cp_async16(base + 2 * FK_ARR + so, gK0 + go);
    cp_async16(base + 3 * FK_ARR + so, gK1 + go);
    cp_async16(base + 4 * FK_ARR + so, gV0 + go);
    cp_async16(base + 5 * FK_ARR + so, gV1 + go);
    CP_COMMIT();
  };

  load_chunk(0, 0);
  load_chunk(1, 1);

  const uint32_t aRow = (wm * 64 + (lane & 15)) * (FK_STRIDE * 2);
  const uint32_t aColB = ((lane >> 4) << 3) * 2;
  const uint32_t bRow = (wn * 32 + (lane & 7)) * (FK_STRIDE * 2);
  const uint32_t bColB = (((lane >> 3) & 1) << 3) * 2;
  const uint32_t bOff = (grp ? 4u : 2u) * FK_ARR;

  for (int c = 0; c < FK_NC; c++) {
    if (c + 1 < FK_NC) { CP_WAIT(1); } else { CP_WAIT(0); }
    __syncthreads();
    if (c + 2 < FK_NC) load_chunk(c + 2, (c + 2) % 3);
    uint32_t base = sb + (c % 3) * FK_STAGE;
#pragma unroll
    for (int ks = 0; ks < 2; ks++) {
      uint32_t kb = ks * 32;
      uint32_t ah[4][4], al[4][4];
#pragma unroll
      for (int mt = 0; mt < 4; mt++) {
        uint32_t ad = base + aRow + mt * 16 * (FK_STRIDE * 2) + kb + aColB;
        ldsm_x4(ah[mt], ad);
        ldsm_x4(al[mt], ad + FK_ARR);
      }
#pragma unroll
      for (int nt = 0; nt < 4; nt++) {
        uint32_t bd = base + bOff + bRow + nt * 8 * (FK_STRIDE * 2) + kb + bColB;
        uint32_t bh2[2], bl2[2];
        ldsm_x2(bh2, bd);
        ldsm_x2(bl2, bd + FK_ARR);
#pragma unroll
        for (int mt = 0; mt < 4; mt++) {
          mma16816(acc[mt][nt], ah[mt], bh2);
          mma16816(acc[mt][nt], ah[mt], bl2);
          mma16816(acc[mt][nt], al[mt], bh2);
        }
      }
    }
  }

#pragma unroll
  for (int mt = 0; mt < 4; mt++) {
    int mloc = wm * 64 + mt * 16 + (lane >> 2);
#pragma unroll
    for (int half = 0; half < 2; half++) {
      int m = m0 + mloc + half * 8;
      int orow = (m / rpbIn) * rpbOut + rowOff + (m % rpbIn);
#pragma unroll
      for (int nt = 0; nt < 4; nt++) {
        int n = n0 + wn * 32 + nt * 8 + (lane & 3) * 2;
        float v0 = acc[mt][nt][half * 2 + 0];
        float v1 = acc[mt][nt][half * 2 + 1];
        if (grp == 0) {
          v0 += biasK[n]; v1 += biasK[n + 1];
          *(float2*)(Kout + (size_t)orow * cHHD + n) = make_float2(v0, v1);
        } else {
          v0 += biasV[n]; v1 += biasV[n + 1];
          bf16 h0 = __float2bfloat16(v0), h1 = __float2bfloat16(v1);
          *(__nv_bfloat162*)(Vhi + (size_t)orow * cHHD + n) =
              __nv_bfloat162(h0, h1);
          *(__nv_bfloat162*)(Vlo + (size_t)orow * cHHD + n) = __nv_bfloat162(
              __float2bfloat16(v0 - __bfloat162float(h0)),
              __float2bfloat16(v1 - __bfloat162float(h1)));
        }
      }
    }
  }
}

// ---------------------------------------------------------------------------
// Generalized pipelined bf16-split MMA GEMM (R6 inner structure)
// ---------------------------------------------------------------------------
#define MG_BK 32
#define MG_STRIDE 40
#define MG_ARR (128 * MG_STRIDE * 2)
#define MG_BUF (4 * MG_ARR)
#define MG_SMEM (2 * MG_BUF)

__global__ __launch_bounds__(256) void mma_gemm_split(
    const bf16* __restrict__ Ahi, const bf16* __restrict__ Alo,
    const bf16* __restrict__ Bhi, const bf16* __restrict__ Blo,
    const float* __restrict__ bias, const float* __restrict__ R,
    float* __restrict__ C, bf16* __restrict__ Chi, bf16* __restrict__ Clo,
    int Kdim, int cN, int relu, int rpbIn, int rpbOut, int rowOff) {
  extern __shared__ char sm[];
  const uint32_t sb = smem_u32(sm);
  const int tid = threadIdx.x;
  const int lane = tid & 31, wid = tid >> 5;
  const int wm = wid & 1, wn = wid >> 1;
  const int m0 = blockIdx.y * 128, n0 = blockIdx.x * 128;
  const int nc = Kdim / MG_BK;

  const bf16* gA0 = Ahi + (size_t)m0 * Kdim;
  const bf16* gA1 = Alo + (size_t)m0 * Kdim;
  const bf16* gB0 = Bhi + (size_t)n0 * Kdim;
  const bf16* gB1 = Blo + (size_t)n0 * Kdim;

  float acc[4][4][4];
#pragma unroll
  for (int mt = 0; mt < 4; mt++)
#pragma unroll
    for (int nt = 0; nt < 4; nt++)
#pragma unroll
      for (int j = 0; j < 4; j++) acc[mt][nt][j] = 0.f;

  const int lr = tid >> 2;
  const int lu = tid & 3;
  auto load_chunk = [&](int c, int buf) {
    int kk = c * MG_BK;
    uint32_t base = sb + buf * MG_BUF;
#pragma unroll
    for (int j = 0; j < 2; j++) {
      int r = lr + j * 64;
      uint32_t so = r * (MG_STRIDE * 2) + lu * 16;
      size_t go = (size_t)r * Kdim + kk + lu * 8;
      cp_async16(base + 0 * MG_ARR + so, gA0 + go);
      cp_async16(base + 1 * MG_ARR + so, gA1 + go);
      cp_async16(base + 2 * MG_ARR + so, gB0 + go);
      cp_async16(base + 3 * MG_ARR + so, gB1 + go);
    }
    CP_COMMIT();
  };

  load_chunk(0, 0);

  const uint32_t aRow = (wm * 64 + (lane & 15)) * (MG_STRIDE * 2);
  const uint32_t aColB = ((lane >> 4) << 3) * 2;
  const uint32_t bRow = (wn * 32 + (lane & 7)) * (MG_STRIDE * 2);
  const uint32_t bColB = (((lane >> 3) & 1) << 3) * 2;

  for (int c = 0; c < nc; c++) {
    int buf = c & 1;
    if (c + 1 < nc) {
      load_chunk(c + 1, buf ^ 1);
      CP_WAIT(1);
    } else {
      CP_WAIT(0);
    }
    __syncthreads();
    uint32_t base = sb + buf * MG_BUF;
#pragma unroll
    for (int ks = 0; ks < 2; ks++) {
      uint32_t kb = ks * 32;
      uint32_t ah[4][4], al[4][4], bh[4][2], bl[4][2];
#pragma unroll
      for (int mt = 0; mt < 4; mt++) {
        uint32_t ad = base + aRow + mt * 16 * (MG_STRIDE * 2) + kb + aColB;
        ldsm_x4(ah[mt], ad);
        ldsm_x4(al[mt], ad + MG_ARR);
      }
#pragma unroll
      for (int nt = 0; nt < 4; nt++) {
        uint32_t bd =
            base + 2 * MG_ARR + bRow + nt * 8 * (MG_STRIDE * 2) + kb + bColB;
        ldsm_x2(bh[nt], bd);
        ldsm_x2(bl[nt], bd + MG_ARR);
      }
#pragma unroll
      for (int mt = 0; mt < 4; mt++)
#pragma unroll
        for (int nt = 0; nt < 4; nt++) {
          mma16816(acc[mt][nt], ah[mt], bh[nt]);
          mma16816(acc[mt][nt], ah[mt], bl[nt]);
          mma16816(acc[mt][nt], al[mt], bh[nt]);
        }
    }
    __syncthreads();
  }

#pragma unroll
  for (int mt = 0; mt < 4; mt++) {
    int mloc = wm * 64 + mt * 16 + (lane >> 2);
#pragma unroll
    for (int half = 0; half < 2; half++) {
      int m = m0 + mloc + half * 8;
      int orow = (m / rpbIn) * rpbOut + rowOff + (m % rpbIn);
#pragma unroll
      for (int nt = 0; nt < 4; nt++) {
        int n = n0 + wn * 32 + nt * 8 + (lane & 3) * 2;
        float v0 = acc[mt][nt][half * 2 + 0];
        float v1 = acc[mt][nt][half * 2 + 1];
        if (bias != nullptr) { v0 += bias[n]; v1 += bias[n + 1]; }
        if (R != nullptr) {
          float2 rv = *(const float2*)(R + (size_t)orow * cN + n);
          v0 += rv.x; v1 += rv.y;
        }
        if (relu) { v0 = fmaxf(v0, 0.f); v1 = fmaxf(v1, 0.f); }
        if (C != nullptr)
          *(float2*)(C + (size_t)orow * cN + n) = make_float2(v0, v1);
        if (Chi != nullptr) {
          bf16 h0 = __float2bfloat16(v0);
          bf16 h1 = __float2bfloat16(v1);
          *(__nv_bfloat162*)(Chi + (size_t)orow * cN + n) =
              __nv_bfloat162(h0, h1);
          *(__nv_bfloat162*)(Clo + (size_t)orow * cN + n) = __nv_bfloat162(
              __float2bfloat16(v0 - __bfloat162float(h0)),
              __float2bfloat16(v1 - __bfloat162float(h1)));
        }
      }
    }
  }
}

// ---------------------------------------------------------------------------
// Attention scores on MMA
// ---------------------------------------------------------------------------
#define SCM_STRIDE 104
#define SCM_ARR (64 * SCM_STRIDE * 2)
#define SCM_SMEM (4 * SCM_ARR)
__global__ __launch_bounds__(256) void attn_scores_mma(
    const bf16* __restrict__ Qh, const bf16* __restrict__ Ql,
    const bf16* __restrict__ Kh, const bf16* __restrict__ Kl,
    float* __restrict__ Sc) {
  extern __shared__ char sm[];
  const uint32_t sb = smem_u32(sm);
  const int tid = threadIdx.x, lane = tid & 31, wid = tid >> 5;
  const int bh = blockIdx.y, b = bh >> 4, h = bh & 15;
  const int t0 = blockIdx.x * 64;

#pragma unroll
  for (int it = 0; it < 3; it++) {
    int e = tid + it * 256;
    int r = e / 12, u = e % 12;
    uint32_t so = r * (SCM_STRIDE * 2) + u * 16;
    size_t qo = (size_t)(b * cL + r) * cHHD + h * cHD + u * 8;
    size_t ko = (size_t)(b * cT + t0 + r) * cHHD + h * cHD + u * 8;
    *(uint4*)(sm + 0 * SCM_ARR + so) = *(const uint4*)(Qh + qo);
    *(uint4*)(sm + 1 * SCM_ARR + so) = *(const uint4*)(Ql + qo);
    *(uint4*)(sm + 2 * SCM_ARR + so) = *(const uint4*)(Kh + ko);
    *(uint4*)(sm + 3 * SCM_ARR + so) = *(const uint4*)(Kl + ko);
  }
  __syncthreads();

  const int wm = wid & 1, wn = wid >> 1;
  float acc[2][2][4];
#pragma unroll
  for (int mt = 0; mt < 2; mt++)
#pragma unroll
    for (int nt = 0; nt < 2; nt++)
#pragma unroll
      for (int j = 0; j < 4; j++) acc[mt][nt][j] = 0.f;

#pragma unroll
  for (int ks = 0; ks < 6; ks++) {
    uint32_t kb = ks * 32;
    uint32_t ah[2][4], al[2][4], bh2[2][2], bl2[2][2];
#pragma unroll
    for (int mt = 0; mt < 2; mt++) {
      uint32_t ad = sb + (wm * 32 + mt * 16 + (lane & 15)) * (SCM_STRIDE * 2) +
                    kb + (lane >> 4) * 16;
      ldsm_x4(ah[mt], ad);
      ldsm_x4(al[mt], ad + SCM_ARR);
    }
#pragma unroll
    for (int nt = 0; nt < 2; nt++) {
      uint32_t bd = sb + 2 * SCM_ARR +
                    (wn * 16 + nt * 8 + (lane & 7)) * (SCM_STRIDE * 2) + kb +
                    ((lane >> 3) & 1) * 16;
      ldsm_x2(bh2[nt], bd);
      ldsm_x2(bl2[nt], bd + SCM_ARR);
    }
#pragma unroll
    for (int mt = 0; mt < 2; mt++)
#pragma unroll
      for (int nt = 0; nt < 2; nt++) {
        mma16816(acc[mt][nt], ah[mt], bh2[nt]);
        mma16816(acc[mt][nt], ah[mt], bl2[nt]);
        mma16816(acc[mt][nt], al[mt], bh2[nt]);
      }
  }

  const float scale = 0.102062072615966f;
#pragma unroll
  for (int mt = 0; mt < 2; mt++)
#pragma unroll
    for (int half = 0; half < 2; half++) {
      int row = wm * 32 + mt * 16 + (lane >> 2) + half * 8;
#pragma unroll
      for (int nt = 0; nt < 2; nt++) {
        int col = t0 + wn * 16 + nt * 8 + (lane & 3) * 2;
        *(float2*)(Sc + ((size_t)bh * cL + row) * cT + col) =
            make_float2(acc[mt][nt][half * 2] * scale,
                        acc[mt][nt][half * 2 + 1] * scale);
      }
    }
}

// ---------------------------------------------------------------------------
// Row softmax -> P bf16 hi/lo. Register-resident, polynomial exp.
// ---------------------------------------------------------------------------
__global__ void softmax_split_kernel(const float* __restrict__ Sc,
                                     bf16* __restrict__ Ph,
                                     bf16* __restrict__ Pl) {
  const float* x = Sc + (size_t)blockIdx.x * cT;
  bf16* ph = Ph + (size_t)blockIdx.x * cT;
  bf16* pl = Pl + (size_t)blockIdx.x * cT;
  int tid = threadIdx.x;
  __shared__ float sh[32];
  __shared__ float bc;
  float v[10];
  float m = -1e30f;
#pragma unroll
  for (int k = 0; k < 10; k++) {
    int c = k * 256 + tid;
    if (c < cT) {
      v[k] = x[c];
      m = fmaxf(m, v[k]);
    } else {
      v[k] = -1e30f;
    }
  }
  for (int o = 16; o; o >>= 1) m = fmaxf(m, __shfl_xor_sync(~0u, m, o));
  int w = tid >> 5, lane = tid & 31;
  if (lane == 0) sh[w] = m;
  __syncthreads();
  if (w == 0) {
    m = (lane < 8) ? sh[lane] : -1e30f;
    for (int o = 16; o; o >>= 1) m = fmaxf(m, __shfl_xor_sync(~0u, m, o));
    if (lane == 0) bc = m;
  }
  __syncthreads();
  m = bc;
  float s = 0.f;
#pragma unroll
  for (int k = 0; k < 10; k++) {
    if (k * 256 + tid < cT) {
      v[k] = fexp(v[k] - m);
      s += v[k];
    }
  }
  for (int o = 16; o; o >>= 1) s += __shfl_xor_sync(~0u, s, o);
  __syncthreads();
  if (lane == 0) sh[w] = s;
  __syncthreads();
  if (w == 0) {
    s = (lane < 8) ? sh[lane] : 0.f;
    for (int o = 16; o; o >>= 1) s += __shfl_xor_sync(~0u, s, o);
    if (lane == 0) bc = 1.f / s;
  }
  __syncthreads();
  float inv = bc;
#pragma unroll
  for (int k = 0; k < 10; k++) {
    int c = k * 256 + tid;
    if (c < cT) {
      float p = v[k] * inv;
      bf16 hh = __float2bfloat16(p);
      ph[c] = hh;
      pl[c] = __float2bfloat16(p - __bfloat162float(hh));
    }
  }
}

// ---------------------------------------------------------------------------
// AV on MMA
// ---------------------------------------------------------------------------
#define AV_PSTR 72
#define AV_VSTR 104
#define AV_PARR (64 * AV_PSTR * 2)
#define AV_VARR (64 * AV_VSTR * 2)
#define AV_STAGE (2 * AV_PARR + 2 * AV_VARR)
#define AV_SMEM (2 * AV_STAGE)
__global__ __launch_bounds__(256) void attn_av_mma(
    const bf16* __restrict__ Ph, const bf16* __restrict__ Pl,
    const bf16* __restrict__ Vh, const bf16* __restrict__ Vl,
    bf16* __restrict__ Ohi, bf16* __restrict__ Olo) {
  extern __shared__ char sm[];
  const uint32_t sb = smem_u32(sm);
  const int tid = threadIdx.x, lane = tid & 31, wid = tid >> 5;
  const int bh = blockIdx.x, b = bh >> 4, h = bh & 15;
  const int wm = wid >> 1, wn = wid & 1;

  auto load_chunk = [&](int ct, int buf) {
    int t0 = ct * 64;
    uint32_t base = sb + buf * AV_STAGE;
#pragma unroll
    for (int it = 0; it < 2; it++) {
      int e = tid + it * 256;
      int r = e >> 3, u = e & 7;
      uint32_t so = r * (AV_PSTR * 2) + u * 16;
      size_t po = (size_t)(bh * cL + r) * cT + t0 + u * 8;
      cp_async16(base + so, Ph + po);
      cp_async16(base + AV_PARR + so, Pl + po);
    }
#pragma unroll
    for (int it = 0; it < 3; it++) {
      int e = tid + it * 256;
      int r = e / 12, u = e % 12;
      uint32_t so = r * (AV_VSTR * 2) + u * 16;
      size_t vo = (size_t)(b * cT + t0 + r) * cHHD + h * cHD + u * 8;
      cp_async16(base + 2 * AV_PARR + so, Vh + vo);
      cp_async16(base + 2 * AV_PARR + AV_VARR + so, Vl + vo);
    }
    CP_COMMIT();
  };

  float acc[6][4];
#pragma unroll
  for (int nt = 0; nt < 6; nt++)
#pragma unroll
    for (int j = 0; j < 4; j++) acc[nt][j] = 0.f;

  load_chunk(0, 0);
  for (int ct = 0; ct < 37; ct++) {
    int buf = ct & 1;
    if (ct + 1 < 37) {
      load_chunk(ct + 1, buf ^ 1);
      CP_WAIT(1);
    } else {
      CP_WAIT(0);
    }
    __syncthreads();
    uint32_t base = sb + buf * AV_STAGE;
#pragma unroll
    for (int ks = 0; ks < 4; ks++) {
      uint32_t kb = ks * 16;
      uint32_t ap[4], al[4];
      uint32_t aa = base + (wm * 16 + (lane & 15)) * (AV_PSTR * 2) + kb * 2 +
                    (lane >> 4) * 16;
      ldsm_x4(ap, aa);
      ldsm_x4(al, aa + AV_PARR);
#pragma unroll
      for (int nt = 0; nt < 6; nt++) {
        uint32_t ba = base + 2 * AV_PARR +
                      (kb + ((lane >> 3) & 1) * 8 + (lane & 7)) * (AV_VSTR * 2) +
                      (wn * 48 + nt * 8) * 2;
        uint32_t bv[2], blv[2];
        ldsm_x2_trans(bv, ba);
        ldsm_x2_trans(blv, ba + AV_VARR);
        mma16816(acc[nt], ap, bv);
        mma16816(acc[nt], ap, blv);
        mma16816(acc[nt], al, bv);
      }
    }
    __syncthreads();
  }

#pragma unroll
  for (int half = 0; half < 2; half++) {
    int row = b * cL + wm * 16 + (lane >> 2) + half * 8;
#pragma unroll
    for (int nt = 0; nt < 6; nt++) {
      int col = h * cHD + wn * 48 + nt * 8 + (lane & 3) * 2;
      float v0 = acc[nt][half * 2], v1 = acc[nt][half * 2 + 1];
      bf16 h0 = __float2bfloat16(v0), h1 = __float2bfloat16(v1);
      *(__nv_bfloat162*)(Ohi + (size_t)row * cHHD + col) = __nv_bfloat162(h0, h1);
      *(__nv_bfloat162*)(Olo + (size_t)row * cHHD + col) = __nv_bfloat162(
          __float2bfloat16(v0 - __bfloat162float(h0)),
          __float2bfloat16(v1 - __bfloat162float(h1)));
    }
  }
}

// ---------------------------------------------------------------------------
// LN (no affine) + bf16 hi/lo split
// ---------------------------------------------------------------------------
__global__ void ln_split_kernel(const float* __restrict__ x,
                                bf16* __restrict__ hi, bf16* __restrict__ lo) {
  int row = blockIdx.x;
  const float* xr = x + (size_t)row * cD;
  float s = 0.f, s2 = 0.f;
  for (int c = threadIdx.x; c < cD; c += 256) {
    float v = xr[c];
    s += v; s2 += v * v;
  }
  __shared__ float sh[64];
  for (int o = 16; o; o >>= 1) {
    s += __shfl_xor_sync(~0u, s, o);
    s2 += __shfl_xor_sync(~0u, s2, o);
  }
  int w = threadIdx.x >> 5, lane = threadIdx.x & 31;
  if (lane == 0) { sh[w] = s; sh[w + 32] = s2; }
  __syncthreads();
  if (w == 0) {
    s = (lane < 8) ? sh[lane] : 0.f;
    s2 = (lane < 8) ? sh[lane + 32] : 0.f;
    for (int o = 16; o; o >>= 1) {
      s += __shfl_xor_sync(~0u, s, o);
      s2 += __shfl_xor_sync(~0u, s2, o);
    }
    if (lane == 0) { sh[0] = s; sh[1] = s2; }
  }
  __syncthreads();
  float mean = sh[0] * (1.f / cD);
  float rstd = rsqrtf(sh[1] * (1.f / cD) - mean * mean + cEPS);
  for (int c = threadIdx.x; c < cD; c += 256) {
    float v = (xr[c] - mean) * rstd;
    bf16 h = __float2bfloat16(v);
    hi[(size_t)row * cD + c] = h;
    lo[(size_t)row * cD + c] = __float2bfloat16(v - __bfloat162float(h));
  }
}

// ---------------------------------------------------------------------------
// Weight prep
// ---------------------------------------------------------------------------
__global__ void wprep_kernel(const float* __restrict__ W,
                             const float* __restrict__ g,
                             const float* __restrict__ b,
                             bf16* __restrict__ Whi, bf16* __restrict__ Wlo,
                             float* __restrict__ bias, int Kdim, int Nw) {
  int n = blockIdx.x;
  float bs = 0.f;
  for (int k = threadIdx.x; k < Kdim; k += 256) {
    float w = W[(size_t)k * Nw + n];
    float v = (g != nullptr) ? g[k] * w : w;
    bf16 h = __float2bfloat16(v);
    Whi[(size_t)n * Kdim + k] = h;
    Wlo[(size_t)n * Kdim + k] = __float2bfloat16(v - __bfloat162float(h));
    if (b != nullptr) bs += b[k] * w;
  }
  if (bias != nullptr) {
    __shared__ float sh[8];
    for (int o = 16; o; o >>= 1) bs += __shfl_xor_sync(~0u, bs, o);
    int w8 = threadIdx.x >> 5, lane = threadIdx.x & 31;
    if (lane == 0) sh[w8] = bs;
    __syncthreads();
    if (threadIdx.x == 0) {
      float t = 0.f;
      for (int i = 0; i < 8; i++) t += sh[i];
      bias[n] = t;
    }
  }
}

// ---------------------------------------------------------------------------
// Broadcast latents
// ---------------------------------------------------------------------------
__global__ void bcast_latents_kernel(const float* __restrict__ lat,
                                     float* __restrict__ out) {
  int idx = blockIdx.x * 256 + threadIdx.x;
  out[idx] = lat[idx % (cL * cD)];
}

// ---------------------------------------------------------------------------
// Final LayerNorm with affine
// ---------------------------------------------------------------------------
__global__ void ln_rows_kernel(const float* __restrict__ x,
                               float* __restrict__ y,
                               const float* __restrict__ g,
                               const float* __restrict__ b) {
  int row = blockIdx.x;
  const float* xr = x + (size_t)row * cD;
  float* yr = y + (size_t)row * cD;
  float s = 0.f, s2 = 0.f;
  for (int c = threadIdx.x; c < cD; c += 256) {
    float v = xr[c];
    s += v; s2 += v * v;
  }
  __shared__ float sh[64];
  for (int o = 16; o; o >>= 1) {
    s += __shfl_xor_sync(~0u, s, o);
    s2 += __shfl_xor_sync(~0u, s2, o);
  }
  int w = threadIdx.x >> 5, lane = threadIdx.x & 31;
  if (lane == 0) { sh[w] = s; sh[w + 32] = s2; }
  __syncthreads();
  if (w == 0) {
    s = (lane < 8) ? sh[lane] : 0.f;
    s2 = (lane < 8) ? sh[lane + 32] : 0.f;
    for (int o = 16; o; o >>= 1) {
      s += __shfl_xor_sync(~0u, s, o);
      s2 += __shfl_xor_sync(~0u, s2, o);
    }
    if (lane == 0) { sh[0] = s; sh[1] = s2; }
  }
  __syncthreads();
  float mean = sh[0] * (1.f / cD);
  float rstd = rsqrtf(sh[1] * (1.f / cD) - mean * mean + cEPS);
  for (int c = threadIdx.x; c < cD; c += 256)
    yr[c] = (xr[c] - mean) * rstd * g[c] + b[c];
}

// ---------------------------------------------------------------------------
// Per-head LN -> bf16 hi/lo
// ---------------------------------------------------------------------------
__global__ void ln_head_split_kernel(const float* __restrict__ x,
                                     const float* __restrict__ g,
                                     const float* __restrict__ b,
                                     bf16* __restrict__ hi,
                                     bf16* __restrict__ lo, int nrows) {
  int r = blockIdx.x * 4 + (threadIdx.x >> 5);
  if (r >= nrows) return;
  int lane = threadIdx.x & 31;
  const float* xr = x + (size_t)r * cHD;
  float v0 = xr[lane], v1 = xr[lane + 32], v2 = xr[lane + 64];
  float s = v0 + v1 + v2;
  float s2 = v0 * v0 + v1 * v1 + v2 * v2;
  for (int o = 16; o; o >>= 1) {
    s += __shfl_xor_sync(~0u, s, o);
    s2 += __shfl_xor_sync(~0u, s2, o);
  }
  float mean = s * (1.f / 96.f);
  float rstd = rsqrtf(s2 * (1.f / 96.f) - mean * mean + cEPS);
  float y0 = (v0 - mean) * rstd * g[lane] + b[lane];
  float y1 = (v1 - mean) * rstd * g[lane + 32] + b[lane + 32];
  float y2 = (v2 - mean) * rstd * g[lane + 64] + b[lane + 64];
  bf16* hr = hi + (size_t)r * cHD;
  bf16* lr = lo + (size_t)r * cHD;
  bf16 h0 = __float2bfloat16(y0), h1 = __float2bfloat16(y1),
       h2 = __float2bfloat16(y2);
  hr[lane] = h0; hr[lane + 32] = h1; hr[lane + 64] = h2;
  lr[lane] = __float2bfloat16(y0 - __bfloat162float(h0));
  lr[lane + 32] = __float2bfloat16(y1 - __bfloat162float(h1));
  lr[lane + 64] = __float2bfloat16(y2 - __bfloat162float(h2));
}

// ---------------------------------------------------------------------------
// Host orchestration
// ---------------------------------------------------------------------------
extern "C" void kernel_launch(void* const* d_in, const int* in_sizes, int n_in,
                              void* d_out, int out_size) {
  (void)in_sizes; (void)n_in; (void)out_size;
  const float* context = (const float*)d_in[0];
  const float* latents = (const float*)d_in[1];
  const float* ctx_g = (const float*)d_in[2];
  const float* ctx_b = (const float*)d_in[3];
  const float* lat_g = (const float*)d_in[4];
  const float* lat_b = (const float*)d_in[5];
  const float* q_g = (const float*)d_in[6];
  const float* q_b = (const float*)d_in[7];
  const float* k_g = (const float*)d_in[8];
  const float* k_b = (const float*)d_in[9];
  const float* Wq = (const float*)d_in[10];
  const float* Wk = (const float*)d_in[11];
  const float* Wv = (const float*)d_in[12];
  const float* Wo = (const float*)d_in[13];
  const float* mlp_g = (const float*)d_in[14];
  const float* mlp_b = (const float*)d_in[15];
  const float* Wfc = (const float*)d_in[16];
  const float* Wcp = (const float*)d_in[17];
  const float* f_g = (const float*)d_in[18];
  const float* f_b = (const float*)d_in[19];
  float* out = (float*)d_out;

#define SYM(var, sym) cudaGetSymbolAddress((void**)&var, sym)
  bf16 *ctxhi, *ctxlo, *lnhi, *lnlo, *atthi, *attlo, *mlphi, *mlplo;
  bf16 *qhi, *qlo, *khi, *klo, *vhi, *vlo, *phi, *plo;
  bf16 *wqh, *wql, *wkch, *wkcl, *wklh, *wkll, *wvch, *wvcl, *wvlh, *wvll,
      *woh, *wol, *wfch, *wfcl, *wcph, *wcpl;
  float *bQ, *bKc, *bKl, *bVc, *bVl, *bFc;
  float *lat, *Qp, *Kp, *Scp;
  SYM(ctxhi, g_ctx_hi); SYM(ctxlo, g_ctx_lo);
  SYM(lnhi, g_latln_hi); SYM(lnlo, g_latln_lo);
  SYM(atthi, g_att_hi); SYM(attlo, g_att_lo);
  SYM(mlphi, g_mlp_hi); SYM(mlplo, g_mlp_lo);
  SYM(qhi, g_Q_hi); SYM(qlo, g_Q_lo);
  SYM(khi, g_K_hi); SYM(klo, g_K_lo);
  SYM(vhi, g_V_hi); SYM(vlo, g_V_lo);
  SYM(phi, g_P_hi); SYM(plo, g_P_lo);
  SYM(wqh, g_wq_hi); SYM(wql, g_wq_lo);
  SYM(wkch, g_wkc_hi); SYM(wkcl, g_wkc_lo);
  SYM(wklh, g_wkl_hi); SYM(wkll, g_wkl_lo);
  SYM(wvch, g_wvc_hi); SYM(wvcl, g_wvc_lo);
  SYM(wvlh, g_wvl_hi); SYM(wvll, g_wvl_lo);
  SYM(woh, g_wo_hi); SYM(wol, g_wo_lo);
  SYM(wfch, g_wfc_hi); SYM(wfcl, g_wfc_lo);
  SYM(wcph, g_wcp_hi); SYM(wcpl, g_wcp_lo);
  SYM(bQ, g_biasQ); SYM(bKc, g_biasKc); SYM(bKl, g_biasKl);
  SYM(bVc, g_biasVc); SYM(bVl, g_biasVl); SYM(bFc, g_biasFc);
  SYM(lat, g_lat); SYM(Qp, g_Q); SYM(Kp, g_K); SYM(Scp, g_scores);
#undef SYM

  cudaFuncSetAttribute(mma_gemm_split,
                       cudaFuncAttributeMaxDynamicSharedMemorySize, MG_SMEM);
  cudaFuncSetAttribute(fused_kv_gemm,
                       cudaFuncAttributeMaxDynamicSharedMemorySize, FK_SMEM);
  cudaFuncSetAttribute(attn_scores_mma,
                       cudaFuncAttributeMaxDynamicSharedMemorySize, SCM_SMEM);
  cudaFuncSetAttribute(attn_av_mma,
                       cudaFuncAttributeMaxDynamicSharedMemorySize, AV_SMEM);

  auto mma = [&](const bf16* Ah, const bf16* Al, const bf16* Bh,
                 const bf16* Bl, const float* bias, const float* R, float* C,
                 bf16* Ch, bf16* Cl, int M, int N, int Kd, int relu, int rpbIn,
                 int rpbOut, int rowOff) {
    dim3 grid(N / 128, M / 128);
    mma_gemm_split<<<grid, 256, MG_SMEM>>>(Ah, Al, Bh, Bl, bias, R, C, Ch, Cl,
                                           Kd, N, relu, rpbIn, rpbOut, rowOff);
  };
  dim3 kvGridCtx(cHHD / 128, cMCTX / 128);
  dim3 kvGridLat(cHHD / 128, cML / 128);

  // launch 0: LN(context) -> bf16 hi/lo (once)
  ln_split_kernel<<<cMCTX, 256>>>(context, ctxhi, ctxlo);
  // launches 1,2: layer-0 ctx weight preps
  wprep_kernel<<<cHHD, 256>>>(Wk, ctx_g, ctx_b, wkch, wkcl, bKc, cD, cHHD);
  wprep_kernel<<<cHHD, 256>>>(Wv, ctx_g, ctx_b, wvch, wvcl, bVc, cD, cHHD);
  // launch 3: layer-0 fused ctx K+V projection  << ncu capture slot >>
  fused_kv_gemm<<<kvGridCtx, 512, FK_SMEM>>>(ctxhi, ctxlo, wkch, wkcl, wvch,
                                             wvcl, bKc, bVc, Kp, vhi, vlo, cS,
                                             cT, 0);
  bcast_latents_kernel<<<(cML * cD) / 256, 256>>>(latents, lat);

  for (int i = 0; i < cDEPTH; i++) {
    const float* Wq_i = Wq + (size_t)i * cD * cHHD;
    const float* Wk_i = Wk + (size_t)i * cD * cHHD;
    const float* Wv_i = Wv + (size_t)i * cD * cHHD;
    const float* Wo_i = Wo + (size_t)i * cHHD * cD;
    const float* Wfc_i = Wfc + (size_t)i * cD * cI;
    const float* Wcp_i = Wcp + (size_t)i * cI * cD;
    const float* lg = lat_g + i * cD;
    const float* lb = lat_b + i * cD;

    if (i > 0) {
      wprep_kernel<<<cHHD, 256>>>(Wk_i, ctx_g + i * cD, ctx_b + i * cD, wkch,
                                  wkcl, bKc, cD, cHHD);
      wprep_kernel<<<cHHD, 256>>>(Wv_i, ctx_g + i * cD, ctx_b + i * cD, wvch,
                                  wvcl, bVc, cD, cHHD);
      fused_kv_gemm<<<kvGridCtx, 512, FK_SMEM>>>(ctxhi, ctxlo, wkch, wkcl,
                                                 wvch, wvcl, bKc, bVc, Kp, vhi,
                                                 vlo, cS, cT, 0);
    }

    // LN(latents) -> normalized hi/lo (affine folded into weights)
    ln_split_kernel<<<cML, 256>>>(lat, lnhi, lnlo);

    wprep_kernel<<<cHHD, 256>>>(Wq_i, lg, lb, wqh, wql, bQ, cD, cHHD);
    wprep_kernel<<<cHHD, 256>>>(Wk_i, lg, lb, wklh, wkll, bKl, cD, cHHD);
    wprep_kernel<<<cHHD, 256>>>(Wv_i, lg, lb, wvlh, wvll, bVl, cD, cHHD);

    // Q (fp32 out for per-head LN)
    mma(lnhi, lnlo, wqh, wql, bQ, nullptr, Qp, nullptr, nullptr, cML, cHHD, cD,
        0, cML, cML, 0);
    // latent K+V rows, appended at offset cS
    fused_kv_gemm<<<kvGridLat, 512, FK_SMEM>>>(lnhi, lnlo, wklh, wkll, wvlh,
                                               wvll, bKl, bVl, Kp, vhi, vlo,
                                               cL, cT, cS);

    // per-head q/k LN -> hi/lo
    ln_head_split_kernel<<<(cML * cH) / 4, 128>>>(Qp, q_g + i * cHD,
                                                  q_b + i * cHD, qhi, qlo,
                                                  cML * cH);
    ln_head_split_kernel<<<(cB * cT * cH) / 4, 128>>>(Kp, k_g + i * cHD,
                                                      k_b + i * cHD, khi, klo,
                                                      cB * cT * cH);

    // attention on MMA
    attn_scores_mma<<<dim3(cT / 64, cB * cH), 256, SCM_SMEM>>>(qhi, qlo, khi,
                                                               klo, Scp);
    softmax_split_kernel<<<cB * cH * cL, 256>>>(Scp, phi, plo);
    attn_av_mma<<<cB * cH, 256, AV_SMEM>>>(phi, plo, vhi, vlo, atthi, attlo);

    // lat = att @ Wo + lat
    wprep_kernel<<<cD, 256>>>(Wo_i, nullptr, nullptr, woh, wol, nullptr, cHHD,
                              cD);
    mma(atthi, attlo, woh, wol, nullptr, lat, lat, nullptr, nullptr, cML, cD,
        cHHD, 0, cML, cML, 0);

    // MLP
    ln_split_kernel<<<cML, 256>>>(lat, lnhi, lnlo);
    wprep_kernel<<<cI, 256>>>(Wfc_i, mlp_g + i * cD, mlp_b + i * cD, wfch, wfcl,
                              bFc, cD, cI);
    mma(lnhi, lnlo, wfch, wfcl, bFc, nullptr, nullptr, mlphi, mlplo, cML, cI,
        cD, 1, cML, cML, 0);
    wprep_kernel<<<cD, 256>>>(Wcp_i, nullptr, nullptr, wcph, wcpl, nullptr, cI,
                              cD);
    mma(mlphi, mlplo, wcph, wcpl, nullptr, lat, lat, nullptr, nullptr, cML, cD,
        cI, 0, cML, cML, 0);
  }

  ln_rows_kernel<<<cML, 256>>>(lat, out, f_g, f_b);
}

// round 10
// speedup vs baseline: 1.1647x; 1.1647x over previous
#include <cuda_runtime.h>
#include <cuda_bf16.h>
#include <cstdint>
#include <cstddef>

// ---------------------------------------------------------------------------
// Problem constants
// ---------------------------------------------------------------------------
#define cB 32
#define cS 2304
#define cD 1280
#define cDEPTH 6
#define cH 16
#define cHD 96
#define cL 64
#define cI 5120
#define cT (cS + cL)      /* 2368 */
#define cHHD (cH * cHD)   /* 1536 */
#define cEPS 1e-5f
#define cMCTX (cB * cS)   /* 73728 ctx rows */
#define cML (cB * cL)     /* 2048 latent rows */
#define cMB (cMCTX / 128) /* 576 ctx row-blocks */
#define cNB (cHHD / 128)  /* 12 weight col-blocks */
#define cNCC (cD / 32)    /* 40 k-chunks */

typedef __nv_bfloat16 bf16;

// ---------------------------------------------------------------------------
// Scratch (device globals: allocation-free rule)
// ---------------------------------------------------------------------------
// Tiled ctx + ctx-weights: blob (blk, chunk) = 128 rows x 40 elems (80B rows)
__device__ bf16 g_ctxT_hi[(size_t)cMB * cNCC * 5120];
__device__ bf16 g_ctxT_lo[(size_t)cMB * cNCC * 5120];
__device__ bf16 g_wkcT_hi[(size_t)cNB * cNCC * 5120];
__device__ bf16 g_wkcT_lo[(size_t)cNB * cNCC * 5120];
__device__ bf16 g_wvcT_hi[(size_t)cNB * cNCC * 5120];
__device__ bf16 g_wvcT_lo[(size_t)cNB * cNCC * 5120];
// linear buffers (unchanged paths)
__device__ bf16 g_latln_hi[cML * cD];
__device__ bf16 g_latln_lo[cML * cD];
__device__ bf16 g_att_hi[cML * cHHD];
__device__ bf16 g_att_lo[cML * cHHD];
__device__ bf16 g_mlp_hi[(size_t)cML * cI];
__device__ bf16 g_mlp_lo[(size_t)cML * cI];
__device__ bf16 g_Q_hi[cML * cHHD], g_Q_lo[cML * cHHD];
__device__ bf16 g_K_hi[(size_t)cB * cT * cHHD], g_K_lo[(size_t)cB * cT * cHHD];
__device__ bf16 g_V_hi[(size_t)cB * cT * cHHD], g_V_lo[(size_t)cB * cT * cHHD];
__device__ bf16 g_P_hi[(size_t)cB * cH * cL * cT];
__device__ bf16 g_P_lo[(size_t)cB * cH * cL * cT];
__device__ bf16 g_wq_hi[cHHD * cD],  g_wq_lo[cHHD * cD];
__device__ bf16 g_wkl_hi[cHHD * cD], g_wkl_lo[cHHD * cD];
__device__ bf16 g_wvl_hi[cHHD * cD], g_wvl_lo[cHHD * cD];
__device__ bf16 g_wo_hi[cD * cHHD],  g_wo_lo[cD * cHHD];
__device__ bf16 g_wfc_hi[(size_t)cI * cD], g_wfc_lo[(size_t)cI * cD];
__device__ bf16 g_wcp_hi[(size_t)cD * cI], g_wcp_lo[(size_t)cD * cI];
__device__ float g_biasQ[cHHD], g_biasKc[cHHD], g_biasKl[cHHD];
__device__ float g_biasVc[cHHD], g_biasVl[cHHD], g_biasFc[cI];
__device__ float g_lat[cML * cD];
__device__ float g_Q[cML * cHHD];
__device__ float g_K[(size_t)cB * cT * cHHD];
__device__ float g_scores[(size_t)cB * cH * cL * cT];

// ---------------------------------------------------------------------------
// PTX helpers (base sm_90 features only)
// ---------------------------------------------------------------------------
__device__ __forceinline__ uint32_t smem_u32(const void* p) {
  uint32_t a;
  asm("{ .reg .u64 t; cvta.to.shared.u64 t, %1; cvt.u32.u64 %0, t; }"
      : "=r"(a) : "l"(p));
  return a;
}
__device__ __forceinline__ void cp_async16(uint32_t saddr, const void* gptr) {
  asm volatile("cp.async.cg.shared.global [%0], [%1], 16;" ::"r"(saddr),
               "l"(gptr)
               : "memory");
}
#define CP_COMMIT() asm volatile("cp.async.commit_group;" ::: "memory")
#define CP_WAIT(N) asm volatile("cp.async.wait_group %0;" ::"n"(N) : "memory")

__device__ __forceinline__ void bulk_g2s(uint32_t dst, const void* src,
                                         uint32_t bytes, uint32_t bar) {
  asm volatile(
      "cp.async.bulk.shared::cta.global.mbarrier::complete_tx::bytes "
      "[%0], [%1], %2, [%3];"
      :: "r"(dst), "l"(src), "r"(bytes), "r"(bar)
      : "memory");
}
#define MBAR_INIT(mb, n)                                                   \
  asm volatile("mbarrier.init.shared.b64 [%0], %1;" ::"r"((uint32_t)(mb)), \
               "r"((uint32_t)(n))                                          \
               : "memory")
#define MBAR_EXPECT_TX(mb, n)                                    \
  asm volatile("mbarrier.arrive.expect_tx.shared.b64 _, [%0], %1;" ::"r"( \
                   (uint32_t)(mb)),                              \
               "r"((uint32_t)(n))                                \
               : "memory")
#define MBAR_WAIT(mb, par) do {                                              \
  uint32_t _mb = (uint32_t)(mb), _p = (uint32_t)(par), _d;                   \
  asm volatile(                                                              \
      "{\n\t.reg .pred p;\n\t"                                               \
      "mbarrier.try_wait.parity.acquire.cta.shared::cta.b64 p, [%1], %2;\n\t"\
      "selp.b32 %0, 1, 0, p;\n\t}"                                           \
      : "=r"(_d) : "r"(_mb), "r"(_p) : "memory");                            \
  if (!_d) {                                                                 \
    asm volatile(                                                            \
        "{\n\t.reg .pred P1;\n\t"                                            \
        "W1_%=:\n\t"                                                         \
        "mbarrier.try_wait.parity.acquire.cta.shared::cta.b64 P1, [%0], %1, 0x989680;\n\t" \
        "@P1 bra.uni W2_%=;\n\tbra.uni W1_%=;\n\tW2_%=:\n\t}"                \
        :: "r"(_mb), "r"(_p) : "memory");                                    \
  }                                                                          \
} while (0)

__device__ __forceinline__ void ldsm_x4(uint32_t* d, uint32_t addr) {
  asm volatile("ldmatrix.sync.aligned.m8n8.x4.shared.b16 {%0,%1,%2,%3},[%4];"
               : "=r"(d[0]), "=r"(d[1]), "=r"(d[2]), "=r"(d[3])
               : "r"(addr));
}
__device__ __forceinline__ void ldsm_x2(uint32_t* d, uint32_t addr) {
  asm volatile("ldmatrix.sync.aligned.m8n8.x2.shared.b16 {%0,%1},[%2];"
               : "=r"(d[0]), "=r"(d[1])
               : "r"(addr));
}
__device__ __forceinline__ void ldsm_x2_trans(uint32_t* d, uint32_t addr) {
  asm volatile("ldmatrix.sync.aligned.m8n8.x2.trans.shared.b16 {%0,%1},[%2];"
               : "=r"(d[0]), "=r"(d[1])
               : "r"(addr));
}
__device__ __forceinline__ void mma16816(float* c, const uint32_t* a,
                                         const uint32_t* b) {
  asm volatile(
      "mma.sync.aligned.m16n8k16.row.col.f32.bf16.bf16.f32 "
      "{%0,%1,%2,%3},{%4,%5,%6,%7},{%8,%9},{%0,%1,%2,%3};"
      : "+f"(c[0]), "+f"(c[1]), "+f"(c[2]), "+f"(c[3])
      : "r"(a[0]), "r"(a[1]), "r"(a[2]), "r"(a[3]), "r"(b[0]), "r"(b[1]));
}

// Fast exp on the FMA pipe (degree-6 2^f poly; rel err ~8e-6).
__device__ __forceinline__ float fexp(float x) {
  x = fmaxf(x, -87.0f);
  float t = x * 1.4426950408889634f;
  float fi = floorf(t);
  float f = t - fi;
  float p = 1.54035304e-4f;
  p = fmaf(p, f, 1.33335581e-3f);
  p = fmaf(p, f, 9.61812911e-3f);
  p = fmaf(p, f, 5.55041087e-2f);
  p = fmaf(p, f, 2.40226507e-1f);
  p = fmaf(p, f, 6.93147181e-1f);
  p = fmaf(p, f, 1.0f);
  int i = (int)fi;
  return p * __int_as_float((i + 127) << 23);
}

// ---------------------------------------------------------------------------
// Fused ctx K+V GEMM, TMA-bulk loader (tiled operands, mbarrier pipeline).
// 512 thr, 3-stage, 1 sync/chunk. smem image per chunk identical to R9.
// ---------------------------------------------------------------------------
#define FB_STRIDE 40
#define FB_ARR 10240                 /* bytes per array per chunk */
#define FB_CHUNK (6 * FB_ARR)        /* 61440 */
#define FB_HDR 1024
#define FB_SMEM (FB_HDR + 3 * FB_CHUNK) /* 185344 */

__global__ __launch_bounds__(512) void fused_kv_bulk(
    const bf16* __restrict__ AThi, const bf16* __restrict__ ATlo,
    const bf16* __restrict__ BkThi, const bf16* __restrict__ BkTlo,
    const bf16* __restrict__ BvThi, const bf16* __restrict__ BvTlo,
    const float* __restrict__ biasK, const float* __restrict__ biasV,
    float* __restrict__ Kout, bf16* __restrict__ Vhi, bf16* __restrict__ Vlo) {
  extern __shared__ char sm[];
  const uint32_t sb = smem_u32(sm);
  const int tid = threadIdx.x, lane = tid & 31, wid = tid >> 5;
  const int grp = wid >> 3;  // 0=K, 1=V
  const int gw = wid & 7;
  const int wm = gw & 1, wn = gw >> 1;
  const int mb = blockIdx.y, nb = blockIdx.x;
  const int m0 = mb * 128, n0 = nb * 128;

  const char* srcs[6];
  srcs[0] = (const char*)AThi + (size_t)mb * cNCC * FB_ARR;
  srcs[1] = (const char*)ATlo + (size_t)mb * cNCC * FB_ARR;
  srcs[2] = (const char*)BkThi + (size_t)nb * cNCC * FB_ARR;
  srcs[3] = (const char*)BkTlo + (size_t)nb * cNCC * FB_ARR;
  srcs[4] = (const char*)BvThi + (size_t)nb * cNCC * FB_ARR;
  srcs[5] = (const char*)BvTlo + (size_t)nb * cNCC * FB_ARR;

  if (tid == 0) {
    MBAR_INIT(sb + 0, 1);
    MBAR_INIT(sb + 8, 1);
    MBAR_INIT(sb + 16, 1);
  }
  __syncthreads();

  auto issue = [&](int c) {
    int s = c % 3;
    uint32_t bar = sb + s * 8;
    MBAR_EXPECT_TX(bar, FB_CHUNK);
    uint32_t dst = sb + FB_HDR + s * FB_CHUNK;
#pragma unroll
    for (int a = 0; a < 6; a++)
      bulk_g2s(dst + a * FB_ARR, srcs[a] + (size_t)c * FB_ARR, FB_ARR, bar);
  };
  if (tid == 0) { issue(0); issue(1); }

  float acc[4][4][4];
#pragma unroll
  for (int mt = 0; mt < 4; mt++)
#pragma unroll
    for (int nt = 0; nt < 4; nt++)
#pragma unroll
      for (int j = 0; j < 4; j++) acc[mt][nt][j] = 0.f;

  const uint32_t aRow = (wm * 64 + (lane & 15)) * (FB_STRIDE * 2);
  const uint32_t aColB = ((lane >> 4) << 3) * 2;
  const uint32_t bRow = (wn * 32 + (lane & 7)) * (FB_STRIDE * 2);
  const uint32_t bColB = (((lane >> 3) & 1) << 3) * 2;
  const uint32_t bOff = (grp ? 4u : 2u) * FB_ARR;

  for (int c = 0; c < cNCC; c++) {
    MBAR_WAIT(sb + (c % 3) * 8, (c / 3) & 1);
    __syncthreads();  // all warps done with stage (c+2)%3's previous contents
    if (tid == 0 && c + 2 < cNCC) issue(c + 2);
    uint32_t base = sb + FB_HDR + (c % 3) * FB_CHUNK;
#pragma unroll
    for (int ks = 0; ks < 2; ks++) {
      uint32_t kb = ks * 32;
      uint32_t ah[4][4], al[4][4];
#pragma unroll
      for (int mt = 0; mt < 4; mt++) {
        uint32_t ad = base + aRow + mt * 16 * (FB_STRIDE * 2) + kb + aColB;
        ldsm_x4(ah[mt], ad);
        ldsm_x4(al[mt], ad + FB_ARR);
      }
#pragma unroll
      for (int nt = 0; nt < 4; nt++) {
        uint32_t bd = base + bOff + bRow + nt * 8 * (FB_STRIDE * 2) + kb + bColB;
        uint32_t bh2[2], bl2[2];
        ldsm_x2(bh2, bd);
        ldsm_x2(bl2, bd + FB_ARR);
#pragma unroll
        for (int mt = 0; mt < 4; mt++) {
          mma16816(acc[mt][nt], ah[mt], bh2);
          mma16816(acc[mt][nt], ah[mt], bl2);
          mma16816(acc[mt][nt], al[mt], bh2);
        }
      }
    }
  }

  // epilogue: ctx rows map 1:1 with row remap (m/cS)*cT + m%cS
#pragma unroll
  for (int mt = 0; mt < 4; mt++) {
    int mloc = wm * 64 + mt * 16 + (lane >> 2);
#pragma unroll
    for (int half = 0; half < 2; half++) {
      int m = m0 + mloc + half * 8;
      int orow = (m / cS) * cT + (m % cS);
#pragma unroll
      for (int nt = 0; nt < 4; nt++) {
        int n = n0 + wn * 32 + nt * 8 + (lane & 3) * 2;
        float v0 = acc[mt][nt][half * 2 + 0];
        float v1 = acc[mt][nt][half * 2 + 1];
        if (grp == 0) {
          v0 += biasK[n]; v1 += biasK[n + 1];
          *(float2*)(Kout + (size_t)orow * cHHD + n) = make_float2(v0, v1);
        } else {
          v0 += biasV[n]; v1 += biasV[n + 1];
          bf16 h0 = __float2bfloat16(v0), h1 = __float2bfloat16(v1);
          *(__nv_bfloat162*)(Vhi + (size_t)orow * cHHD + n) =
              __nv_bfloat162(h0, h1);
          *(__nv_bfloat162*)(Vlo + (size_t)orow * cHHD + n) = __nv_bfloat162(
              __float2bfloat16(v0 - __bfloat162float(h0)),
              __float2bfloat16(v1 - __bfloat162float(h1)));
        }
      }
    }
  }
}

// ---------------------------------------------------------------------------
// Fused K+V bf16-split GEMM (cp.async path) — latent rows only (small)
// ---------------------------------------------------------------------------
#define FK_BK 32
#define FK_NC (cD / FK_BK)
#define FK_STRIDE 40
#define FK_ARR (128 * FK_STRIDE * 2)
#define FK_STAGE (6 * FK_ARR)
#define FK_SMEM (3 * FK_STAGE)

__global__ __launch_bounds__(512) void fused_kv_gemm(
    const bf16* __restrict__ Ahi, const bf16* __restrict__ Alo,
    const bf16* __restrict__ Bkh, const bf16* __restrict__ Bkl,
    const bf16* __restrict__ Bvh, const bf16* __restrict__ Bvl,
    const float* __restrict__ biasK, const float* __restrict__ biasV,
    float* __restrict__ Kout, bf16* __restrict__ Vhi, bf16* __restrict__ Vlo,
    int rpbIn, int rpbOut, int rowOff) {
  extern __shared__ char sm[];
  const uint32_t sb = smem_u32(sm);
  const int tid = threadIdx.x, lane = tid & 31, wid = tid >> 5;
  const int grp = wid >> 3;
  const int gw = wid & 7;
  const int wm = gw & 1, wn = gw >> 1;
  const int m0 = blockIdx.y * 128, n0 = blockIdx.x * 128;

  const bf16* gA0 = Ahi + (size_t)m0 * cD;
  const bf16* gA1 = Alo + (size_t)m0 * cD;
  const bf16* gK0 = Bkh + (size_t)n0 * cD;
  const bf16* gK1 = Bkl + (size_t)n0 * cD;
  const bf16* gV0 = Bvh + (size_t)n0 * cD;
  const bf16* gV1 = Bvl + (size_t)n0 * cD;

  float acc[4][4][4];
#pragma unroll
  for (int mt = 0; mt < 4; mt++)
#pragma unroll
    for (int nt = 0; nt < 4; nt++)
#pragma unroll
      for (int j = 0; j < 4; j++) acc[mt][nt][j] = 0.f;

  const int lr = tid >> 2;
  const int lu = tid & 3;
  auto load_chunk = [&](int c, int buf) {
    int kk = c * FK_BK;
    uint32_t base = sb + buf * FK_STAGE;
    uint32_t so = lr * (FK_STRIDE * 2) + lu * 16;
    size_t go = (size_t)lr * cD + kk + lu * 8;
    cp_async16(base + 0 * FK_ARR + so, gA0 + go);
    cp_async16(base + 1 * FK_ARR + so, gA1 + go);
    cp_async16(base + 2 * FK_ARR + so, gK0 + go);
    cp_async16(base + 3 * FK_ARR + so, gK1 + go);
    cp_async16(base + 4 * FK_ARR + so, gV0 + go);
    cp_async16(base + 5 * FK_ARR + so, gV1 + go);
    CP_COMMIT();
  };

  load_chunk(0, 0);
  load_chunk(1, 1);

  const uint32_t aRow = (wm * 64 + (lane & 15)) * (FK_STRIDE * 2);
  const uint32_t aColB = ((lane >> 4) << 3) * 2;
  const uint32_t bRow = (wn * 32 + (lane & 7)) * (FK_STRIDE * 2);
  const uint32_t bColB = (((lane >> 3) & 1) << 3) * 2;
  const uint32_t bOff = (grp ? 4u : 2u) * FK_ARR;

  for (int c = 0; c < FK_NC; c++) {
    if (c + 1 < FK_NC) { CP_WAIT(1); } else { CP_WAIT(0); }
    __syncthreads();
    if (c + 2 < FK_NC) load_chunk(c + 2, (c + 2) % 3);
    uint32_t base = sb + (c % 3) * FK_STAGE;
#pragma unroll
    for (int ks = 0; ks < 2; ks++) {
      uint32_t kb = ks * 32;
      uint32_t ah[4][4], al[4][4];
#pragma unroll
      for (int mt = 0; mt < 4; mt++) {
        uint32_t ad = base + aRow + mt * 16 * (FK_STRIDE * 2) + kb + aColB;
        ldsm_x4(ah[mt], ad);
        ldsm_x4(al[mt], ad + FK_ARR);
      }
#pragma unroll
      for (int nt = 0; nt < 4; nt++) {
        uint32_t bd = base + bOff + bRow + nt * 8 * (FK_STRIDE * 2) + kb + bColB;
        uint32_t bh2[2], bl2[2];
        ldsm_x2(bh2, bd);
        ldsm_x2(bl2, bd + FK_ARR);
#pragma unroll
        for (int mt = 0; mt < 4; mt++) {
          mma16816(acc[mt][nt], ah[mt], bh2);
          mma16816(acc[mt][nt], ah[mt], bl2);
          mma16816(acc[mt][nt], al[mt], bh2);
        }
      }
    }
  }

#pragma unroll
  for (int mt = 0; mt < 4; mt++) {
    int mloc = wm * 64 + mt * 16 + (lane >> 2);
#pragma unroll
    for (int half = 0; half < 2; half++) {
      int m = m0 + mloc + half * 8;
      int orow = (m / rpbIn) * rpbOut + rowOff + (m % rpbIn);
#pragma unroll
      for (int nt = 0; nt < 4; nt++) {
        int n = n0 + wn * 32 + nt * 8 + (lane & 3) * 2;
        float v0 = acc[mt][nt][half * 2 + 0];
        float v1 = acc[mt][nt][half * 2 + 1];
        if (grp == 0) {
          v0 += biasK[n]; v1 += biasK[n + 1];
          *(float2*)(Kout + (size_t)orow * cHHD + n) = make_float2(v0, v1);
        } else {
          v0 += biasV[n]; v1 += biasV[n + 1];
          bf16 h0 = __float2bfloat16(v0), h1 = __float2bfloat16(v1);
          *(__nv_bfloat162*)(Vhi + (size_t)orow * cHHD + n) =
              __nv_bfloat162(h0, h1);
          *(__nv_bfloat162*)(Vlo + (size_t)orow * cHHD + n) = __nv_bfloat162(
              __float2bfloat16(v0 - __bfloat162float(h0)),
              __float2bfloat16(v1 - __bfloat162float(h1)));
        }
      }
    }
  }
}

// ---------------------------------------------------------------------------
// Generalized pipelined bf16-split MMA GEMM (Q, Wo, Wfc, Wcp)
// ---------------------------------------------------------------------------
#define MG_BK 32
#define MG_STRIDE 40
#define MG_ARR (128 * MG_STRIDE * 2)
#define MG_BUF (4 * MG_ARR)
#define MG_SMEM (2 * MG_BUF)

__global__ __launch_bounds__(256) void mma_gemm_split(
    const bf16* __restrict__ Ahi, const bf16* __restrict__ Alo,
    const bf16* __restrict__ Bhi, const bf16* __restrict__ Blo,
    const float* __restrict__ bias, const float* __restrict__ R,
    float* __restrict__ C, bf16* __restrict__ Chi, bf16* __restrict__ Clo,
    int Kdim, int cN, int relu, int rpbIn, int rpbOut, int rowOff) {
  extern __shared__ char sm[];
  const uint32_t sb = smem_u32(sm);
  const int tid = threadIdx.x;
  const int lane = tid & 31, wid = tid >> 5;
  const int wm = wid & 1, wn = wid >> 1;
  const int m0 = blockIdx.y * 128, n0 = blockIdx.x * 128;
  const int nc = Kdim / MG_BK;

  const bf16* gA0 = Ahi + (size_t)m0 * Kdim;
  const bf16* gA1 = Alo + (size_t)m0 * Kdim;
  const bf16* gB0 = Bhi + (size_t)n0 * Kdim;
  const bf16* gB1 = Blo + (size_t)n0 * Kdim;

  float acc[4][4][4];
#pragma unroll
  for (int mt = 0; mt < 4; mt++)
#pragma unroll
    for (int nt = 0; nt < 4; nt++)
#pragma unroll
      for (int j = 0; j < 4; j++) acc[mt][nt][j] = 0.f;

  const int lr = tid >> 2;
  const int lu = tid & 3;
  auto load_chunk = [&](int c, int buf) {
    int kk = c * MG_BK;
    uint32_t base = sb + buf * MG_BUF;
#pragma unroll
    for (int j = 0; j < 2; j++) {
      int r = lr + j * 64;
      uint32_t so = r * (MG_STRIDE * 2) + lu * 16;
      size_t go = (size_t)r * Kdim + kk + lu * 8;
      cp_async16(base + 0 * MG_ARR + so, gA0 + go);
      cp_async16(base + 1 * MG_ARR + so, gA1 + go);
      cp_async16(base + 2 * MG_ARR + so, gB0 + go);
      cp_async16(base + 3 * MG_ARR + so, gB1 + go);
    }
    CP_COMMIT();
  };

  load_chunk(0, 0);

  const uint32_t aRow = (wm * 64 + (lane & 15)) * (MG_STRIDE * 2);
  const uint32_t aColB = ((lane >> 4) << 3) * 2;
  const uint32_t bRow = (wn * 32 + (lane & 7)) * (MG_STRIDE * 2);
  const uint32_t bColB = (((lane >> 3) & 1) << 3) * 2;

  for (int c = 0; c < nc; c++) {
    int buf = c & 1;
    if (c + 1 < nc) {
      load_chunk(c + 1, buf ^ 1);
      CP_WAIT(1);
    } else {
      CP_WAIT(0);
    }
    __syncthreads();
    uint32_t base = sb + buf * MG_BUF;
#pragma unroll
    for (int ks = 0; ks < 2; ks++) {
      uint32_t kb = ks * 32;
      uint32_t ah[4][4], al[4][4], bh[4][2], bl[4][2];
#pragma unroll
      for (int mt = 0; mt < 4; mt++) {
        uint32_t ad = base + aRow + mt * 16 * (MG_STRIDE * 2) + kb + aColB;
        ldsm_x4(ah[mt], ad);
        ldsm_x4(al[mt], ad + MG_ARR);
      }
#pragma unroll
      for (int nt = 0; nt < 4; nt++) {
        uint32_t bd =
            base + 2 * MG_ARR + bRow + nt * 8 * (MG_STRIDE * 2) + kb + bColB;
        ldsm_x2(bh[nt], bd);
        ldsm_x2(bl[nt], bd + MG_ARR);
      }
#pragma unroll
      for (int mt = 0; mt < 4; mt++)
#pragma unroll
        for (int nt = 0; nt < 4; nt++) {
          mma16816(acc[mt][nt], ah[mt], bh[nt]);
          mma16816(acc[mt][nt], ah[mt], bl[nt]);
          mma16816(acc[mt][nt], al[mt], bh[nt]);
        }
    }
    __syncthreads();
  }

#pragma unroll
  for (int mt = 0; mt < 4; mt++) {
    int mloc = wm * 64 + mt * 16 + (lane >> 2);
#pragma unroll
    for (int half = 0; half < 2; half++) {
      int m = m0 + mloc + half * 8;
      int orow = (m / rpbIn) * rpbOut + rowOff + (m % rpbIn);
#pragma unroll
      for (int nt = 0; nt < 4; nt++) {
        int n = n0 + wn * 32 + nt * 8 + (lane & 3) * 2;
        float v0 = acc[mt][nt][half * 2 + 0];
        float v1 = acc[mt][nt][half * 2 + 1];
        if (bias != nullptr) { v0 += bias[n]; v1 += bias[n + 1]; }
        if (R != nullptr) {
          float2 rv = *(const float2*)(R + (size_t)orow * cN + n);
          v0 += rv.x; v1 += rv.y;
        }
        if (relu) { v0 = fmaxf(v0, 0.f); v1 = fmaxf(v1, 0.f); }
        if (C != nullptr)
          *(float2*)(C + (size_t)orow * cN + n) = make_float2(v0, v1);
        if (Chi != nullptr) {
          bf16 h0 = __float2bfloat16(v0);
          bf16 h1 = __float2bfloat16(v1);
          *(__nv_bfloat162*)(Chi + (size_t)orow * cN + n) =
              __nv_bfloat162(h0, h1);
          *(__nv_bfloat162*)(Clo + (size_t)orow * cN + n) = __nv_bfloat162(
              __float2bfloat16(v0 - __bfloat162float(h0)),
              __float2bfloat16(v1 - __bfloat162float(h1)));
        }
      }
    }
  }
}

// ---------------------------------------------------------------------------
// Attention scores on MMA
// ---------------------------------------------------------------------------
#define SCM_STRIDE 104
#define SCM_ARR (64 * SCM_STRIDE * 2)
#define SCM_SMEM (4 * SCM_ARR)
__global__ __launch_bounds__(256) void attn_scores_mma(
    const bf16* __restrict__ Qh, const bf16* __restrict__ Ql,
    const bf16* __restrict__ Kh, const bf16* __restrict__ Kl,
    float* __restrict__ Sc) {
  extern __shared__ char sm[];
  const uint32_t sb = smem_u32(sm);
  const int tid = threadIdx.x, lane = tid & 31, wid = tid >> 5;
  const int bh = blockIdx.y, b = bh >> 4, h = bh & 15;
  const int t0 = blockIdx.x * 64;

#pragma unroll
  for (int it = 0; it < 3; it++) {
    int e = tid + it * 256;
    int r = e / 12, u = e % 12;
    uint32_t so = r * (SCM_STRIDE * 2) + u * 16;
    size_t qo = (size_t)(b * cL + r) * cHHD + h * cHD + u * 8;
    size_t ko = (size_t)(b * cT + t0 + r) * cHHD + h * cHD + u * 8;
    *(uint4*)(sm + 0 * SCM_ARR + so) = *(const uint4*)(Qh + qo);
    *(uint4*)(sm + 1 * SCM_ARR + so) = *(const uint4*)(Ql + qo);
    *(uint4*)(sm + 2 * SCM_ARR + so) = *(const uint4*)(Kh + ko);
    *(uint4*)(sm + 3 * SCM_ARR + so) = *(const uint4*)(Kl + ko);
  }
  __syncthreads();

  const int wm = wid & 1, wn = wid >> 1;
  float acc[2][2][4];
#pragma unroll
  for (int mt = 0; mt < 2; mt++)
#pragma unroll
    for (int nt = 0; nt < 2; nt++)
#pragma unroll
      for (int j = 0; j < 4; j++) acc[mt][nt][j] = 0.f;

#pragma unroll
  for (int ks = 0; ks < 6; ks++) {
    uint32_t kb = ks * 32;
    uint32_t ah[2][4], al[2][4], bh2[2][2], bl2[2][2];
#pragma unroll
    for (int mt = 0; mt < 2; mt++) {
      uint32_t ad = sb + (wm * 32 + mt * 16 + (lane & 15)) * (SCM_STRIDE * 2) +
                    kb + (lane >> 4) * 16;
      ldsm_x4(ah[mt], ad);
      ldsm_x4(al[mt], ad + SCM_ARR);
    }
#pragma unroll
    for (int nt = 0; nt < 2; nt++) {
      uint32_t bd = sb + 2 * SCM_ARR +
                    (wn * 16 + nt * 8 + (lane & 7)) * (SCM_STRIDE * 2) + kb +
                    ((lane >> 3) & 1) * 16;
      ldsm_x2(bh2[nt], bd);
      ldsm_x2(bl2[nt], bd + SCM_ARR);
    }
#pragma unroll
    for (int mt = 0; mt < 2; mt++)
#pragma unroll
      for (int nt = 0; nt < 2; nt++) {
        mma16816(acc[mt][nt], ah[mt], bh2[nt]);
        mma16816(acc[mt][nt], ah[mt], bl2[nt]);
        mma16816(acc[mt][nt], al[mt], bh2[nt]);
      }
  }

  const float scale = 0.102062072615966f;
#pragma unroll
  for (int mt = 0; mt < 2; mt++)
#pragma unroll
    for (int half = 0; half < 2; half++) {
      int row = wm * 32 + mt * 16 + (lane >> 2) + half * 8;
#pragma unroll
      for (int nt = 0; nt < 2; nt++) {
        int col = t0 + wn * 16 + nt * 8 + (lane & 3) * 2;
        *(float2*)(Sc + ((size_t)bh * cL + row) * cT + col) =
            make_float2(acc[mt][nt][half * 2] * scale,
                        acc[mt][nt][half * 2 + 1] * scale);
      }
    }
}

// ---------------------------------------------------------------------------
// Row softmax -> P bf16 hi/lo. Register-resident, polynomial exp.
// ---------------------------------------------------------------------------
__global__ void softmax_split_kernel(const float* __restrict__ Sc,
                                     bf16* __restrict__ Ph,
                                     bf16* __restrict__ Pl) {
  const float* x = Sc + (size_t)blockIdx.x * cT;
  bf16* ph = Ph + (size_t)blockIdx.x * cT;
  bf16* pl = Pl + (size_t)blockIdx.x * cT;
  int tid = threadIdx.x;
  __shared__ float sh[32];
  __shared__ float bc;
  float v[10];
  float m = -1e30f;
#pragma unroll
  for (int k = 0; k < 10; k++) {
    int c = k * 256 + tid;
    if (c < cT) {
      v[k] = x[c];
      m = fmaxf(m, v[k]);
    } else {
      v[k] = -1e30f;
    }
  }
  for (int o = 16; o; o >>= 1) m = fmaxf(m, __shfl_xor_sync(~0u, m, o));
  int w = tid >> 5, lane = tid & 31;
  if (lane == 0) sh[w] = m;
  __syncthreads();
  if (w == 0) {
    m = (lane < 8) ? sh[lane] : -1e30f;
    for (int o = 16; o; o >>= 1) m = fmaxf(m, __shfl_xor_sync(~0u, m, o));
    if (lane == 0) bc = m;
  }
  __syncthreads();
  m = bc;
  float s = 0.f;
#pragma unroll
  for (int k = 0; k < 10; k++) {
    if (k * 256 + tid < cT) {
      v[k] = fexp(v[k] - m);
      s += v[k];
    }
  }
  for (int o = 16; o; o >>= 1) s += __shfl_xor_sync(~0u, s, o);
  __syncthreads();
  if (lane == 0) sh[w] = s;
  __syncthreads();
  if (w == 0) {
    s = (lane < 8) ? sh[lane] : 0.f;
    for (int o = 16; o; o >>= 1) s += __shfl_xor_sync(~0u, s, o);
    if (lane == 0) bc = 1.f / s;
  }
  __syncthreads();
  float inv = bc;
#pragma unroll
  for (int k = 0; k < 10; k++) {
    int c = k * 256 + tid;
    if (c < cT) {
      float p = v[k] * inv;
      bf16 hh = __float2bfloat16(p);
      ph[c] = hh;
      pl[c] = __float2bfloat16(p - __bfloat162float(hh));
    }
  }
}

// ---------------------------------------------------------------------------
// AV on MMA
// ---------------------------------------------------------------------------
#define AV_PSTR 72
#define AV_VSTR 104
#define AV_PARR (64 * AV_PSTR * 2)
#define AV_VARR (64 * AV_VSTR * 2)
#define AV_STAGE (2 * AV_PARR + 2 * AV_VARR)
#define AV_SMEM (2 * AV_STAGE)
__global__ __launch_bounds__(256) void attn_av_mma(
    const bf16* __restrict__ Ph, const bf16* __restrict__ Pl,
    const bf16* __restrict__ Vh, const bf16* __restrict__ Vl,
    bf16* __restrict__ Ohi, bf16* __restrict__ Olo) {
  extern __shared__ char sm[];
  const uint32_t sb = smem_u32(sm);
  const int tid = threadIdx.x, lane = tid & 31, wid = tid >> 5;
  const int bh = blockIdx.x, b = bh >> 4, h = bh & 15;
  const int wm = wid >> 1, wn = wid & 1;

  auto load_chunk = [&](int ct, int buf) {
    int t0 = ct * 64;
    uint32_t base = sb + buf * AV_STAGE;
#pragma unroll
    for (int it = 0; it < 2; it++) {
      int e = tid + it * 256;
      int r = e >> 3, u = e & 7;
      uint32_t so = r * (AV_PSTR * 2) + u * 16;
      size_t po = (size_t)(bh * cL + r) * cT + t0 + u * 8;
      cp_async16(base + so, Ph + po);
      cp_async16(base + AV_PARR + so, Pl + po);
    }
#pragma unroll
    for (int it = 0; it < 3; it++) {
      int e = tid + it * 256;
      int r = e / 12, u = e % 12;
      uint32_t so = r * (AV_VSTR * 2) + u * 16;
      size_t vo = (size_t)(b * cT + t0 + r) * cHHD + h * cHD + u * 8;
      cp_async16(base + 2 * AV_PARR + so, Vh + vo);
      cp_async16(base + 2 * AV_PARR + AV_VARR + so, Vl + vo);
    }
    CP_COMMIT();
  };

  float acc[6][4];
#pragma unroll
  for (int nt = 0; nt < 6; nt++)
#pragma unroll
    for (int j = 0; j < 4; j++) acc[nt][j] = 0.f;

  load_chunk(0, 0);
  for (int ct = 0; ct < 37; ct++) {
    int buf = ct & 1;
    if (ct + 1 < 37) {
      load_chunk(ct + 1, buf ^ 1);
      CP_WAIT(1);
    } else {
      CP_WAIT(0);
    }
    __syncthreads();
    uint32_t base = sb + buf * AV_STAGE;
#pragma unroll
    for (int ks = 0; ks < 4; ks++) {
      uint32_t kb = ks * 16;
      uint32_t ap[4], al[4];
      uint32_t aa = base + (wm * 16 + (lane & 15)) * (AV_PSTR * 2) + kb * 2 +
                    (lane >> 4) * 16;
      ldsm_x4(ap, aa);
      ldsm_x4(al, aa + AV_PARR);
#pragma unroll
      for (int nt = 0; nt < 6; nt++) {
        uint32_t ba = base + 2 * AV_PARR +
                      (kb + ((lane >> 3) & 1) * 8 + (lane & 7)) * (AV_VSTR * 2) +
                      (wn * 48 + nt * 8) * 2;
        uint32_t bv[2], blv[2];
        ldsm_x2_trans(bv, ba);
        ldsm_x2_trans(blv, ba + AV_VARR);
        mma16816(acc[nt], ap, bv);
        mma16816(acc[nt], ap, blv);
        mma16816(acc[nt], al, bv);
      }
    }
    __syncthreads();
  }

#pragma unroll
  for (int half = 0; half < 2; half++) {
    int row = b * cL + wm * 16 + (lane >> 2) + half * 8;
#pragma unroll
    for (int nt = 0; nt < 6; nt++) {
      int col = h * cHD + wn * 48 + nt * 8 + (lane & 3) * 2;
      float v0 = acc[nt][half * 2], v1 = acc[nt][half * 2 + 1];
      bf16 h0 = __float2bfloat16(v0), h1 = __float2bfloat16(v1);
      *(__nv_bfloat162*)(Ohi + (size_t)row * cHHD + col) = __nv_bfloat162(h0, h1);
      *(__nv_bfloat162*)(Olo + (size_t)row * cHHD + col) = __nv_bfloat162(
          __float2bfloat16(v0 - __bfloat162float(h0)),
          __float2bfloat16(v1 - __bfloat162float(h1)));
    }
  }
}

// ---------------------------------------------------------------------------
// ctx LN -> TILED bf16 hi/lo (blob layout matches GEMM smem image)
// ---------------------------------------------------------------------------
__global__ void ln_ctx_tiled_kernel(const float* __restrict__ x,
                                    bf16* __restrict__ hi,
                                    bf16* __restrict__ lo) {
  int row = blockIdx.x;
  const float* xr = x + (size_t)row * cD;
  float s = 0.f, s2 = 0.f;
  for (int c = threadIdx.x; c < cD; c += 256) {
    float v = xr[c];
    s += v; s2 += v * v;
  }
  __shared__ float sh[64];
  for (int o = 16; o; o >>= 1) {
    s += __shfl_xor_sync(~0u, s, o);
    s2 += __shfl_xor_sync(~0u, s2, o);
  }
  int w = threadIdx.x >> 5, lane = threadIdx.x & 31;
  if (lane == 0) { sh[w] = s; sh[w + 32] = s2; }
  __syncthreads();
  if (w == 0) {
    s = (lane < 8) ? sh[lane] : 0.f;
    s2 = (lane < 8) ? sh[lane + 32] : 0.f;
    for (int o = 16; o; o >>= 1) {
      s += __shfl_xor_sync(~0u, s, o);
      s2 += __shfl_xor_sync(~0u, s2, o);
    }
    if (lane == 0) { sh[0] = s; sh[1] = s2; }
  }
  __syncthreads();
  float mean = sh[0] * (1.f / cD);
  float rstd = rsqrtf(sh[1] * (1.f / cD) - mean * mean + cEPS);
  size_t rowbase = (size_t)(row >> 7) * cNCC * 5120 + (size_t)(row & 127) * 40;
  for (int c = threadIdx.x; c < cD; c += 256) {
    float v = (xr[c] - mean) * rstd;
    bf16 h = __float2bfloat16(v);
    size_t off = rowbase + (size_t)(c >> 5) * 5120 + (c & 31);
    hi[off] = h;
    lo[off] = __float2bfloat16(v - __bfloat162float(h));
  }
}

// ---------------------------------------------------------------------------
// Tiled weight prep for ctx K/V GEMM
// ---------------------------------------------------------------------------
__global__ void wprep_tiled_kernel(const float* __restrict__ W,
                                   const float* __restrict__ g,
                                   const float* __restrict__ b,
                                   bf16* __restrict__ Whi,
                                   bf16* __restrict__ Wlo,
                                   float* __restrict__ bias) {
  int n = blockIdx.x;
  float bs = 0.f;
  size_t rowbase = (size_t)(n >> 7) * cNCC * 5120 + (size_t)(n & 127) * 40;
  for (int k = threadIdx.x; k < cD; k += 256) {
    float w = W[(size_t)k * cHHD + n];
    float v = g[k] * w;
    bf16 h = __float2bfloat16(v);
    size_t off = rowbase + (size_t)(k >> 5) * 5120 + (k & 31);
    Whi[off] = h;
    Wlo[off] = __float2bfloat16(v - __bfloat162float(h));
    bs += b[k] * w;
  }
  __shared__ float sh[8];
  for (int o = 16; o; o >>= 1) bs += __shfl_xor_sync(~0u, bs, o);
  int w8 = threadIdx.x >> 5, lane = threadIdx.x & 31;
  if (lane == 0) sh[w8] = bs;
  __syncthreads();
  if (threadIdx.x == 0) {
    float t = 0.f;
    for (int i = 0; i < 8; i++) t += sh[i];
    bias[n] = t;
  }
}

// ---------------------------------------------------------------------------
// LN (no affine) + linear bf16 hi/lo split (latents / MLP input)
// ---------------------------------------------------------------------------
__global__ void ln_split_kernel(const float* __restrict__ x,
                                bf16* __restrict__ hi, bf16* __restrict__ lo) {
  int row = blockIdx.x;
  const float* xr = x + (size_t)row * cD;
  float s = 0.f, s2 = 0.f;
  for (int c = threadIdx.x; c < cD; c += 256) {
    float v = xr[c];
    s += v; s2 += v * v;
  }
  __shared__ float sh[64];
  for (int o = 16; o; o >>= 1) {
    s += __shfl_xor_sync(~0u, s, o);
    s2 += __shfl_xor_sync(~0u, s2, o);
  }
  int w = threadIdx.x >> 5, lane = threadIdx.x & 31;
  if (lane == 0) { sh[w] = s; sh[w + 32] = s2; }
  __syncthreads();
  if (w == 0) {
    s = (lane < 8) ? sh[lane] : 0.f;
    s2 = (lane < 8) ? sh[lane + 32] : 0.f;
    for (int o = 16; o; o >>= 1) {
      s += __shfl_xor_sync(~0u, s, o);
      s2 += __shfl_xor_sync(~0u, s2, o);
    }
    if (lane == 0) { sh[0] = s; sh[1] = s2; }
  }
  __syncthreads();
  float mean = sh[0] * (1.f / cD);
  float rstd = rsqrtf(sh[1] * (1.f / cD) - mean * mean + cEPS);
  for (int c = threadIdx.x; c < cD; c += 256) {
    float v = (xr[c] - mean) * rstd;
    bf16 h = __float2bfloat16(v);
    hi[(size_t)row * cD + c] = h;
    lo[(size_t)row * cD + c] = __float2bfloat16(v - __bfloat162float(h));
  }
}

// ---------------------------------------------------------------------------
// Linear weight prep
// ---------------------------------------------------------------------------
__global__ void wprep_kernel(const float* __restrict__ W,
                             const float* __restrict__ g,
                             const float* __restrict__ b,
                             bf16* __restrict__ Whi, bf16* __restrict__ Wlo,
                             float* __restrict__ bias, int Kdim, int Nw) {
  int n = blockIdx.x;
  float bs = 0.f;
  for (int k = threadIdx.x; k < Kdim; k += 256) {
    float w = W[(size_t)k * Nw + n];
    float v = (g != nullptr) ? g[k] * w : w;
    bf16 h = __float2bfloat16(v);
    Whi[(size_t)n * Kdim + k] = h;
    Wlo[(size_t)n * Kdim + k] = __float2bfloat16(v - __bfloat162float(h));
    if (b != nullptr) bs += b[k] * w;
  }
  if (bias != nullptr) {
    __shared__ float sh[8];
    for (int o = 16; o; o >>= 1) bs += __shfl_xor_sync(~0u, bs, o);
    int w8 = threadIdx.x >> 5, lane = threadIdx.x & 31;
    if (lane == 0) sh[w8] = bs;
    __syncthreads();
    if (threadIdx.x == 0) {
      float t = 0.f;
      for (int i = 0; i < 8; i++) t += sh[i];
      bias[n] = t;
    }
  }
}

// ---------------------------------------------------------------------------
// Broadcast latents
// ---------------------------------------------------------------------------
__global__ void bcast_latents_kernel(const float* __restrict__ lat,
                                     float* __restrict__ out) {
  int idx = blockIdx.x * 256 + threadIdx.x;
  out[idx] = lat[idx % (cL * cD)];
}

// ---------------------------------------------------------------------------
// Final LayerNorm with affine
// ---------------------------------------------------------------------------
__global__ void ln_rows_kernel(const float* __restrict__ x,
                               float* __restrict__ y,
                               const float* __restrict__ g,
                               const float* __restrict__ b) {
  int row = blockIdx.x;
  const float* xr = x + (size_t)row * cD;
  float* yr = y + (size_t)row * cD;
  float s = 0.f, s2 = 0.f;
  for (int c = threadIdx.x; c < cD; c += 256) {
    float v = xr[c];
    s += v; s2 += v * v;
  }
  __shared__ float sh[64];
  for (int o = 16; o; o >>= 1) {
    s += __shfl_xor_sync(~0u, s, o);
    s2 += __shfl_xor_sync(~0u, s2, o);
  }
  int w = threadIdx.x >> 5, lane = threadIdx.x & 31;
  if (lane == 0) { sh[w] = s; sh[w + 32] = s2; }
  __syncthreads();
  if (w == 0) {
    s = (lane < 8) ? sh[lane] : 0.f;
    s2 = (lane < 8) ? sh[lane + 32] : 0.f;
    for (int o = 16; o; o >>= 1) {
      s += __shfl_xor_sync(~0u, s, o);
      s2 += __shfl_xor_sync(~0u, s2, o);
    }
    if (lane == 0) { sh[0] = s; sh[1] = s2; }
  }
  __syncthreads();
  float mean = sh[0] * (1.f / cD);
  float rstd = rsqrtf(sh[1] * (1.f / cD) - mean * mean + cEPS);
  for (int c = threadIdx.x; c < cD; c += 256)
    yr[c] = (xr[c] - mean) * rstd * g[c] + b[c];
}

// ---------------------------------------------------------------------------
// Per-head LN -> bf16 hi/lo
// ---------------------------------------------------------------------------
__global__ void ln_head_split_kernel(const float* __restrict__ x,
                                     const float* __restrict__ g,
                                     const float* __restrict__ b,
                                     bf16* __restrict__ hi,
                                     bf16* __restrict__ lo, int nrows) {
  int r = blockIdx.x * 4 + (threadIdx.x >> 5);
  if (r >= nrows) return;
  int lane = threadIdx.x & 31;
  const float* xr = x + (size_t)r * cHD;
  float v0 = xr[lane], v1 = xr[lane + 32], v2 = xr[lane + 64];
  float s = v0 + v1 + v2;
  float s2 = v0 * v0 + v1 * v1 + v2 * v2;
  for (int o = 16; o; o >>= 1) {
    s += __shfl_xor_sync(~0u, s, o);
    s2 += __shfl_xor_sync(~0u, s2, o);
  }
  float mean = s * (1.f / 96.f);
  float rstd = rsqrtf(s2 * (1.f / 96.f) - mean * mean + cEPS);
  float y0 = (v0 - mean) * rstd * g[lane] + b[lane];
  float y1 = (v1 - mean) * rstd * g[lane + 32] + b[lane + 32];
  float y2 = (v2 - mean) * rstd * g[lane + 64] + b[lane + 64];
  bf16* hr = hi + (size_t)r * cHD;
  bf16* lr = lo + (size_t)r * cHD;
  bf16 h0 = __float2bfloat16(y0), h1 = __float2bfloat16(y1),
       h2 = __float2bfloat16(y2);
  hr[lane] = h0; hr[lane + 32] = h1; hr[lane + 64] = h2;
  lr[lane] = __float2bfloat16(y0 - __bfloat162float(h0));
  lr[lane + 32] = __float2bfloat16(y1 - __bfloat162float(h1));
  lr[lane + 64] = __float2bfloat16(y2 - __bfloat162float(h2));
}

// ---------------------------------------------------------------------------
// Host orchestration
// ---------------------------------------------------------------------------
extern "C" void kernel_launch(void* const* d_in, const int* in_sizes, int n_in,
                              void* d_out, int out_size) {
  (void)in_sizes; (void)n_in; (void)out_size;
  const float* context = (const float*)d_in[0];
  const float* latents = (const float*)d_in[1];
  const float* ctx_g = (const float*)d_in[2];
  const float* ctx_b = (const float*)d_in[3];
  const float* lat_g = (const float*)d_in[4];
  const float* lat_b = (const float*)d_in[5];
  const float* q_g = (const float*)d_in[6];
  const float* q_b = (const float*)d_in[7];
  const float* k_g = (const float*)d_in[8];
  const float* k_b = (const float*)d_in[9];
  const float* Wq = (const float*)d_in[10];
  const float* Wk = (const float*)d_in[11];
  const float* Wv = (const float*)d_in[12];
  const float* Wo = (const float*)d_in[13];
  const float* mlp_g = (const float*)d_in[14];
  const float* mlp_b = (const float*)d_in[15];
  const float* Wfc = (const float*)d_in[16];
  const float* Wcp = (const float*)d_in[17];
  const float* f_g = (const float*)d_in[18];
  const float* f_b = (const float*)d_in[19];
  float* out = (float*)d_out;

#define SYM(var, sym) cudaGetSymbolAddress((void**)&var, sym)
  bf16 *ctxThi, *ctxTlo, *lnhi, *lnlo, *atthi, *attlo, *mlphi, *mlplo;
  bf16 *qhi, *qlo, *khi, *klo, *vhi, *vlo, *phi, *plo;
  bf16 *wqh, *wql, *wkcTh, *wkcTl, *wklh, *wkll, *wvcTh, *wvcTl, *wvlh, *wvll,
      *woh, *wol, *wfch, *wfcl, *wcph, *wcpl;
  float *bQ, *bKc, *bKl, *bVc, *bVl, *bFc;
  float *lat, *Qp, *Kp, *Scp;
  SYM(ctxThi, g_ctxT_hi); SYM(ctxTlo, g_ctxT_lo);
  SYM(lnhi, g_latln_hi); SYM(lnlo, g_latln_lo);
  SYM(atthi, g_att_hi); SYM(attlo, g_att_lo);
  SYM(mlphi, g_mlp_hi); SYM(mlplo, g_mlp_lo);
  SYM(qhi, g_Q_hi); SYM(qlo, g_Q_lo);
  SYM(khi, g_K_hi); SYM(klo, g_K_lo);
  SYM(vhi, g_V_hi); SYM(vlo, g_V_lo);
  SYM(phi, g_P_hi); SYM(plo, g_P_lo);
  SYM(wqh, g_wq_hi); SYM(wql, g_wq_lo);
  SYM(wkcTh, g_wkcT_hi); SYM(wkcTl, g_wkcT_lo);
  SYM(wklh, g_wkl_hi); SYM(wkll, g_wkl_lo);
  SYM(wvcTh, g_wvcT_hi); SYM(wvcTl, g_wvcT_lo);
  SYM(wvlh, g_wvl_hi); SYM(wvll, g_wvl_lo);
  SYM(woh, g_wo_hi); SYM(wol, g_wo_lo);
  SYM(wfch, g_wfc_hi); SYM(wfcl, g_wfc_lo);
  SYM(wcph, g_wcp_hi); SYM(wcpl, g_wcp_lo);
  SYM(bQ, g_biasQ); SYM(bKc, g_biasKc); SYM(bKl, g_biasKl);
  SYM(bVc, g_biasVc); SYM(bVl, g_biasVl); SYM(bFc, g_biasFc);
  SYM(lat, g_lat); SYM(Qp, g_Q); SYM(Kp, g_K); SYM(Scp, g_scores);
#undef SYM

  cudaFuncSetAttribute(mma_gemm_split,
                       cudaFuncAttributeMaxDynamicSharedMemorySize, MG_SMEM);
  cudaFuncSetAttribute(fused_kv_gemm,
                       cudaFuncAttributeMaxDynamicSharedMemorySize, FK_SMEM);
  cudaFuncSetAttribute(fused_kv_bulk,
                       cudaFuncAttributeMaxDynamicSharedMemorySize, FB_SMEM);
  cudaFuncSetAttribute(attn_scores_mma,
                       cudaFuncAttributeMaxDynamicSharedMemorySize, SCM_SMEM);
  cudaFuncSetAttribute(attn_av_mma,
                       cudaFuncAttributeMaxDynamicSharedMemorySize, AV_SMEM);

  auto mma = [&](const bf16* Ah, const bf16* Al, const bf16* Bh,
                 const bf16* Bl, const float* bias, const float* R, float* C,
                 bf16* Ch, bf16* Cl, int M, int N, int Kd, int relu, int rpbIn,
                 int rpbOut, int rowOff) {
    dim3 grid(N / 128, M / 128);
    mma_gemm_split<<<grid, 256, MG_SMEM>>>(Ah, Al, Bh, Bl, bias, R, C, Ch, Cl,
                                           Kd, N, relu, rpbIn, rpbOut, rowOff);
  };
  dim3 kvGridCtx(cNB, cMB);
  dim3 kvGridLat(cNB, cML / 128);

  // launch 0: LN(context) -> tiled bf16 hi/lo (once)
  ln_ctx_tiled_kernel<<<cMCTX, 256>>>(context, ctxThi, ctxTlo);
  // launches 1,2: layer-0 ctx weight preps (tiled)
  wprep_tiled_kernel<<<cHHD, 256>>>(Wk, ctx_g, ctx_b, wkcTh, wkcTl, bKc);
  wprep_tiled_kernel<<<cHHD, 256>>>(Wv, ctx_g, ctx_b, wvcTh, wvcTl, bVc);
  // launch 3: layer-0 fused ctx K+V projection (bulk)  << ncu capture slot >>
  fused_kv_bulk<<<kvGridCtx, 512, FB_SMEM>>>(ctxThi, ctxTlo, wkcTh, wkcTl,
                                             wvcTh, wvcTl, bKc, bVc, Kp, vhi,
                                             vlo);
  bcast_latents_kernel<<<(cML * cD) / 256, 256>>>(latents, lat);

  for (int i = 0; i < cDEPTH; i++) {
    const float* Wq_i = Wq + (size_t)i * cD * cHHD;
    const float* Wk_i = Wk + (size_t)i * cD * cHHD;
    const float* Wv_i = Wv + (size_t)i * cD * cHHD;
    const float* Wo_i = Wo + (size_t)i * cHHD * cD;
    const float* Wfc_i = Wfc + (size_t)i * cD * cI;
    const float* Wcp_i = Wcp + (size_t)i * cI * cD;
    const float* lg = lat_g + i * cD;
    const float* lb = lat_b + i * cD;

    if (i > 0) {
      wprep_tiled_kernel<<<cHHD, 256>>>(Wk_i, ctx_g + i * cD, ctx_b + i * cD,
                                        wkcTh, wkcTl, bKc);
      wprep_tiled_kernel<<<cHHD, 256>>>(Wv_i, ctx_g + i * cD, ctx_b + i * cD,
                                        wvcTh, wvcTl, bVc);
      fused_kv_bulk<<<kvGridCtx, 512, FB_SMEM>>>(ctxThi, ctxTlo, wkcTh, wkcTl,
                                                 wvcTh, wvcTl, bKc, bVc, Kp,
                                                 vhi, vlo);
    }

    // LN(latents) -> normalized hi/lo (linear; affine folded into weights)
    ln_split_kernel<<<cML, 256>>>(lat, lnhi, lnlo);

    wprep_kernel<<<cHHD, 256>>>(Wq_i, lg, lb, wqh, wql, bQ, cD, cHHD);
    wprep_kernel<<<cHHD, 256>>>(Wk_i, lg, lb, wklh, wkll, bKl, cD, cHHD);
    wprep_kernel<<<cHHD, 256>>>(Wv_i, lg, lb, wvlh, wvll, bVl, cD, cHHD);

    // Q (fp32 out for per-head LN)
    mma(lnhi, lnlo, wqh, wql, bQ, nullptr, Qp, nullptr, nullptr, cML, cHHD, cD,
        0, cML, cML, 0);
    // latent K+V rows, appended at offset cS (cp.async path)
    fused_kv_gemm<<<kvGridLat, 512, FK_SMEM>>>(lnhi, lnlo, wklh, wkll, wvlh,
                                               wvll, bKl, bVl, Kp, vhi, vlo,
                                               cL, cT, cS);

    // per-head q/k LN -> hi/lo
    ln_head_split_kernel<<<(cML * cH) / 4, 128>>>(Qp, q_g + i * cHD,
                                                  q_b + i * cHD, qhi, qlo,
                                                  cML * cH);
    ln_head_split_kernel<<<(cB * cT * cH) / 4, 128>>>(Kp, k_g + i * cHD,
                                                      k_b + i * cHD, khi, klo,
                                                      cB * cT * cH);

    // attention on MMA
    attn_scores_mma<<<dim3(cT / 64, cB * cH), 256, SCM_SMEM>>>(qhi, qlo, khi,
                                                               klo, Scp);
    softmax_split_kernel<<<cB * cH * cL, 256>>>(Scp, phi, plo);
    attn_av_mma<<<cB * cH, 256, AV_SMEM>>>(phi, plo, vhi, vlo, atthi, attlo);

    // lat = att @ Wo + lat
    wprep_kernel<<<cD, 256>>>(Wo_i, nullptr, nullptr, woh, wol, nullptr, cHHD,
                              cD);
    mma(atthi, attlo, woh, wol, nullptr, lat, lat, nullptr, nullptr, cML, cD,
        cHHD, 0, cML, cML, 0);

    // MLP
    ln_split_kernel<<<cML, 256>>>(lat, lnhi, lnlo);
    wprep_kernel<<<cI, 256>>>(Wfc_i, mlp_g + i * cD, mlp_b + i * cD, wfch, wfcl,
                              bFc, cD, cI);
    mma(lnhi, lnlo, wfch, wfcl, bFc, nullptr, nullptr, mlphi, mlplo, cML, cI,
        cD, 1, cML, cML, 0);
    wprep_kernel<<<cD, 256>>>(Wcp_i, nullptr, nullptr, wcph, wcpl, nullptr, cI,
                              cD);
    mma(mlphi, mlplo, wcph, wcpl, nullptr, lat, lat, nullptr, nullptr, cML, cD,
        cI, 0, cML, cML, 0);
  }

  ln_rows_kernel<<<cML, 256>>>(lat, out, f_g, f_b);
}

// round 11
// speedup vs baseline: 1.2097x; 1.0387x over previous
#include <cuda_runtime.h>
#include <cuda_bf16.h>
#include <cstdint>
#include <cstddef>

// ---------------------------------------------------------------------------
// Problem constants
// ---------------------------------------------------------------------------
#define cB 32
#define cS 2304
#define cD 1280
#define cDEPTH 6
#define cH 16
#define cHD 96
#define cL 64
#define cI 5120
#define cT (cS + cL)      /* 2368 */
#define cHHD (cH * cHD)   /* 1536 */
#define cEPS 1e-5f
#define cMCTX (cB * cS)   /* 73728 ctx rows */
#define cML (cB * cL)     /* 2048 latent rows */
#define cMB (cMCTX / 128) /* 576 ctx row-blocks */
#define cNCC (cD / 32)    /* 40 k-chunks for Kdim=1280 */

typedef __nv_bfloat16 bf16;

// Tiled blob: (row>>7, k>>5) chunk of 128 rows x 32 elems, stored 128x40 elems
// (80B rows, 8-elem pad) = 5120 elements = 10240 bytes per chunk.
#define TBE(blocks, nc) ((size_t)(blocks) * (nc) * 5120)

// ---------------------------------------------------------------------------
// Scratch (device globals: allocation-free rule)
// ---------------------------------------------------------------------------
__device__ bf16 g_ctxT_hi[TBE(cMB, 40)], g_ctxT_lo[TBE(cMB, 40)];
__device__ bf16 g_latlnT_hi[TBE(16, 40)], g_latlnT_lo[TBE(16, 40)];
__device__ bf16 g_attT_hi[TBE(16, 48)], g_attT_lo[TBE(16, 48)];
__device__ bf16 g_mlpT_hi[TBE(16, 160)], g_mlpT_lo[TBE(16, 160)];
__device__ bf16 g_wkcT_hi[TBE(12, 40)], g_wkcT_lo[TBE(12, 40)];
__device__ bf16 g_wvcT_hi[TBE(12, 40)], g_wvcT_lo[TBE(12, 40)];
__device__ bf16 g_wqT_hi[TBE(12, 40)],  g_wqT_lo[TBE(12, 40)];
__device__ bf16 g_wklT_hi[TBE(12, 40)], g_wklT_lo[TBE(12, 40)];
__device__ bf16 g_wvlT_hi[TBE(12, 40)], g_wvlT_lo[TBE(12, 40)];
__device__ bf16 g_woT_hi[TBE(10, 48)],  g_woT_lo[TBE(10, 48)];
__device__ bf16 g_wfcT_hi[TBE(40, 40)], g_wfcT_lo[TBE(40, 40)];
__device__ bf16 g_wcpT_hi[TBE(10, 160)], g_wcpT_lo[TBE(10, 160)];
// linear buffers
__device__ bf16 g_Q_hi[cML * cHHD], g_Q_lo[cML * cHHD];
__device__ bf16 g_K_hi[(size_t)cB * cT * cHHD], g_K_lo[(size_t)cB * cT * cHHD];
__device__ bf16 g_V_hi[(size_t)cB * cT * cHHD], g_V_lo[(size_t)cB * cT * cHHD];
__device__ bf16 g_P_hi[(size_t)cB * cH * cL * cT];
__device__ bf16 g_P_lo[(size_t)cB * cH * cL * cT];
__device__ float g_biasQ[cHHD], g_biasKc[cHHD], g_biasKl[cHHD];
__device__ float g_biasVc[cHHD], g_biasVl[cHHD], g_biasFc[cI];
__device__ float g_lat[cML * cD];
__device__ float g_Q[cML * cHHD];
__device__ float g_K[(size_t)cB * cT * cHHD];
__device__ float g_scores[(size_t)cB * cH * cL * cT];

// ---------------------------------------------------------------------------
// PTX helpers (base sm_90 features only)
// ---------------------------------------------------------------------------
__device__ __forceinline__ uint32_t smem_u32(const void* p) {
  uint32_t a;
  asm("{ .reg .u64 t; cvta.to.shared.u64 t, %1; cvt.u32.u64 %0, t; }"
      : "=r"(a) : "l"(p));
  return a;
}
__device__ __forceinline__ void cp_async16(uint32_t saddr, const void* gptr) {
  asm volatile("cp.async.cg.shared.global [%0], [%1], 16;" ::"r"(saddr),
               "l"(gptr)
               : "memory");
}
#define CP_COMMIT() asm volatile("cp.async.commit_group;" ::: "memory")
#define CP_WAIT(N) asm volatile("cp.async.wait_group %0;" ::"n"(N) : "memory")

__device__ __forceinline__ void bulk_g2s(uint32_t dst, const void* src,
                                         uint32_t bytes, uint32_t bar) {
  asm volatile(
      "cp.async.bulk.shared::cta.global.mbarrier::complete_tx::bytes "
      "[%0], [%1], %2, [%3];"
      :: "r"(dst), "l"(src), "r"(bytes), "r"(bar)
      : "memory");
}
#define MBAR_INIT(mb, n)                                                   \
  asm volatile("mbarrier.init.shared.b64 [%0], %1;" ::"r"((uint32_t)(mb)), \
               "r"((uint32_t)(n))                                          \
               : "memory")
#define MBAR_EXPECT_TX(mb, n)                                              \
  asm volatile("mbarrier.arrive.expect_tx.shared.b64 _, [%0], %1;" ::"r"(  \
                   (uint32_t)(mb)),                                        \
               "r"((uint32_t)(n))                                          \
               : "memory")
#define MBAR_WAIT(mb, par) do {                                              \
  uint32_t _mb = (uint32_t)(mb), _p = (uint32_t)(par), _d;                   \
  asm volatile(                                                              \
      "{\n\t.reg .pred p;\n\t"                                               \
      "mbarrier.try_wait.parity.acquire.cta.shared::cta.b64 p, [%1], %2;\n\t"\
      "selp.b32 %0, 1, 0, p;\n\t}"                                           \
      : "=r"(_d) : "r"(_mb), "r"(_p) : "memory");                            \
  if (!_d) {                                                                 \
    asm volatile(                                                            \
        "{\n\t.reg .pred P1;\n\t"                                            \
        "W1_%=:\n\t"                                                         \
        "mbarrier.try_wait.parity.acquire.cta.shared::cta.b64 P1, [%0], %1, 0x989680;\n\t" \
        "@P1 bra.uni W2_%=;\n\tbra.uni W1_%=;\n\tW2_%=:\n\t}"                \
        :: "r"(_mb), "r"(_p) : "memory");                                    \
  }                                                                          \
} while (0)

__device__ __forceinline__ void ldsm_x4(uint32_t* d, uint32_t addr) {
  asm volatile("ldmatrix.sync.aligned.m8n8.x4.shared.b16 {%0,%1,%2,%3},[%4];"
               : "=r"(d[0]), "=r"(d[1]), "=r"(d[2]), "=r"(d[3])
               : "r"(addr));
}
__device__ __forceinline__ void ldsm_x2(uint32_t* d, uint32_t addr) {
  asm volatile("ldmatrix.sync.aligned.m8n8.x2.shared.b16 {%0,%1},[%2];"
               : "=r"(d[0]), "=r"(d[1])
               : "r"(addr));
}
__device__ __forceinline__ void ldsm_x2_trans(uint32_t* d, uint32_t addr) {
  asm volatile("ldmatrix.sync.aligned.m8n8.x2.trans.shared.b16 {%0,%1},[%2];"
               : "=r"(d[0]), "=r"(d[1])
               : "r"(addr));
}
__device__ __forceinline__ void mma16816(float* c, const uint32_t* a,
                                         const uint32_t* b) {
  asm volatile(
      "mma.sync.aligned.m16n8k16.row.col.f32.bf16.bf16.f32 "
      "{%0,%1,%2,%3},{%4,%5,%6,%7},{%8,%9},{%0,%1,%2,%3};"
      : "+f"(c[0]), "+f"(c[1]), "+f"(c[2]), "+f"(c[3])
      : "r"(a[0]), "r"(a[1]), "r"(a[2]), "r"(a[3]), "r"(b[0]), "r"(b[1]));
}

// Fast exp on the FMA pipe (degree-6 2^f poly; rel err ~8e-6).
__device__ __forceinline__ float fexp(float x) {
  x = fmaxf(x, -87.0f);
  float t = x * 1.4426950408889634f;
  float fi = floorf(t);
  float f = t - fi;
  float p = 1.54035304e-4f;
  p = fmaf(p, f, 1.33335581e-3f);
  p = fmaf(p, f, 9.61812911e-3f);
  p = fmaf(p, f, 5.55041087e-2f);
  p = fmaf(p, f, 2.40226507e-1f);
  p = fmaf(p, f, 6.93147181e-1f);
  p = fmaf(p, f, 1.0f);
  int i = (int)fi;
  return p * __int_as_float((i + 127) << 23);
}

// ---------------------------------------------------------------------------
// Fused K+V GEMM, bulk loader (tiled operands, Kd=1280 fixed).
// 512 thr, 3 stages, 1 sync/chunk. Row remap via rpbIn/rpbOut/rowOff.
// ---------------------------------------------------------------------------
#define FB_STRIDE 40
#define FB_ARR 10240
#define FB_CHUNK (6 * FB_ARR)
#define FB_HDR 1024
#define FB_SMEM (FB_HDR + 3 * FB_CHUNK)

__global__ __launch_bounds__(512) void fused_kv_bulk(
    const bf16* __restrict__ AThi, const bf16* __restrict__ ATlo,
    const bf16* __restrict__ BkThi, const bf16* __restrict__ BkTlo,
    const bf16* __restrict__ BvThi, const bf16* __restrict__ BvTlo,
    const float* __restrict__ biasK, const float* __restrict__ biasV,
    float* __restrict__ Kout, bf16* __restrict__ Vhi, bf16* __restrict__ Vlo,
    int rpbIn, int rpbOut, int rowOff) {
  extern __shared__ char sm[];
  const uint32_t sb = smem_u32(sm);
  const int tid = threadIdx.x, lane = tid & 31, wid = tid >> 5;
  const int grp = wid >> 3;  // 0=K, 1=V
  const int gw = wid & 7;
  const int wm = gw & 1, wn = gw >> 1;
  const int mb = blockIdx.y, nb = blockIdx.x;
  const int m0 = mb * 128, n0 = nb * 128;

  const char* srcs[6];
  srcs[0] = (const char*)AThi + (size_t)mb * cNCC * FB_ARR;
  srcs[1] = (const char*)ATlo + (size_t)mb * cNCC * FB_ARR;
  srcs[2] = (const char*)BkThi + (size_t)nb * cNCC * FB_ARR;
  srcs[3] = (const char*)BkTlo + (size_t)nb * cNCC * FB_ARR;
  srcs[4] = (const char*)BvThi + (size_t)nb * cNCC * FB_ARR;
  srcs[5] = (const char*)BvTlo + (size_t)nb * cNCC * FB_ARR;

  if (tid == 0) {
    MBAR_INIT(sb + 0, 1);
    MBAR_INIT(sb + 8, 1);
    MBAR_INIT(sb + 16, 1);
  }
  __syncthreads();

  auto issue = [&](int c) {
    int s = c % 3;
    uint32_t bar = sb + s * 8;
    MBAR_EXPECT_TX(bar, FB_CHUNK);
    uint32_t dst = sb + FB_HDR + s * FB_CHUNK;
#pragma unroll
    for (int a = 0; a < 6; a++)
      bulk_g2s(dst + a * FB_ARR, srcs[a] + (size_t)c * FB_ARR, FB_ARR, bar);
  };
  if (tid == 0) { issue(0); issue(1); }

  float acc[4][4][4];
#pragma unroll
  for (int mt = 0; mt < 4; mt++)
#pragma unroll
    for (int nt = 0; nt < 4; nt++)
#pragma unroll
      for (int j = 0; j < 4; j++) acc[mt][nt][j] = 0.f;

  const uint32_t aRow = (wm * 64 + (lane & 15)) * (FB_STRIDE * 2);
  const uint32_t aColB = ((lane >> 4) << 3) * 2;
  const uint32_t bRow = (wn * 32 + (lane & 7)) * (FB_STRIDE * 2);
  const uint32_t bColB = (((lane >> 3) & 1) << 3) * 2;
  const uint32_t bOff = (grp ? 4u : 2u) * FB_ARR;

  for (int c = 0; c < cNCC; c++) {
    MBAR_WAIT(sb + (c % 3) * 8, (c / 3) & 1);
    __syncthreads();
    if (tid == 0 && c + 2 < cNCC) issue(c + 2);
    uint32_t base = sb + FB_HDR + (c % 3) * FB_CHUNK;
#pragma unroll
    for (int ks = 0; ks < 2; ks++) {
      uint32_t kb = ks * 32;
      uint32_t ah[4][4], al[4][4];
#pragma unroll
      for (int mt = 0; mt < 4; mt++) {
        uint32_t ad = base + aRow + mt * 16 * (FB_STRIDE * 2) + kb + aColB;
        ldsm_x4(ah[mt], ad);
        ldsm_x4(al[mt], ad + FB_ARR);
      }
#pragma unroll
      for (int nt = 0; nt < 4; nt++) {
        uint32_t bd = base + bOff + bRow + nt * 8 * (FB_STRIDE * 2) + kb + bColB;
        uint32_t bh2[2], bl2[2];
        ldsm_x2(bh2, bd);
        ldsm_x2(bl2, bd + FB_ARR);
        // term-outer ordering: consecutive MMAs hit different accumulators
#pragma unroll
        for (int mt = 0; mt < 4; mt++) mma16816(acc[mt][nt], ah[mt], bh2);
#pragma unroll
        for (int mt = 0; mt < 4; mt++) mma16816(acc[mt][nt], ah[mt], bl2);
#pragma unroll
        for (int mt = 0; mt < 4; mt++) mma16816(acc[mt][nt], al[mt], bh2);
      }
    }
  }

#pragma unroll
  for (int mt = 0; mt < 4; mt++) {
    int mloc = wm * 64 + mt * 16 + (lane >> 2);
#pragma unroll
    for (int half = 0; half < 2; half++) {
      int m = m0 + mloc + half * 8;
      int orow = (m / rpbIn) * rpbOut + rowOff + (m % rpbIn);
#pragma unroll
      for (int nt = 0; nt < 4; nt++) {
        int n = n0 + wn * 32 + nt * 8 + (lane & 3) * 2;
        float v0 = acc[mt][nt][half * 2 + 0];
        float v1 = acc[mt][nt][half * 2 + 1];
        if (grp == 0) {
          v0 += biasK[n]; v1 += biasK[n + 1];
          *(float2*)(Kout + (size_t)orow * cHHD + n) = make_float2(v0, v1);
        } else {
          v0 += biasV[n]; v1 += biasV[n + 1];
          bf16 h0 = __float2bfloat16(v0), h1 = __float2bfloat16(v1);
          *(__nv_bfloat162*)(Vhi + (size_t)orow * cHHD + n) =
              __nv_bfloat162(h0, h1);
          *(__nv_bfloat162*)(Vlo + (size_t)orow * cHHD + n) = __nv_bfloat162(
              __float2bfloat16(v0 - __bfloat162float(h0)),
              __float2bfloat16(v1 - __bfloat162float(h1)));
        }
      }
    }
  }
}

// ---------------------------------------------------------------------------
// Generalized bulk MMA GEMM (Q, Wo, Wfc, Wcp).
// 256 thr, 2 stages, 2 CTAs/SM. Tiled A/B; fp32 linear C (+bias,+R,relu)
// and/or tiled hi/lo output (outKd blob).
// ---------------------------------------------------------------------------
#define GB_ARR 10240
#define GB_CHUNK (4 * GB_ARR) /* 40960 */
#define GB_HDR 1024
#define GB_SMEM (GB_HDR + 2 * GB_CHUNK) /* 82944 */

__global__ __launch_bounds__(256) void mma_gemm_bulk(
    const bf16* __restrict__ ATh, const bf16* __restrict__ ATl,
    const bf16* __restrict__ BTh, const bf16* __restrict__ BTl,
    const float* __restrict__ bias, const float* __restrict__ R,
    float* __restrict__ C, bf16* __restrict__ ChiT, bf16* __restrict__ CloT,
    int Kdim, int cN, int outKd, int relu) {
  extern __shared__ char sm[];
  const uint32_t sb = smem_u32(sm);
  const int tid = threadIdx.x, lane = tid & 31, wid = tid >> 5;
  const int wm = wid & 1, wn = wid >> 1;
  const int mb = blockIdx.y, nb = blockIdx.x;
  const int m0 = mb * 128, n0 = nb * 128;
  const int nc = Kdim >> 5;

  const char* srcs[4];
  srcs[0] = (const char*)ATh + (size_t)mb * nc * GB_ARR;
  srcs[1] = (const char*)ATl + (size_t)mb * nc * GB_ARR;
  srcs[2] = (const char*)BTh + (size_t)nb * nc * GB_ARR;
  srcs[3] = (const char*)BTl + (size_t)nb * nc * GB_ARR;

  if (tid == 0) {
    MBAR_INIT(sb + 0, 1);
    MBAR_INIT(sb + 8, 1);
  }
  __syncthreads();

  auto issue = [&](int c) {
    int s = c & 1;
    uint32_t bar = sb + s * 8;
    MBAR_EXPECT_TX(bar, GB_CHUNK);
    uint32_t dst = sb + GB_HDR + s * GB_CHUNK;
#pragma unroll
    for (int a = 0; a < 4; a++)
      bulk_g2s(dst + a * GB_ARR, srcs[a] + (size_t)c * GB_ARR, GB_ARR, bar);
  };
  if (tid == 0) issue(0);

  float acc[4][4][4];
#pragma unroll
  for (int mt = 0; mt < 4; mt++)
#pragma unroll
    for (int nt = 0; nt < 4; nt++)
#pragma unroll
      for (int j = 0; j < 4; j++) acc[mt][nt][j] = 0.f;

  const uint32_t aRow = (wm * 64 + (lane & 15)) * (FB_STRIDE * 2);
  const uint32_t aColB = ((lane >> 4) << 3) * 2;
  const uint32_t bRow = (wn * 32 + (lane & 7)) * (FB_STRIDE * 2);
  const uint32_t bColB = (((lane >> 3) & 1) << 3) * 2;

  for (int c = 0; c < nc; c++) {
    MBAR_WAIT(sb + (c & 1) * 8, (c >> 1) & 1);
    __syncthreads();
    if (tid == 0 && c + 1 < nc) issue(c + 1);
    uint32_t base = sb + GB_HDR + (c & 1) * GB_CHUNK;
#pragma unroll
    for (int ks = 0; ks < 2; ks++) {
      uint32_t kb = ks * 32;
      uint32_t ah[4][4], al[4][4];
#pragma unroll
      for (int mt = 0; mt < 4; mt++) {
        uint32_t ad = base + aRow + mt * 16 * (FB_STRIDE * 2) + kb + aColB;
        ldsm_x4(ah[mt], ad);
        ldsm_x4(al[mt], ad + GB_ARR);
      }
#pragma unroll
      for (int nt = 0; nt < 4; nt++) {
        uint32_t bd =
            base + 2 * GB_ARR + bRow + nt * 8 * (FB_STRIDE * 2) + kb + bColB;
        uint32_t bh2[2], bl2[2];
        ldsm_x2(bh2, bd);
        ldsm_x2(bl2, bd + GB_ARR);
#pragma unroll
        for (int mt = 0; mt < 4; mt++) mma16816(acc[mt][nt], ah[mt], bh2);
#pragma unroll
        for (int mt = 0; mt < 4; mt++) mma16816(acc[mt][nt], ah[mt], bl2);
#pragma unroll
        for (int mt = 0; mt < 4; mt++) mma16816(acc[mt][nt], al[mt], bh2);
      }
    }
  }

  const int ncOut = outKd >> 5;
#pragma unroll
  for (int mt = 0; mt < 4; mt++) {
    int mloc = wm * 64 + mt * 16 + (lane >> 2);
#pragma unroll
    for (int half = 0; half < 2; half++) {
      int orow = m0 + mloc + half * 8;
#pragma unroll
      for (int nt = 0; nt < 4; nt++) {
        int n = n0 + wn * 32 + nt * 8 + (lane & 3) * 2;
        float v0 = acc[mt][nt][half * 2 + 0];
        float v1 = acc[mt][nt][half * 2 + 1];
        if (bias != nullptr) { v0 += bias[n]; v1 += bias[n + 1]; }
        if (R != nullptr) {
          float2 rv = *(const float2*)(R + (size_t)orow * cN + n);
          v0 += rv.x; v1 += rv.y;
        }
        if (relu) { v0 = fmaxf(v0, 0.f); v1 = fmaxf(v1, 0.f); }
        if (C != nullptr)
          *(float2*)(C + (size_t)orow * cN + n) = make_float2(v0, v1);
        if (ChiT != nullptr) {
          size_t off = ((size_t)(orow >> 7) * ncOut + (n >> 5)) * 5120 +
                       (orow & 127) * 40 + (n & 31);
          bf16 h0 = __float2bfloat16(v0);
          bf16 h1 = __float2bfloat16(v1);
          *(__nv_bfloat162*)(ChiT + off) = __nv_bfloat162(h0, h1);
          *(__nv_bfloat162*)(CloT + off) = __nv_bfloat162(
              __float2bfloat16(v0 - __bfloat162float(h0)),
              __float2bfloat16(v1 - __bfloat162float(h1)));
        }
      }
    }
  }
}

// ---------------------------------------------------------------------------
// Attention scores on MMA (linear q/k hi-lo inputs)
// ---------------------------------------------------------------------------
#define SCM_STRIDE 104
#define SCM_ARR (64 * SCM_STRIDE * 2)
#define SCM_SMEM (4 * SCM_ARR)
__global__ __launch_bounds__(256) void attn_scores_mma(
    const bf16* __restrict__ Qh, const bf16* __restrict__ Ql,
    const bf16* __restrict__ Kh, const bf16* __restrict__ Kl,
    float* __restrict__ Sc) {
  extern __shared__ char sm[];
  const uint32_t sb = smem_u32(sm);
  const int tid = threadIdx.x, lane = tid & 31, wid = tid >> 5;
  const int bh = blockIdx.y, b = bh >> 4, h = bh & 15;
  const int t0 = blockIdx.x * 64;

#pragma unroll
  for (int it = 0; it < 3; it++) {
    int e = tid + it * 256;
    int r = e / 12, u = e % 12;
    uint32_t so = r * (SCM_STRIDE * 2) + u * 16;
    size_t qo = (size_t)(b * cL + r) * cHHD + h * cHD + u * 8;
    size_t ko = (size_t)(b * cT + t0 + r) * cHHD + h * cHD + u * 8;
    *(uint4*)(sm + 0 * SCM_ARR + so) = *(const uint4*)(Qh + qo);
    *(uint4*)(sm + 1 * SCM_ARR + so) = *(const uint4*)(Ql + qo);
    *(uint4*)(sm + 2 * SCM_ARR + so) = *(const uint4*)(Kh + ko);
    *(uint4*)(sm + 3 * SCM_ARR + so) = *(const uint4*)(Kl + ko);
  }
  __syncthreads();

  const int wm = wid & 1, wn = wid >> 1;
  float acc[2][2][4];
#pragma unroll
  for (int mt = 0; mt < 2; mt++)
#pragma unroll
    for (int nt = 0; nt < 2; nt++)
#pragma unroll
      for (int j = 0; j < 4; j++) acc[mt][nt][j] = 0.f;

#pragma unroll
  for (int ks = 0; ks < 6; ks++) {
    uint32_t kb = ks * 32;
    uint32_t ah[2][4], al[2][4], bh2[2][2], bl2[2][2];
#pragma unroll
    for (int mt = 0; mt < 2; mt++) {
      uint32_t ad = sb + (wm * 32 + mt * 16 + (lane & 15)) * (SCM_STRIDE * 2) +
                    kb + (lane >> 4) * 16;
      ldsm_x4(ah[mt], ad);
      ldsm_x4(al[mt], ad + SCM_ARR);
    }
#pragma unroll
    for (int nt = 0; nt < 2; nt++) {
      uint32_t bd = sb + 2 * SCM_ARR +
                    (wn * 16 + nt * 8 + (lane & 7)) * (SCM_STRIDE * 2) + kb +
                    ((lane >> 3) & 1) * 16;
      ldsm_x2(bh2[nt], bd);
      ldsm_x2(bl2[nt], bd + SCM_ARR);
    }
#pragma unroll
    for (int mt = 0; mt < 2; mt++)
#pragma unroll
      for (int nt = 0; nt < 2; nt++) mma16816(acc[mt][nt], ah[mt], bh2[nt]);
#pragma unroll
    for (int mt = 0; mt < 2; mt++)
#pragma unroll
      for (int nt = 0; nt < 2; nt++) mma16816(acc[mt][nt], ah[mt], bl2[nt]);
#pragma unroll
    for (int mt = 0; mt < 2; mt++)
#pragma unroll
      for (int nt = 0; nt < 2; nt++) mma16816(acc[mt][nt], al[mt], bh2[nt]);
  }

  const float scale = 0.102062072615966f;
#pragma unroll
  for (int mt = 0; mt < 2; mt++)
#pragma unroll
    for (int half = 0; half < 2; half++) {
      int row = wm * 32 + mt * 16 + (lane >> 2) + half * 8;
#pragma unroll
      for (int nt = 0; nt < 2; nt++) {
        int col = t0 + wn * 16 + nt * 8 + (lane & 3) * 2;
        *(float2*)(Sc + ((size_t)bh * cL + row) * cT + col) =
            make_float2(acc[mt][nt][half * 2] * scale,
                        acc[mt][nt][half * 2 + 1] * scale);
      }
    }
}

// ---------------------------------------------------------------------------
// Row softmax -> P bf16 hi/lo. Register-resident, polynomial exp.
// ---------------------------------------------------------------------------
__global__ void softmax_split_kernel(const float* __restrict__ Sc,
                                     bf16* __restrict__ Ph,
                                     bf16* __restrict__ Pl) {
  const float* x = Sc + (size_t)blockIdx.x * cT;
  bf16* ph = Ph + (size_t)blockIdx.x * cT;
  bf16* pl = Pl + (size_t)blockIdx.x * cT;
  int tid = threadIdx.x;
  __shared__ float sh[32];
  __shared__ float bc;
  float v[10];
  float m = -1e30f;
#pragma unroll
  for (int k = 0; k < 10; k++) {
    int c = k * 256 + tid;
    if (c < cT) {
      v[k] = x[c];
      m = fmaxf(m, v[k]);
    } else {
      v[k] = -1e30f;
    }
  }
  for (int o = 16; o; o >>= 1) m = fmaxf(m, __shfl_xor_sync(~0u, m, o));
  int w = tid >> 5, lane = tid & 31;
  if (lane == 0) sh[w] = m;
  __syncthreads();
  if (w == 0) {
    m = (lane < 8) ? sh[lane] : -1e30f;
    for (int o = 16; o; o >>= 1) m = fmaxf(m, __shfl_xor_sync(~0u, m, o));
    if (lane == 0) bc = m;
  }
  __syncthreads();
  m = bc;
  float s = 0.f;
#pragma unroll
  for (int k = 0; k < 10; k++) {
    if (k * 256 + tid < cT) {
      v[k] = fexp(v[k] - m);
      s += v[k];
    }
  }
  for (int o = 16; o; o >>= 1) s += __shfl_xor_sync(~0u, s, o);
  __syncthreads();
  if (lane == 0) sh[w] = s;
  __syncthreads();
  if (w == 0) {
    s = (lane < 8) ? sh[lane] : 0.f;
    for (int o = 16; o; o >>= 1) s += __shfl_xor_sync(~0u, s, o);
    if (lane == 0) bc = 1.f / s;
  }
  __syncthreads();
  float inv = bc;
#pragma unroll
  for (int k = 0; k < 10; k++) {
    int c = k * 256 + tid;
    if (c < cT) {
      float p = v[k] * inv;
      bf16 hh = __float2bfloat16(p);
      ph[c] = hh;
      pl[c] = __float2bfloat16(p - __bfloat162float(hh));
    }
  }
}

// ---------------------------------------------------------------------------
// AV on MMA -> att written TILED (Kd=1536 blob) for the Wo bulk GEMM
// ---------------------------------------------------------------------------
#define AV_PSTR 72
#define AV_VSTR 104
#define AV_PARR (64 * AV_PSTR * 2)
#define AV_VARR (64 * AV_VSTR * 2)
#define AV_STAGE (2 * AV_PARR + 2 * AV_VARR)
#define AV_SMEM (2 * AV_STAGE)
__global__ __launch_bounds__(256) void attn_av_mma(
    const bf16* __restrict__ Ph, const bf16* __restrict__ Pl,
    const bf16* __restrict__ Vh, const bf16* __restrict__ Vl,
    bf16* __restrict__ OhiT, bf16* __restrict__ OloT) {
  extern __shared__ char sm[];
  const uint32_t sb = smem_u32(sm);
  const int tid = threadIdx.x, lane = tid & 31, wid = tid >> 5;
  const int bh = blockIdx.x, b = bh >> 4, h = bh & 15;
  const int wm = wid >> 1, wn = wid & 1;

  auto load_chunk = [&](int ct, int buf) {
    int t0 = ct * 64;
    uint32_t base = sb + buf * AV_STAGE;
#pragma unroll
    for (int it = 0; it < 2; it++) {
      int e = tid + it * 256;
      int r = e >> 3, u = e & 7;
      uint32_t so = r * (AV_PSTR * 2) + u * 16;
      size_t po = (size_t)(bh * cL + r) * cT + t0 + u * 8;
      cp_async16(base + so, Ph + po);
      cp_async16(base + AV_PARR + so, Pl + po);
    }
#pragma unroll
    for (int it = 0; it < 3; it++) {
      int e = tid + it * 256;
      int r = e / 12, u = e % 12;
      uint32_t so = r * (AV_VSTR * 2) + u * 16;
      size_t vo = (size_t)(b * cT + t0 + r) * cHHD + h * cHD + u * 8;
      cp_async16(base + 2 * AV_PARR + so, Vh + vo);
      cp_async16(base + 2 * AV_PARR + AV_VARR + so, Vl + vo);
    }
    CP_COMMIT();
  };

  float acc[6][4];
#pragma unroll
  for (int nt = 0; nt < 6; nt++)
#pragma unroll
    for (int j = 0; j < 4; j++) acc[nt][j] = 0.f;

  load_chunk(0, 0);
  for (int ct = 0; ct < 37; ct++) {
    int buf = ct & 1;
    if (ct + 1 < 37) {
      load_chunk(ct + 1, buf ^ 1);
      CP_WAIT(1);
    } else {
      CP_WAIT(0);
    }
    __syncthreads();
    uint32_t base = sb + buf * AV_STAGE;
#pragma unroll
    for (int ks = 0; ks < 4; ks++) {
      uint32_t kb = ks * 16;
      uint32_t ap[4], al[4];
      uint32_t aa = base + (wm * 16 + (lane & 15)) * (AV_PSTR * 2) + kb * 2 +
                    (lane >> 4) * 16;
      ldsm_x4(ap, aa);
      ldsm_x4(al, aa + AV_PARR);
      uint32_t bv[6][2], blv[6][2];
#pragma unroll
      for (int nt = 0; nt < 6; nt++) {
        uint32_t ba = base + 2 * AV_PARR +
                      (kb + ((lane >> 3) & 1) * 8 + (lane & 7)) * (AV_VSTR * 2) +
                      (wn * 48 + nt * 8) * 2;
        ldsm_x2_trans(bv[nt], ba);
        ldsm_x2_trans(blv[nt], ba + AV_VARR);
      }
#pragma unroll
      for (int nt = 0; nt < 6; nt++) mma16816(acc[nt], ap, bv[nt]);
#pragma unroll
      for (int nt = 0; nt < 6; nt++) mma16816(acc[nt], ap, blv[nt]);
#pragma unroll
      for (int nt = 0; nt < 6; nt++) mma16816(acc[nt], al, bv[nt]);
    }
    __syncthreads();
  }

#pragma unroll
  for (int half = 0; half < 2; half++) {
    int row = b * cL + wm * 16 + (lane >> 2) + half * 8;
#pragma unroll
    for (int nt = 0; nt < 6; nt++) {
      int col = h * cHD + wn * 48 + nt * 8 + (lane & 3) * 2;
      float v0 = acc[nt][half * 2], v1 = acc[nt][half * 2 + 1];
      bf16 h0 = __float2bfloat16(v0), h1 = __float2bfloat16(v1);
      size_t off = ((size_t)(row >> 7) * 48 + (col >> 5)) * 5120 +
                   (row & 127) * 40 + (col & 31);
      *(__nv_bfloat162*)(OhiT + off) = __nv_bfloat162(h0, h1);
      *(__nv_bfloat162*)(OloT + off) = __nv_bfloat162(
          __float2bfloat16(v0 - __bfloat162float(h0)),
          __float2bfloat16(v1 - __bfloat162float(h1)));
    }
  }
}

// ---------------------------------------------------------------------------
// LN (no affine) -> TILED bf16 hi/lo blob (row length cD, nc=40)
// ---------------------------------------------------------------------------
__global__ void ln_tiled_kernel(const float* __restrict__ x,
                                bf16* __restrict__ hi, bf16* __restrict__ lo) {
  int row = blockIdx.x;
  const float* xr = x + (size_t)row * cD;
  float s = 0.f, s2 = 0.f;
  for (int c = threadIdx.x; c < cD; c += 256) {
    float v = xr[c];
    s += v; s2 += v * v;
  }
  __shared__ float sh[64];
  for (int o = 16; o; o >>= 1) {
    s += __shfl_xor_sync(~0u, s, o);
    s2 += __shfl_xor_sync(~0u, s2, o);
  }
  int w = threadIdx.x >> 5, lane = threadIdx.x & 31;
  if (lane == 0) { sh[w] = s; sh[w + 32] = s2; }
  __syncthreads();
  if (w == 0) {
    s = (lane < 8) ? sh[lane] : 0.f;
    s2 = (lane < 8) ? sh[lane + 32] : 0.f;
    for (int o = 16; o; o >>= 1) {
      s += __shfl_xor_sync(~0u, s, o);
      s2 += __shfl_xor_sync(~0u, s2, o);
    }
    if (lane == 0) { sh[0] = s; sh[1] = s2; }
  }
  __syncthreads();
  float mean = sh[0] * (1.f / cD);
  float rstd = rsqrtf(sh[1] * (1.f / cD) - mean * mean + cEPS);
  size_t rowbase = (size_t)(row >> 7) * cNCC * 5120 + (size_t)(row & 127) * 40;
  for (int c = threadIdx.x; c < cD; c += 256) {
    float v = (xr[c] - mean) * rstd;
    bf16 h = __float2bfloat16(v);
    size_t off = rowbase + (size_t)(c >> 5) * 5120 + (c & 31);
    hi[off] = h;
    lo[off] = __float2bfloat16(v - __bfloat162float(h));
  }
}

// ---------------------------------------------------------------------------
// Tiled weight prep (any Kdim/Nw): Wt blob + rank-1 bias
// ---------------------------------------------------------------------------
__global__ void wprep_tiled_kernel(const float* __restrict__ W,
                                   const float* __restrict__ g,
                                   const float* __restrict__ b,
                                   bf16* __restrict__ Whi,
                                   bf16* __restrict__ Wlo,
                                   float* __restrict__ bias, int Kdim, int Nw) {
  int n = blockIdx.x;
  int nc = Kdim >> 5;
  float bs = 0.f;
  size_t rowbase = (size_t)(n >> 7) * nc * 5120 + (size_t)(n & 127) * 40;
  for (int k = threadIdx.x; k < Kdim; k += 256) {
    float w = W[(size_t)k * Nw + n];
    float v = (g != nullptr) ? g[k] * w : w;
    bf16 h = __float2bfloat16(v);
    size_t off = rowbase + (size_t)(k >> 5) * 5120 + (k & 31);
    Whi[off] = h;
    Wlo[off] = __float2bfloat16(v - __bfloat162float(h));
    if (b != nullptr) bs += b[k] * w;
  }
  if (bias != nullptr) {
    __shared__ float sh[8];
    for (int o = 16; o; o >>= 1) bs += __shfl_xor_sync(~0u, bs, o);
    int w8 = threadIdx.x >> 5, lane = threadIdx.x & 31;
    if (lane == 0) sh[w8] = bs;
    __syncthreads();
    if (threadIdx.x == 0) {
      float t = 0.f;
      for (int i = 0; i < 8; i++) t += sh[i];
      bias[n] = t;
    }
  }
}

// ---------------------------------------------------------------------------
// Broadcast latents
// ---------------------------------------------------------------------------
__global__ void bcast_latents_kernel(const float* __restrict__ lat,
                                     float* __restrict__ out) {
  int idx = blockIdx.x * 256 + threadIdx.x;
  out[idx] = lat[idx % (cL * cD)];
}

// ---------------------------------------------------------------------------
// Final LayerNorm with affine
// ---------------------------------------------------------------------------
__global__ void ln_rows_kernel(const float* __restrict__ x,
                               float* __restrict__ y,
                               const float* __restrict__ g,
                               const float* __restrict__ b) {
  int row = blockIdx.x;
  const float* xr = x + (size_t)row * cD;
  float* yr = y + (size_t)row * cD;
  float s = 0.f, s2 = 0.f;
  for (int c = threadIdx.x; c < cD; c += 256) {
    float v = xr[c];
    s += v; s2 += v * v;
  }
  __shared__ float sh[64];
  for (int o = 16; o; o >>= 1) {
    s += __shfl_xor_sync(~0u, s, o);
    s2 += __shfl_xor_sync(~0u, s2, o);
  }
  int w = threadIdx.x >> 5, lane = threadIdx.x & 31;
  if (lane == 0) { sh[w] = s; sh[w + 32] = s2; }
  __syncthreads();
  if (w == 0) {
    s = (lane < 8) ? sh[lane] : 0.f;
    s2 = (lane < 8) ? sh[lane + 32] : 0.f;
    for (int o = 16; o; o >>= 1) {
      s += __shfl_xor_sync(~0u, s, o);
      s2 += __shfl_xor_sync(~0u, s2, o);
    }
    if (lane == 0) { sh[0] = s; sh[1] = s2; }
  }
  __syncthreads();
  float mean = sh[0] * (1.f / cD);
  float rstd = rsqrtf(sh[1] * (1.f / cD) - mean * mean + cEPS);
  for (int c = threadIdx.x; c < cD; c += 256)
    yr[c] = (xr[c] - mean) * rstd * g[c] + b[c];
}

// ---------------------------------------------------------------------------
// Per-head LN -> bf16 hi/lo (linear)
// ---------------------------------------------------------------------------
__global__ void ln_head_split_kernel(const float* __restrict__ x,
                                     const float* __restrict__ g,
                                     const float* __restrict__ b,
                                     bf16* __restrict__ hi,
                                     bf16* __restrict__ lo, int nrows) {
  int r = blockIdx.x * 4 + (threadIdx.x >> 5);
  if (r >= nrows) return;
  int lane = threadIdx.x & 31;
  const float* xr = x + (size_t)r * cHD;
  float v0 = xr[lane], v1 = xr[lane + 32], v2 = xr[lane + 64];
  float s = v0 + v1 + v2;
  float s2 = v0 * v0 + v1 * v1 + v2 * v2;
  for (int o = 16; o; o >>= 1) {
    s += __shfl_xor_sync(~0u, s, o);
    s2 += __shfl_xor_sync(~0u, s2, o);
  }
  float mean = s * (1.f / 96.f);
  float rstd = rsqrtf(s2 * (1.f / 96.f) - mean * mean + cEPS);
  float y0 = (v0 - mean) * rstd * g[lane] + b[lane];
  float y1 = (v1 - mean) * rstd * g[lane + 32] + b[lane + 32];
  float y2 = (v2 - mean) * rstd * g[lane + 64] + b[lane + 64];
  bf16* hr = hi + (size_t)r * cHD;
  bf16* lr = lo + (size_t)r * cHD;
  bf16 h0 = __float2bfloat16(y0), h1 = __float2bfloat16(y1),
       h2 = __float2bfloat16(y2);
  hr[lane] = h0; hr[lane + 32] = h1; hr[lane + 64] = h2;
  lr[lane] = __float2bfloat16(y0 - __bfloat162float(h0));
  lr[lane + 32] = __float2bfloat16(y1 - __bfloat162float(h1));
  lr[lane + 64] = __float2bfloat16(y2 - __bfloat162float(h2));
}

// ---------------------------------------------------------------------------
// Host orchestration
// ---------------------------------------------------------------------------
extern "C" void kernel_launch(void* const* d_in, const int* in_sizes, int n_in,
                              void* d_out, int out_size) {
  (void)in_sizes; (void)n_in; (void)out_size;
  const float* context = (const float*)d_in[0];
  const float* latents = (const float*)d_in[1];
  const float* ctx_g = (const float*)d_in[2];
  const float* ctx_b = (const float*)d_in[3];
  const float* lat_g = (const float*)d_in[4];
  const float* lat_b = (const float*)d_in[5];
  const float* q_g = (const float*)d_in[6];
  const float* q_b = (const float*)d_in[7];
  const float* k_g = (const float*)d_in[8];
  const float* k_b = (const float*)d_in[9];
  const float* Wq = (const float*)d_in[10];
  const float* Wk = (const float*)d_in[11];
  const float* Wv = (const float*)d_in[12];
  const float* Wo = (const float*)d_in[13];
  const float* mlp_g = (const float*)d_in[14];
  const float* mlp_b = (const float*)d_in[15];
  const float* Wfc = (const float*)d_in[16];
  const float* Wcp = (const float*)d_in[17];
  const float* f_g = (const float*)d_in[18];
  const float* f_b = (const float*)d_in[19];
  float* out = (float*)d_out;

#define SYM(var, sym) cudaGetSymbolAddress((void**)&var, sym)
  bf16 *ctxTh, *ctxTl, *lnTh, *lnTl, *attTh, *attTl, *mlpTh, *mlpTl;
  bf16 *qhi, *qlo, *khi, *klo, *vhi, *vlo, *phi, *plo;
  bf16 *wkcTh, *wkcTl, *wvcTh, *wvcTl, *wqTh, *wqTl, *wklTh, *wklTl, *wvlTh,
      *wvlTl, *woTh, *woTl, *wfcTh, *wfcTl, *wcpTh, *wcpTl;
  float *bQ, *bKc, *bKl, *bVc, *bVl, *bFc;
  float *lat, *Qp, *Kp, *Scp;
  SYM(ctxTh, g_ctxT_hi); SYM(ctxTl, g_ctxT_lo);
  SYM(lnTh, g_latlnT_hi); SYM(lnTl, g_latlnT_lo);
  SYM(attTh, g_attT_hi); SYM(attTl, g_attT_lo);
  SYM(mlpTh, g_mlpT_hi); SYM(mlpTl, g_mlpT_lo);
  SYM(qhi, g_Q_hi); SYM(qlo, g_Q_lo);
  SYM(khi, g_K_hi); SYM(klo, g_K_lo);
  SYM(vhi, g_V_hi); SYM(vlo, g_V_lo);
  SYM(phi, g_P_hi); SYM(plo, g_P_lo);
  SYM(wkcTh, g_wkcT_hi); SYM(wkcTl, g_wkcT_lo);
  SYM(wvcTh, g_wvcT_hi); SYM(wvcTl, g_wvcT_lo);
  SYM(wqTh, g_wqT_hi); SYM(wqTl, g_wqT_lo);
  SYM(wklTh, g_wklT_hi); SYM(wklTl, g_wklT_lo);
  SYM(wvlTh, g_wvlT_hi); SYM(wvlTl, g_wvlT_lo);
  SYM(woTh, g_woT_hi); SYM(woTl, g_woT_lo);
  SYM(wfcTh, g_wfcT_hi); SYM(wfcTl, g_wfcT_lo);
  SYM(wcpTh, g_wcpT_hi); SYM(wcpTl, g_wcpT_lo);
  SYM(bQ, g_biasQ); SYM(bKc, g_biasKc); SYM(bKl, g_biasKl);
  SYM(bVc, g_biasVc); SYM(bVl, g_biasVl); SYM(bFc, g_biasFc);
  SYM(lat, g_lat); SYM(Qp, g_Q); SYM(Kp, g_K); SYM(Scp, g_scores);
#undef SYM

  cudaFuncSetAttribute(fused_kv_bulk,
                       cudaFuncAttributeMaxDynamicSharedMemorySize, FB_SMEM);
  cudaFuncSetAttribute(mma_gemm_bulk,
                       cudaFuncAttributeMaxDynamicSharedMemorySize, GB_SMEM);
  cudaFuncSetAttribute(attn_scores_mma,
                       cudaFuncAttributeMaxDynamicSharedMemorySize, SCM_SMEM);
  cudaFuncSetAttribute(attn_av_mma,
                       cudaFuncAttributeMaxDynamicSharedMemorySize, AV_SMEM);

  dim3 kvGridCtx(12, cMB);       // (1536/128, 576)
  dim3 kvGridLat(12, cML / 128); // (12, 16)

  // launch 0: LN(context) -> tiled (once)
  ln_tiled_kernel<<<cMCTX, 256>>>(context, ctxTh, ctxTl);
  // launches 1,2: layer-0 ctx weight preps
  wprep_tiled_kernel<<<cHHD, 256>>>(Wk, ctx_g, ctx_b, wkcTh, wkcTl, bKc, cD,
                                    cHHD);
  wprep_tiled_kernel<<<cHHD, 256>>>(Wv, ctx_g, ctx_b, wvcTh, wvcTl, bVc, cD,
                                    cHHD);
  // launch 3: layer-0 fused ctx K+V projection  << ncu capture slot >>
  fused_kv_bulk<<<kvGridCtx, 512, FB_SMEM>>>(ctxTh, ctxTl, wkcTh, wkcTl, wvcTh,
                                             wvcTl, bKc, bVc, Kp, vhi, vlo, cS,
                                             cT, 0);
  bcast_latents_kernel<<<(cML * cD) / 256, 256>>>(latents, lat);

  for (int i = 0; i < cDEPTH; i++) {
    const float* Wq_i = Wq + (size_t)i * cD * cHHD;
    const float* Wk_i = Wk + (size_t)i * cD * cHHD;
    const float* Wv_i = Wv + (size_t)i * cD * cHHD;
    const float* Wo_i = Wo + (size_t)i * cHHD * cD;
    const float* Wfc_i = Wfc + (size_t)i * cD * cI;
    const float* Wcp_i = Wcp + (size_t)i * cI * cD;
    const float* lg = lat_g + i * cD;
    const float* lb = lat_b + i * cD;

    if (i > 0) {
      wprep_tiled_kernel<<<cHHD, 256>>>(Wk_i, ctx_g + i * cD, ctx_b + i * cD,
                                        wkcTh, wkcTl, bKc, cD, cHHD);
      wprep_tiled_kernel<<<cHHD, 256>>>(Wv_i, ctx_g + i * cD, ctx_b + i * cD,
                                        wvcTh, wvcTl, bVc, cD, cHHD);
      fused_kv_bulk<<<kvGridCtx, 512, FB_SMEM>>>(ctxTh, ctxTl, wkcTh, wkcTl,
                                                 wvcTh, wvcTl, bKc, bVc, Kp,
                                                 vhi, vlo, cS, cT, 0);
    }

    // LN(latents) -> tiled hi/lo (affine folded into weights)
    ln_tiled_kernel<<<cML, 256>>>(lat, lnTh, lnTl);

    wprep_tiled_kernel<<<cHHD, 256>>>(Wq_i, lg, lb, wqTh, wqTl, bQ, cD, cHHD);
    wprep_tiled_kernel<<<cHHD, 256>>>(Wk_i, lg, lb, wklTh, wklTl, bKl, cD,
                                      cHHD);
    wprep_tiled_kernel<<<cHHD, 256>>>(Wv_i, lg, lb, wvlTh, wvlTl, bVl, cD,
                                      cHHD);

    // Q (fp32 out for per-head LN)
    mma_gemm_bulk<<<dim3(12, 16), 256, GB_SMEM>>>(
        lnTh, lnTl, wqTh, wqTl, bQ, nullptr, Qp, nullptr, nullptr, cD, cHHD,
        cHHD, 0);
    // latent K+V rows appended at offset cS
    fused_kv_bulk<<<kvGridLat, 512, FB_SMEM>>>(lnTh, lnTl, wklTh, wklTl, wvlTh,
                                               wvlTl, bKl, bVl, Kp, vhi, vlo,
                                               cL, cT, cS);

    // per-head q/k LN -> hi/lo (linear)
    ln_head_split_kernel<<<(cML * cH) / 4, 128>>>(Qp, q_g + i * cHD,
                                                  q_b + i * cHD, qhi, qlo,
                                                  cML * cH);
    ln_head_split_kernel<<<(cB * cT * cH) / 4, 128>>>(Kp, k_g + i * cHD,
                                                      k_b + i * cHD, khi, klo,
                                                      cB * cT * cH);

    // attention on MMA (att written tiled)
    attn_scores_mma<<<dim3(cT / 64, cB * cH), 256, SCM_SMEM>>>(qhi, qlo, khi,
                                                               klo, Scp);
    softmax_split_kernel<<<cB * cH * cL, 256>>>(Scp, phi, plo);
    attn_av_mma<<<cB * cH, 256, AV_SMEM>>>(phi, plo, vhi, vlo, attTh, attTl);

    // lat = att @ Wo + lat
    wprep_tiled_kernel<<<cD, 256>>>(Wo_i, nullptr, nullptr, woTh, woTl,
                                    nullptr, cHHD, cD);
    mma_gemm_bulk<<<dim3(10, 16), 256, GB_SMEM>>>(
        attTh, attTl, woTh, woTl, nullptr, lat, lat, nullptr, nullptr, cHHD,
        cD, cD, 0);

    // MLP
    ln_tiled_kernel<<<cML, 256>>>(lat, lnTh, lnTl);
    wprep_tiled_kernel<<<cI, 256>>>(Wfc_i, mlp_g + i * cD, mlp_b + i * cD,
                                    wfcTh, wfcTl, bFc, cD, cI);
    mma_gemm_bulk<<<dim3(40, 16), 256, GB_SMEM>>>(
        lnTh, lnTl, wfcTh, wfcTl, bFc, nullptr, nullptr, mlpTh, mlpTl, cD, cI,
        cI, 1);
    wprep_tiled_kernel<<<cD, 256>>>(Wcp_i, nullptr, nullptr, wcpTh, wcpTl,
                                    nullptr, cI, cD);
    mma_gemm_bulk<<<dim3(10, 16), 256, GB_SMEM>>>(
        mlpTh, mlpTl, wcpTh, wcpTl, nullptr, lat, lat, nullptr, nullptr, cI,
        cD, cD, 0);
  }

  ln_rows_kernel<<<cML, 256>>>(lat, out, f_g, f_b);
}

// round 12
// speedup vs baseline: 1.2400x; 1.0250x over previous
#include <cuda_runtime.h>
#include <cuda_bf16.h>
#include <cstdint>
#include <cstddef>

// ---------------------------------------------------------------------------
// Problem constants
// ---------------------------------------------------------------------------
#define cB 32
#define cS 2304
#define cD 1280
#define cDEPTH 6
#define cH 16
#define cHD 96
#define cL 64
#define cI 5120
#define cT (cS + cL)      /* 2368 */
#define cHHD (cH * cHD)   /* 1536 */
#define cEPS 1e-5f
#define cMCTX (cB * cS)   /* 73728 ctx rows */
#define cML (cB * cL)     /* 2048 latent rows */
#define cMB (cMCTX / 128) /* 576 ctx row-blocks */
#define cNCC (cD / 32)    /* 40 k-chunks for Kdim=1280 */

typedef __nv_bfloat16 bf16;

// Tiled blob: (row>>7, k>>5) chunk of 128 rows x 32 elems, stored 128x40 elems
#define TBE(blocks, nc) ((size_t)(blocks) * (nc) * 5120)

// ---------------------------------------------------------------------------
// Scratch (device globals: allocation-free rule)
// ---------------------------------------------------------------------------
__device__ bf16 g_ctxT_hi[TBE(cMB, 40)], g_ctxT_lo[TBE(cMB, 40)];
__device__ bf16 g_latlnT_hi[TBE(16, 40)], g_latlnT_lo[TBE(16, 40)];
__device__ bf16 g_attT_hi[TBE(16, 48)], g_attT_lo[TBE(16, 48)];
__device__ bf16 g_mlpT_hi[TBE(16, 160)], g_mlpT_lo[TBE(16, 160)];
__device__ bf16 g_wkcT_hi[TBE(12, 40)], g_wkcT_lo[TBE(12, 40)];
__device__ bf16 g_wvcT_hi[TBE(12, 40)], g_wvcT_lo[TBE(12, 40)];
__device__ bf16 g_wqT_hi[TBE(12, 40)],  g_wqT_lo[TBE(12, 40)];
__device__ bf16 g_wklT_hi[TBE(12, 40)], g_wklT_lo[TBE(12, 40)];
__device__ bf16 g_wvlT_hi[TBE(12, 40)], g_wvlT_lo[TBE(12, 40)];
__device__ bf16 g_woT_hi[TBE(10, 48)],  g_woT_lo[TBE(10, 48)];
__device__ bf16 g_wfcT_hi[TBE(40, 40)], g_wfcT_lo[TBE(40, 40)];
__device__ bf16 g_wcpT_hi[TBE(10, 160)], g_wcpT_lo[TBE(10, 160)];
// linear buffers
__device__ bf16 g_V_hi[(size_t)cB * cT * cHHD], g_V_lo[(size_t)cB * cT * cHHD];
__device__ bf16 g_P_hi[(size_t)cB * cH * cL * cT];
__device__ bf16 g_P_lo[(size_t)cB * cH * cL * cT];
__device__ float g_biasQ[cHHD], g_biasKc[cHHD], g_biasKl[cHHD];
__device__ float g_biasVc[cHHD], g_biasVl[cHHD], g_biasFc[cI];
__device__ float g_lat[cML * cD];
__device__ float g_Q[cML * cHHD];
__device__ float g_K[(size_t)cB * cT * cHHD];
__device__ float g_scores[(size_t)cB * cH * cL * cT];

// ---------------------------------------------------------------------------
// PTX helpers (base sm_90 features only)
// ---------------------------------------------------------------------------
__device__ __forceinline__ uint32_t smem_u32(const void* p) {
  uint32_t a;
  asm("{ .reg .u64 t; cvta.to.shared.u64 t, %1; cvt.u32.u64 %0, t; }"
      : "=r"(a) : "l"(p));
  return a;
}
__device__ __forceinline__ void cp_async16(uint32_t saddr, const void* gptr) {
  asm volatile("cp.async.cg.shared.global [%0], [%1], 16;" ::"r"(saddr),
               "l"(gptr)
               : "memory");
}
#define CP_COMMIT() asm volatile("cp.async.commit_group;" ::: "memory")
#define CP_WAIT(N) asm volatile("cp.async.wait_group %0;" ::"n"(N) : "memory")

__device__ __forceinline__ void bulk_g2s(uint32_t dst, const void* src,
                                         uint32_t bytes, uint32_t bar) {
  asm volatile(
      "cp.async.bulk.shared::cta.global.mbarrier::complete_tx::bytes "
      "[%0], [%1], %2, [%3];"
      :: "r"(dst), "l"(src), "r"(bytes), "r"(bar)
      : "memory");
}
#define MBAR_INIT(mb, n)                                                   \
  asm volatile("mbarrier.init.shared.b64 [%0], %1;" ::"r"((uint32_t)(mb)), \
               "r"((uint32_t)(n))                                          \
               : "memory")
#define MBAR_EXPECT_TX(mb, n)                                              \
  asm volatile("mbarrier.arrive.expect_tx.shared.b64 _, [%0], %1;" ::"r"(  \
                   (uint32_t)(mb)),                                        \
               "r"((uint32_t)(n))                                          \
               : "memory")
#define MBAR_WAIT(mb, par) do {                                              \
  uint32_t _mb = (uint32_t)(mb), _p = (uint32_t)(par), _d;                   \
  asm volatile(                                                              \
      "{\n\t.reg .pred p;\n\t"                                               \
      "mbarrier.try_wait.parity.acquire.cta.shared::cta.b64 p, [%1], %2;\n\t"\
      "selp.b32 %0, 1, 0, p;\n\t}"                                           \
      : "=r"(_d) : "r"(_mb), "r"(_p) : "memory");                            \
  if (!_d) {                                                                 \
    asm volatile(                                                            \
        "{\n\t.reg .pred P1;\n\t"                                            \
        "W1_%=:\n\t"                                                         \
        "mbarrier.try_wait.parity.acquire.cta.shared::cta.b64 P1, [%0], %1, 0x989680;\n\t" \
        "@P1 bra.uni W2_%=;\n\tbra.uni W1_%=;\n\tW2_%=:\n\t}"                \
        :: "r"(_mb), "r"(_p) : "memory");                                    \
  }                                                                          \
} while (0)

__device__ __forceinline__ void ldsm_x4(uint32_t* d, uint32_t addr) {
  asm volatile("ldmatrix.sync.aligned.m8n8.x4.shared.b16 {%0,%1,%2,%3},[%4];"
               : "=r"(d[0]), "=r"(d[1]), "=r"(d[2]), "=r"(d[3])
               : "r"(addr));
}
__device__ __forceinline__ void ldsm_x2(uint32_t* d, uint32_t addr) {
  asm volatile("ldmatrix.sync.aligned.m8n8.x2.shared.b16 {%0,%1},[%2];"
               : "=r"(d[0]), "=r"(d[1])
               : "r"(addr));
}
__device__ __forceinline__ void ldsm_x2_trans(uint32_t* d, uint32_t addr) {
  asm volatile("ldmatrix.sync.aligned.m8n8.x2.trans.shared.b16 {%0,%1},[%2];"
               : "=r"(d[0]), "=r"(d[1])
               : "r"(addr));
}
__device__ __forceinline__ void mma16816(float* c, const uint32_t* a,
                                         const uint32_t* b) {
  asm volatile(
      "mma.sync.aligned.m16n8k16.row.col.f32.bf16.bf16.f32 "
      "{%0,%1,%2,%3},{%4,%5,%6,%7},{%8,%9},{%0,%1,%2,%3};"
      : "+f"(c[0]), "+f"(c[1]), "+f"(c[2]), "+f"(c[3])
      : "r"(a[0]), "r"(a[1]), "r"(a[2]), "r"(a[3]), "r"(b[0]), "r"(b[1]));
}

// Fast exp on the FMA pipe (degree-6 2^f poly; rel err ~8e-6).
__device__ __forceinline__ float fexp(float x) {
  x = fmaxf(x, -87.0f);
  float t = x * 1.4426950408889634f;
  float fi = floorf(t);
  float f = t - fi;
  float p = 1.54035304e-4f;
  p = fmaf(p, f, 1.33335581e-3f);
  p = fmaf(p, f, 9.61812911e-3f);
  p = fmaf(p, f, 5.55041087e-2f);
  p = fmaf(p, f, 2.40226507e-1f);
  p = fmaf(p, f, 6.93147181e-1f);
  p = fmaf(p, f, 1.0f);
  int i = (int)fi;
  return p * __int_as_float((i + 127) << 23);
}

// ---------------------------------------------------------------------------
// Fused K+V GEMM, bulk loader (tiled operands, Kd=1280 fixed).
// ---------------------------------------------------------------------------
#define FB_STRIDE 40
#define FB_ARR 10240
#define FB_CHUNK (6 * FB_ARR)
#define FB_HDR 1024
#define FB_SMEM (FB_HDR + 3 * FB_CHUNK)

__global__ __launch_bounds__(512) void fused_kv_bulk(
    const bf16* __restrict__ AThi, const bf16* __restrict__ ATlo,
    const bf16* __restrict__ BkThi, const bf16* __restrict__ BkTlo,
    const bf16* __restrict__ BvThi, const bf16* __restrict__ BvTlo,
    const float* __restrict__ biasK, const float* __restrict__ biasV,
    float* __restrict__ Kout, bf16* __restrict__ Vhi, bf16* __restrict__ Vlo,
    int rpbIn, int rpbOut, int rowOff) {
  extern __shared__ char sm[];
  const uint32_t sb = smem_u32(sm);
  const int tid = threadIdx.x, lane = tid & 31, wid = tid >> 5;
  const int grp = wid >> 3;  // 0=K, 1=V
  const int gw = wid & 7;
  const int wm = gw & 1, wn = gw >> 1;
  const int mb = blockIdx.y, nb = blockIdx.x;
  const int m0 = mb * 128, n0 = nb * 128;

  const char* srcs[6];
  srcs[0] = (const char*)AThi + (size_t)mb * cNCC * FB_ARR;
  srcs[1] = (const char*)ATlo + (size_t)mb * cNCC * FB_ARR;
  srcs[2] = (const char*)BkThi + (size_t)nb * cNCC * FB_ARR;
  srcs[3] = (const char*)BkTlo + (size_t)nb * cNCC * FB_ARR;
  srcs[4] = (const char*)BvThi + (size_t)nb * cNCC * FB_ARR;
  srcs[5] = (const char*)BvTlo + (size_t)nb * cNCC * FB_ARR;

  if (tid == 0) {
    MBAR_INIT(sb + 0, 1);
    MBAR_INIT(sb + 8, 1);
    MBAR_INIT(sb + 16, 1);
  }
  __syncthreads();

  auto issue = [&](int c) {
    int s = c % 3;
    uint32_t bar = sb + s * 8;
    MBAR_EXPECT_TX(bar, FB_CHUNK);
    uint32_t dst = sb + FB_HDR + s * FB_CHUNK;
#pragma unroll
    for (int a = 0; a < 6; a++)
      bulk_g2s(dst + a * FB_ARR, srcs[a] + (size_t)c * FB_ARR, FB_ARR, bar);
  };
  if (tid == 0) { issue(0); issue(1); }

  float acc[4][4][4];
#pragma unroll
  for (int mt = 0; mt < 4; mt++)
#pragma unroll
    for (int nt = 0; nt < 4; nt++)
#pragma unroll
      for (int j = 0; j < 4; j++) acc[mt][nt][j] = 0.f;

  const uint32_t aRow = (wm * 64 + (lane & 15)) * (FB_STRIDE * 2);
  const uint32_t aColB = ((lane >> 4) << 3) * 2;
  const uint32_t bRow = (wn * 32 + (lane & 7)) * (FB_STRIDE * 2);
  const uint32_t bColB = (((lane >> 3) & 1) << 3) * 2;
  const uint32_t bOff = (grp ? 4u : 2u) * FB_ARR;

  for (int c = 0; c < cNCC; c++) {
    MBAR_WAIT(sb + (c % 3) * 8, (c / 3) & 1);
    __syncthreads();
    if (tid == 0 && c + 2 < cNCC) issue(c + 2);
    uint32_t base = sb + FB_HDR + (c % 3) * FB_CHUNK;
#pragma unroll
    for (int ks = 0; ks < 2; ks++) {
      uint32_t kb = ks * 32;
      uint32_t ah[4][4], al[4][4];
#pragma unroll
      for (int mt = 0; mt < 4; mt++) {
        uint32_t ad = base + aRow + mt * 16 * (FB_STRIDE * 2) + kb + aColB;
        ldsm_x4(ah[mt], ad);
        ldsm_x4(al[mt], ad + FB_ARR);
      }
#pragma unroll
      for (int nt = 0; nt < 4; nt++) {
        uint32_t bd = base + bOff + bRow + nt * 8 * (FB_STRIDE * 2) + kb + bColB;
        uint32_t bh2[2], bl2[2];
        ldsm_x2(bh2, bd);
        ldsm_x2(bl2, bd + FB_ARR);
#pragma unroll
        for (int mt = 0; mt < 4; mt++) mma16816(acc[mt][nt], ah[mt], bh2);
#pragma unroll
        for (int mt = 0; mt < 4; mt++) mma16816(acc[mt][nt], ah[mt], bl2);
#pragma unroll
        for (int mt = 0; mt < 4; mt++) mma16816(acc[mt][nt], al[mt], bh2);
      }
    }
  }

#pragma unroll
  for (int mt = 0; mt < 4; mt++) {
    int mloc = wm * 64 + mt * 16 + (lane >> 2);
#pragma unroll
    for (int half = 0; half < 2; half++) {
      int m = m0 + mloc + half * 8;
      int orow = (m / rpbIn) * rpbOut + rowOff + (m % rpbIn);
#pragma unroll
      for (int nt = 0; nt < 4; nt++) {
        int n = n0 + wn * 32 + nt * 8 + (lane & 3) * 2;
        float v0 = acc[mt][nt][half * 2 + 0];
        float v1 = acc[mt][nt][half * 2 + 1];
        if (grp == 0) {
          v0 += biasK[n]; v1 += biasK[n + 1];
          *(float2*)(Kout + (size_t)orow * cHHD + n) = make_float2(v0, v1);
        } else {
          v0 += biasV[n]; v1 += biasV[n + 1];
          bf16 h0 = __float2bfloat16(v0), h1 = __float2bfloat16(v1);
          *(__nv_bfloat162*)(Vhi + (size_t)orow * cHHD + n) =
              __nv_bfloat162(h0, h1);
          *(__nv_bfloat162*)(Vlo + (size_t)orow * cHHD + n) = __nv_bfloat162(
              __float2bfloat16(v0 - __bfloat162float(h0)),
              __float2bfloat16(v1 - __bfloat162float(h1)));
        }
      }
    }
  }
}

// ---------------------------------------------------------------------------
// Generalized bulk MMA GEMM (Q, Wo, Wfc, Wcp).
// ---------------------------------------------------------------------------
#define GB_ARR 10240
#define GB_CHUNK (4 * GB_ARR)
#define GB_HDR 1024
#define GB_SMEM (GB_HDR + 2 * GB_CHUNK)

__global__ __launch_bounds__(256) void mma_gemm_bulk(
    const bf16* __restrict__ ATh, const bf16* __restrict__ ATl,
    const bf16* __restrict__ BTh, const bf16* __restrict__ BTl,
    const float* __restrict__ bias, const float* __restrict__ R,
    float* __restrict__ C, bf16* __restrict__ ChiT, bf16* __restrict__ CloT,
    int Kdim, int cN, int outKd, int relu) {
  extern __shared__ char sm[];
  const uint32_t sb = smem_u32(sm);
  const int tid = threadIdx.x, lane = tid & 31, wid = tid >> 5;
  const int wm = wid & 1, wn = wid >> 1;
  const int mb = blockIdx.y, nb = blockIdx.x;
  const int m0 = mb * 128, n0 = nb * 128;
  const int nc = Kdim >> 5;

  const char* srcs[4];
  srcs[0] = (const char*)ATh + (size_t)mb * nc * GB_ARR;
  srcs[1] = (const char*)ATl + (size_t)mb * nc * GB_ARR;
  srcs[2] = (const char*)BTh + (size_t)nb * nc * GB_ARR;
  srcs[3] = (const char*)BTl + (size_t)nb * nc * GB_ARR;

  if (tid == 0) {
    MBAR_INIT(sb + 0, 1);
    MBAR_INIT(sb + 8, 1);
  }
  __syncthreads();

  auto issue = [&](int c) {
    int s = c & 1;
    uint32_t bar = sb + s * 8;
    MBAR_EXPECT_TX(bar, GB_CHUNK);
    uint32_t dst = sb + GB_HDR + s * GB_CHUNK;
#pragma unroll
    for (int a = 0; a < 4; a++)
      bulk_g2s(dst + a * GB_ARR, srcs[a] + (size_t)c * GB_ARR, GB_ARR, bar);
  };
  if (tid == 0) issue(0);

  float acc[4][4][4];
#pragma unroll
  for (int mt = 0; mt < 4; mt++)
#pragma unroll
    for (int nt = 0; nt < 4; nt++)
#pragma unroll
      for (int j = 0; j < 4; j++) acc[mt][nt][j] = 0.f;

  const uint32_t aRow = (wm * 64 + (lane & 15)) * (FB_STRIDE * 2);
  const uint32_t aColB = ((lane >> 4) << 3) * 2;
  const uint32_t bRow = (wn * 32 + (lane & 7)) * (FB_STRIDE * 2);
  const uint32_t bColB = (((lane >> 3) & 1) << 3) * 2;

  for (int c = 0; c < nc; c++) {
    MBAR_WAIT(sb + (c & 1) * 8, (c >> 1) & 1);
    __syncthreads();
    if (tid == 0 && c + 1 < nc) issue(c + 1);
    uint32_t base = sb + GB_HDR + (c & 1) * GB_CHUNK;
#pragma unroll
    for (int ks = 0; ks < 2; ks++) {
      uint32_t kb = ks * 32;
      uint32_t ah[4][4], al[4][4];
#pragma unroll
      for (int mt = 0; mt < 4; mt++) {
        uint32_t ad = base + aRow + mt * 16 * (FB_STRIDE * 2) + kb + aColB;
        ldsm_x4(ah[mt], ad);
        ldsm_x4(al[mt], ad + GB_ARR);
      }
#pragma unroll
      for (int nt = 0; nt < 4; nt++) {
        uint32_t bd =
            base + 2 * GB_ARR + bRow + nt * 8 * (FB_STRIDE * 2) + kb + bColB;
        uint32_t bh2[2], bl2[2];
        ldsm_x2(bh2, bd);
        ldsm_x2(bl2, bd + GB_ARR);
#pragma unroll
        for (int mt = 0; mt < 4; mt++) mma16816(acc[mt][nt], ah[mt], bh2);
#pragma unroll
        for (int mt = 0; mt < 4; mt++) mma16816(acc[mt][nt], ah[mt], bl2);
#pragma unroll
        for (int mt = 0; mt < 4; mt++) mma16816(acc[mt][nt], al[mt], bh2);
      }
    }
  }

  const int ncOut = outKd >> 5;
#pragma unroll
  for (int mt = 0; mt < 4; mt++) {
    int mloc = wm * 64 + mt * 16 + (lane >> 2);
#pragma unroll
    for (int half = 0; half < 2; half++) {
      int orow = m0 + mloc + half * 8;
#pragma unroll
      for (int nt = 0; nt < 4; nt++) {
        int n = n0 + wn * 32 + nt * 8 + (lane & 3) * 2;
        float v0 = acc[mt][nt][half * 2 + 0];
        float v1 = acc[mt][nt][half * 2 + 1];
        if (bias != nullptr) { v0 += bias[n]; v1 += bias[n + 1]; }
        if (R != nullptr) {
          float2 rv = *(const float2*)(R + (size_t)orow * cN + n);
          v0 += rv.x; v1 += rv.y;
        }
        if (relu) { v0 = fmaxf(v0, 0.f); v1 = fmaxf(v1, 0.f); }
        if (C != nullptr)
          *(float2*)(C + (size_t)orow * cN + n) = make_float2(v0, v1);
        if (ChiT != nullptr) {
          size_t off = ((size_t)(orow >> 7) * ncOut + (n >> 5)) * 5120 +
                       (orow & 127) * 40 + (n & 31);
          bf16 h0 = __float2bfloat16(v0);
          bf16 h1 = __float2bfloat16(v1);
          *(__nv_bfloat162*)(ChiT + off) = __nv_bfloat162(h0, h1);
          *(__nv_bfloat162*)(CloT + off) = __nv_bfloat162(
              __float2bfloat16(v0 - __bfloat162float(h0)),
              __float2bfloat16(v1 - __bfloat162float(h1)));
        }
      }
    }
  }
}

// ---------------------------------------------------------------------------
// Attention scores with FUSED per-head LN + hi/lo split (fp32 Q/K inputs).
// grid (37, 512), 256 thr. smem: Qh,Ql,Kh,Kl [64][104] bf16.
// Each K row (b,t,h) is LN'd exactly once; Q rows re-LN'd per t0 (cheap).
// ---------------------------------------------------------------------------
#define SCM_STRIDE 104
#define SCM_ARR (64 * SCM_STRIDE * 2)
#define SCM_SMEM (4 * SCM_ARR)
__global__ __launch_bounds__(256) void attn_scores_fused(
    const float* __restrict__ Q, const float* __restrict__ K,
    const float* __restrict__ qg, const float* __restrict__ qb,
    const float* __restrict__ kg, const float* __restrict__ kb,
    float* __restrict__ Sc) {
  extern __shared__ char sm[];
  const uint32_t sb = smem_u32(sm);
  const int tid = threadIdx.x, lane = tid & 31, wid = tid >> 5;
  const int bh = blockIdx.y, b = bh >> 4, h = bh & 15;
  const int t0 = blockIdx.x * 64;

  // LN + split: warp per row, lane covers elems {lane, lane+32, lane+64}
  const float gq0 = qg[lane], gq1 = qg[lane + 32], gq2 = qg[lane + 64];
  const float bq0 = qb[lane], bq1 = qb[lane + 32], bq2 = qb[lane + 64];
  const float gk0 = kg[lane], gk1 = kg[lane + 32], gk2 = kg[lane + 64];
  const float bk0 = kb[lane], bk1 = kb[lane + 32], bk2 = kb[lane + 64];
  bf16* qh = (bf16*)(sm + 0 * SCM_ARR);
  bf16* ql = (bf16*)(sm + 1 * SCM_ARR);
  bf16* kh = (bf16*)(sm + 2 * SCM_ARR);
  bf16* kl = (bf16*)(sm + 3 * SCM_ARR);
#pragma unroll
  for (int rr = 0; rr < 8; rr++) {
    int r = wid + rr * 8;
    // --- Q row ---
    {
      const float* xr = Q + (size_t)(b * cL + r) * cHHD + h * cHD;
      float v0 = xr[lane], v1 = xr[lane + 32], v2 = xr[lane + 64];
      float s = v0 + v1 + v2, s2 = v0 * v0 + v1 * v1 + v2 * v2;
      for (int o = 16; o; o >>= 1) {
        s += __shfl_xor_sync(~0u, s, o);
        s2 += __shfl_xor_sync(~0u, s2, o);
      }
      float mean = s * (1.f / 96.f);
      float rstd = rsqrtf(s2 * (1.f / 96.f) - mean * mean + cEPS);
      float y0 = (v0 - mean) * rstd * gq0 + bq0;
      float y1 = (v1 - mean) * rstd * gq1 + bq1;
      float y2 = (v2 - mean) * rstd * gq2 + bq2;
      bf16 h0 = __float2bfloat16(y0), h1 = __float2bfloat16(y1),
           h2 = __float2bfloat16(y2);
      int rb = r * SCM_STRIDE;
      qh[rb + lane] = h0; qh[rb + lane + 32] = h1; qh[rb + lane + 64] = h2;
      ql[rb + lane] = __float2bfloat16(y0 - __bfloat162float(h0));
      ql[rb + lane + 32] = __float2bfloat16(y1 - __bfloat162float(h1));
      ql[rb + lane + 64] = __float2bfloat16(y2 - __bfloat162float(h2));
    }
    // --- K row ---
    {
      const float* xr = K + (size_t)(b * cT + t0 + r) * cHHD + h * cHD;
      float v0 = xr[lane], v1 = xr[lane + 32], v2 = xr[lane + 64];
      float s = v0 + v1 + v2, s2 = v0 * v0 + v1 * v1 + v2 * v2;
      for (int o = 16; o; o >>= 1) {
        s += __shfl_xor_sync(~0u, s, o);
        s2 += __shfl_xor_sync(~0u, s2, o);
      }
      float mean = s * (1.f / 96.f);
      float rstd = rsqrtf(s2 * (1.f / 96.f) - mean * mean + cEPS);
      float y0 = (v0 - mean) * rstd * gk0 + bk0;
      float y1 = (v1 - mean) * rstd * gk1 + bk1;
      float y2 = (v2 - mean) * rstd * gk2 + bk2;
      bf16 h0 = __float2bfloat16(y0), h1 = __float2bfloat16(y1),
           h2 = __float2bfloat16(y2);
      int rb = r * SCM_STRIDE;
      kh[rb + lane] = h0; kh[rb + lane + 32] = h1; kh[rb + lane + 64] = h2;
      kl[rb + lane] = __float2bfloat16(y0 - __bfloat162float(h0));
      kl[rb + lane + 32] = __float2bfloat16(y1 - __bfloat162float(h1));
      kl[rb + lane + 64] = __float2bfloat16(y2 - __bfloat162float(h2));
    }
  }
  __syncthreads();

  const int wm = wid & 1, wn = wid >> 1;
  float acc[2][2][4];
#pragma unroll
  for (int mt = 0; mt < 2; mt++)
#pragma unroll
    for (int nt = 0; nt < 2; nt++)
#pragma unroll
      for (int j = 0; j < 4; j++) acc[mt][nt][j] = 0.f;

#pragma unroll
  for (int ks = 0; ks < 6; ks++) {
    uint32_t kbo = ks * 32;
    uint32_t ah[2][4], al[2][4], bh2[2][2], bl2[2][2];
#pragma unroll
    for (int mt = 0; mt < 2; mt++) {
      uint32_t ad = sb + (wm * 32 + mt * 16 + (lane & 15)) * (SCM_STRIDE * 2) +
                    kbo + (lane >> 4) * 16;
      ldsm_x4(ah[mt], ad);
      ldsm_x4(al[mt], ad + SCM_ARR);
    }
#pragma unroll
    for (int nt = 0; nt < 2; nt++) {
      uint32_t bd = sb + 2 * SCM_ARR +
                    (wn * 16 + nt * 8 + (lane & 7)) * (SCM_STRIDE * 2) + kbo +
                    ((lane >> 3) & 1) * 16;
      ldsm_x2(bh2[nt], bd);
      ldsm_x2(bl2[nt], bd + SCM_ARR);
    }
#pragma unroll
    for (int mt = 0; mt < 2; mt++)
#pragma unroll
      for (int nt = 0; nt < 2; nt++) mma16816(acc[mt][nt], ah[mt], bh2[nt]);
#pragma unroll
    for (int mt = 0; mt < 2; mt++)
#pragma unroll
      for (int nt = 0; nt < 2; nt++) mma16816(acc[mt][nt], ah[mt], bl2[nt]);
#pragma unroll
    for (int mt = 0; mt < 2; mt++)
#pragma unroll
      for (int nt = 0; nt < 2; nt++) mma16816(acc[mt][nt], al[mt], bh2[nt]);
  }

  const float scale = 0.102062072615966f;
#pragma unroll
  for (int mt = 0; mt < 2; mt++)
#pragma unroll
    for (int half = 0; half < 2; half++) {
      int row = wm * 32 + mt * 16 + (lane >> 2) + half * 8;
#pragma unroll
      for (int nt = 0; nt < 2; nt++) {
        int col = t0 + wn * 16 + nt * 8 + (lane & 3) * 2;
        *(float2*)(Sc + ((size_t)bh * cL + row) * cT + col) =
            make_float2(acc[mt][nt][half * 2] * scale,
                        acc[mt][nt][half * 2 + 1] * scale);
      }
    }
}

// ---------------------------------------------------------------------------
// Row softmax -> P bf16 hi/lo. Register-resident, polynomial exp.
// ---------------------------------------------------------------------------
__global__ void softmax_split_kernel(const float* __restrict__ Sc,
                                     bf16* __restrict__ Ph,
                                     bf16* __restrict__ Pl) {
  const float* x = Sc + (size_t)blockIdx.x * cT;
  bf16* ph = Ph + (size_t)blockIdx.x * cT;
  bf16* pl = Pl + (size_t)blockIdx.x * cT;
  int tid = threadIdx.x;
  __shared__ float sh[32];
  __shared__ float bc;
  float v[10];
  float m = -1e30f;
#pragma unroll
  for (int k = 0; k < 10; k++) {
    int c = k * 256 + tid;
    if (c < cT) {
      v[k] = x[c];
      m = fmaxf(m, v[k]);
    } else {
      v[k] = -1e30f;
    }
  }
  for (int o = 16; o; o >>= 1) m = fmaxf(m, __shfl_xor_sync(~0u, m, o));
  int w = tid >> 5, lane = tid & 31;
  if (lane == 0) sh[w] = m;
  __syncthreads();
  if (w == 0) {
    m = (lane < 8) ? sh[lane] : -1e30f;
    for (int o = 16; o; o >>= 1) m = fmaxf(m, __shfl_xor_sync(~0u, m, o));
    if (lane == 0) bc = m;
  }
  __syncthreads();
  m = bc;
  float s = 0.f;
#pragma unroll
  for (int k = 0; k < 10; k++) {
    if (k * 256 + tid < cT) {
      v[k] = fexp(v[k] - m);
      s += v[k];
    }
  }
  for (int o = 16; o; o >>= 1) s += __shfl_xor_sync(~0u, s, o);
  __syncthreads();
  if (lane == 0) sh[w] = s;
  __syncthreads();
  if (w == 0) {
    s = (lane < 8) ? sh[lane] : 0.f;
    for (int o = 16; o; o >>= 1) s += __shfl_xor_sync(~0u, s, o);
    if (lane == 0) bc = 1.f / s;
  }
  __syncthreads();
  float inv = bc;
#pragma unroll
  for (int k = 0; k < 10; k++) {
    int c = k * 256 + tid;
    if (c < cT) {
      float p = v[k] * inv;
      bf16 hh = __float2bfloat16(p);
      ph[c] = hh;
      pl[c] = __float2bfloat16(p - __bfloat162float(hh));
    }
  }
}

// ---------------------------------------------------------------------------
// AV on MMA -> att written TILED (Kd=1536 blob) for the Wo bulk GEMM
// ---------------------------------------------------------------------------
#define AV_PSTR 72
#define AV_VSTR 104
#define AV_PARR (64 * AV_PSTR * 2)
#define AV_VARR (64 * AV_VSTR * 2)
#define AV_STAGE (2 * AV_PARR + 2 * AV_VARR)
#define AV_SMEM (2 * AV_STAGE)
__global__ __launch_bounds__(256) void attn_av_mma(
    const bf16* __restrict__ Ph, const bf16* __restrict__ Pl,
    const bf16* __restrict__ Vh, const bf16* __restrict__ Vl,
    bf16* __restrict__ OhiT, bf16* __restrict__ OloT) {
  extern __shared__ char sm[];
  const uint32_t sb = smem_u32(sm);
  const int tid = threadIdx.x, lane = tid & 31, wid = tid >> 5;
  const int bh = blockIdx.x, b = bh >> 4, h = bh & 15;
  const int wm = wid >> 1, wn = wid & 1;

  auto load_chunk = [&](int ct, int buf) {
    int t0 = ct * 64;
    uint32_t base = sb + buf * AV_STAGE;
#pragma unroll
    for (int it = 0; it < 2; it++) {
      int e = tid + it * 256;
      int r = e >> 3, u = e & 7;
      uint32_t so = r * (AV_PSTR * 2) + u * 16;
      size_t po = (size_t)(bh * cL + r) * cT + t0 + u * 8;
      cp_async16(base + so, Ph + po);
      cp_async16(base + AV_PARR + so, Pl + po);
    }
#pragma unroll
    for (int it = 0; it < 3; it++) {
      int e = tid + it * 256;
      int r = e / 12, u = e % 12;
      uint32_t so = r * (AV_VSTR * 2) + u * 16;
      size_t vo = (size_t)(b * cT + t0 + r) * cHHD + h * cHD + u * 8;
      cp_async16(base + 2 * AV_PARR + so, Vh + vo);
      cp_async16(base + 2 * AV_PARR + AV_VARR + so, Vl + vo);
    }
    CP_COMMIT();
  };

  float acc[6][4];
#pragma unroll
  for (int nt = 0; nt < 6; nt++)
#pragma unroll
    for (int j = 0; j < 4; j++) acc[nt][j] = 0.f;

  load_chunk(0, 0);
  for (int ct = 0; ct < 37; ct++) {
    int buf = ct & 1;
    if (ct + 1 < 37) {
      load_chunk(ct + 1, buf ^ 1);
      CP_WAIT(1);
    } else {
      CP_WAIT(0);
    }
    __syncthreads();
    uint32_t base = sb + buf * AV_STAGE;
#pragma unroll
    for (int ks = 0; ks < 4; ks++) {
      uint32_t kb = ks * 16;
      uint32_t ap[4], al[4];
      uint32_t aa = base + (wm * 16 + (lane & 15)) * (AV_PSTR * 2) + kb * 2 +
                    (lane >> 4) * 16;
      ldsm_x4(ap, aa);
      ldsm_x4(al, aa + AV_PARR);
      uint32_t bv[6][2], blv[6][2];
#pragma unroll
      for (int nt = 0; nt < 6; nt++) {
        uint32_t ba = base + 2 * AV_PARR +
                      (kb + ((lane >> 3) & 1) * 8 + (lane & 7)) * (AV_VSTR * 2) +
                      (wn * 48 + nt * 8) * 2;
        ldsm_x2_trans(bv[nt], ba);
        ldsm_x2_trans(blv[nt], ba + AV_VARR);
      }
#pragma unroll
      for (int nt = 0; nt < 6; nt++) mma16816(acc[nt], ap, bv[nt]);
#pragma unroll
      for (int nt = 0; nt < 6; nt++) mma16816(acc[nt], ap, blv[nt]);
#pragma unroll
      for (int nt = 0; nt < 6; nt++) mma16816(acc[nt], al, bv[nt]);
    }
    __syncthreads();
  }

#pragma unroll
  for (int half = 0; half < 2; half++) {
    int row = b * cL + wm * 16 + (lane >> 2) + half * 8;
#pragma unroll
    for (int nt = 0; nt < 6; nt++) {
      int col = h * cHD + wn * 48 + nt * 8 + (lane & 3) * 2;
      float v0 = acc[nt][half * 2], v1 = acc[nt][half * 2 + 1];
      bf16 h0 = __float2bfloat16(v0), h1 = __float2bfloat16(v1);
      size_t off = ((size_t)(row >> 7) * 48 + (col >> 5)) * 5120 +
                   (row & 127) * 40 + (col & 31);
      *(__nv_bfloat162*)(OhiT + off) = __nv_bfloat162(h0, h1);
      *(__nv_bfloat162*)(OloT + off) = __nv_bfloat162(
          __float2bfloat16(v0 - __bfloat162float(h0)),
          __float2bfloat16(v1 - __bfloat162float(h1)));
    }
  }
}

// ---------------------------------------------------------------------------
// LN (no affine) -> TILED bf16 hi/lo blob (row length cD, nc=40)
// ---------------------------------------------------------------------------
__global__ void ln_tiled_kernel(const float* __restrict__ x,
                                bf16* __restrict__ hi, bf16* __restrict__ lo) {
  int row = blockIdx.x;
  const float* xr = x + (size_t)row * cD;
  float s = 0.f, s2 = 0.f;
  for (int c = threadIdx.x; c < cD; c += 256) {
    float v = xr[c];
    s += v; s2 += v * v;
  }
  __shared__ float sh[64];
  for (int o = 16; o; o >>= 1) {
    s += __shfl_xor_sync(~0u, s, o);
    s2 += __shfl_xor_sync(~0u, s2, o);
  }
  int w = threadIdx.x >> 5, lane = threadIdx.x & 31;
  if (lane == 0) { sh[w] = s; sh[w + 32] = s2; }
  __syncthreads();
  if (w == 0) {
    s = (lane < 8) ? sh[lane] : 0.f;
    s2 = (lane < 8) ? sh[lane + 32] : 0.f;
    for (int o = 16; o; o >>= 1) {
      s += __shfl_xor_sync(~0u, s, o);
      s2 += __shfl_xor_sync(~0u, s2, o);
    }
    if (lane == 0) { sh[0] = s; sh[1] = s2; }
  }
  __syncthreads();
  float mean = sh[0] * (1.f / cD);
  float rstd = rsqrtf(sh[1] * (1.f / cD) - mean * mean + cEPS);
  size_t rowbase = (size_t)(row >> 7) * cNCC * 5120 + (size_t)(row & 127) * 40;
  for (int c = threadIdx.x; c < cD; c += 256) {
    float v = (xr[c] - mean) * rstd;
    bf16 h = __float2bfloat16(v);
    size_t off = rowbase + (size_t)(c >> 5) * 5120 + (c & 31);
    hi[off] = h;
    lo[off] = __float2bfloat16(v - __bfloat162float(h));
  }
}

// ---------------------------------------------------------------------------
// Tiled weight prep (any Kdim/Nw): Wt blob + rank-1 bias
// ---------------------------------------------------------------------------
__global__ void wprep_tiled_kernel(const float* __restrict__ W,
                                   const float* __restrict__ g,
                                   const float* __restrict__ b,
                                   bf16* __restrict__ Whi,
                                   bf16* __restrict__ Wlo,
                                   float* __restrict__ bias, int Kdim, int Nw) {
  int n = blockIdx.x;
  int nc = Kdim >> 5;
  float bs = 0.f;
  size_t rowbase = (size_t)(n >> 7) * nc * 5120 + (size_t)(n & 127) * 40;
  for (int k = threadIdx.x; k < Kdim; k += 256) {
    float w = W[(size_t)k * Nw + n];
    float v = (g != nullptr) ? g[k] * w : w;
    bf16 h = __float2bfloat16(v);
    size_t off = rowbase + (size_t)(k >> 5) * 5120 + (k & 31);
    Whi[off] = h;
    Wlo[off] = __float2bfloat16(v - __bfloat162float(h));
    if (b != nullptr) bs += b[k] * w;
  }
  if (bias != nullptr) {
    __shared__ float sh[8];
    for (int o = 16; o; o >>= 1) bs += __shfl_xor_sync(~0u, bs, o);
    int w8 = threadIdx.x >> 5, lane = threadIdx.x & 31;
    if (lane == 0) sh[w8] = bs;
    __syncthreads();
    if (threadIdx.x == 0) {
      float t = 0.f;
      for (int i = 0; i < 8; i++) t += sh[i];
      bias[n] = t;
    }
  }
}

// ---------------------------------------------------------------------------
// Broadcast latents
// ---------------------------------------------------------------------------
__global__ void bcast_latents_kernel(const float* __restrict__ lat,
                                     float* __restrict__ out) {
  int idx = blockIdx.x * 256 + threadIdx.x;
  out[idx] = lat[idx % (cL * cD)];
}

// ---------------------------------------------------------------------------
// Final LayerNorm with affine
// ---------------------------------------------------------------------------
__global__ void ln_rows_kernel(const float* __restrict__ x,
                               float* __restrict__ y,
                               const float* __restrict__ g,
                               const float* __restrict__ b) {
  int row = blockIdx.x;
  const float* xr = x + (size_t)row * cD;
  float* yr = y + (size_t)row * cD;
  float s = 0.f, s2 = 0.f;
  for (int c = threadIdx.x; c < cD; c += 256) {
    float v = xr[c];
    s += v; s2 += v * v;
  }
  __shared__ float sh[64];
  for (int o = 16; o; o >>= 1) {
    s += __shfl_xor_sync(~0u, s, o);
    s2 += __shfl_xor_sync(~0u, s2, o);
  }
  int w = threadIdx.x >> 5, lane = threadIdx.x & 31;
  if (lane == 0) { sh[w] = s; sh[w + 32] = s2; }
  __syncthreads();
  if (w == 0) {
    s = (lane < 8) ? sh[lane] : 0.f;
    s2 = (lane < 8) ? sh[lane + 32] : 0.f;
    for (int o = 16; o; o >>= 1) {
      s += __shfl_xor_sync(~0u, s, o);
      s2 += __shfl_xor_sync(~0u, s2, o);
    }
    if (lane == 0) { sh[0] = s; sh[1] = s2; }
  }
  __syncthreads();
  float mean = sh[0] * (1.f / cD);
  float rstd = rsqrtf(sh[1] * (1.f / cD) - mean * mean + cEPS);
  for (int c = threadIdx.x; c < cD; c += 256)
    yr[c] = (xr[c] - mean) * rstd * g[c] + b[c];
}

// ---------------------------------------------------------------------------
// Host orchestration
// ---------------------------------------------------------------------------
extern "C" void kernel_launch(void* const* d_in, const int* in_sizes, int n_in,
                              void* d_out, int out_size) {
  (void)in_sizes; (void)n_in; (void)out_size;
  const float* context = (const float*)d_in[0];
  const float* latents = (const float*)d_in[1];
  const float* ctx_g = (const float*)d_in[2];
  const float* ctx_b = (const float*)d_in[3];
  const float* lat_g = (const float*)d_in[4];
  const float* lat_b = (const float*)d_in[5];
  const float* q_g = (const float*)d_in[6];
  const float* q_b = (const float*)d_in[7];
  const float* k_g = (const float*)d_in[8];
  const float* k_b = (const float*)d_in[9];
  const float* Wq = (const float*)d_in[10];
  const float* Wk = (const float*)d_in[11];
  const float* Wv = (const float*)d_in[12];
  const float* Wo = (const float*)d_in[13];
  const float* mlp_g = (const float*)d_in[14];
  const float* mlp_b = (const float*)d_in[15];
  const float* Wfc = (const float*)d_in[16];
  const float* Wcp = (const float*)d_in[17];
  const float* f_g = (const float*)d_in[18];
  const float* f_b = (const float*)d_in[19];
  float* out = (float*)d_out;

#define SYM(var, sym) cudaGetSymbolAddress((void**)&var, sym)
  bf16 *ctxTh, *ctxTl, *lnTh, *lnTl, *attTh, *attTl, *mlpTh, *mlpTl;
  bf16 *vhi, *vlo, *phi, *plo;
  bf16 *wkcTh, *wkcTl, *wvcTh, *wvcTl, *wqTh, *wqTl, *wklTh, *wklTl, *wvlTh,
      *wvlTl, *woTh, *woTl, *wfcTh, *wfcTl, *wcpTh, *wcpTl;
  float *bQ, *bKc, *bKl, *bVc, *bVl, *bFc;
  float *lat, *Qp, *Kp, *Scp;
  SYM(ctxTh, g_ctxT_hi); SYM(ctxTl, g_ctxT_lo);
  SYM(lnTh, g_latlnT_hi); SYM(lnTl, g_latlnT_lo);
  SYM(attTh, g_attT_hi); SYM(attTl, g_attT_lo);
  SYM(mlpTh, g_mlpT_hi); SYM(mlpTl, g_mlpT_lo);
  SYM(vhi, g_V_hi); SYM(vlo, g_V_lo);
  SYM(phi, g_P_hi); SYM(plo, g_P_lo);
  SYM(wkcTh, g_wkcT_hi); SYM(wkcTl, g_wkcT_lo);
  SYM(wvcTh, g_wvcT_hi); SYM(wvcTl, g_wvcT_lo);
  SYM(wqTh, g_wqT_hi); SYM(wqTl, g_wqT_lo);
  SYM(wklTh, g_wklT_hi); SYM(wklTl, g_wklT_lo);
  SYM(wvlTh, g_wvlT_hi); SYM(wvlTl, g_wvlT_lo);
  SYM(woTh, g_woT_hi); SYM(woTl, g_woT_lo);
  SYM(wfcTh, g_wfcT_hi); SYM(wfcTl, g_wfcT_lo);
  SYM(wcpTh, g_wcpT_hi); SYM(wcpTl, g_wcpT_lo);
  SYM(bQ, g_biasQ); SYM(bKc, g_biasKc); SYM(bKl, g_biasKl);
  SYM(bVc, g_biasVc); SYM(bVl, g_biasVl); SYM(bFc, g_biasFc);
  SYM(lat, g_lat); SYM(Qp, g_Q); SYM(Kp, g_K); SYM(Scp, g_scores);
#undef SYM

  cudaFuncSetAttribute(fused_kv_bulk,
                       cudaFuncAttributeMaxDynamicSharedMemorySize, FB_SMEM);
  cudaFuncSetAttribute(mma_gemm_bulk,
                       cudaFuncAttributeMaxDynamicSharedMemorySize, GB_SMEM);
  cudaFuncSetAttribute(attn_scores_fused,
                       cudaFuncAttributeMaxDynamicSharedMemorySize, SCM_SMEM);
  cudaFuncSetAttribute(attn_av_mma,
                       cudaFuncAttributeMaxDynamicSharedMemorySize, AV_SMEM);

  dim3 kvGridCtx(12, cMB);
  dim3 kvGridLat(12, cML / 128);

  // launch 0: LN(context) -> tiled (once)
  ln_tiled_kernel<<<cMCTX, 256>>>(context, ctxTh, ctxTl);
  // launches 1,2: layer-0 ctx weight preps
  wprep_tiled_kernel<<<cHHD, 256>>>(Wk, ctx_g, ctx_b, wkcTh, wkcTl, bKc, cD,
                                    cHHD);
  wprep_tiled_kernel<<<cHHD, 256>>>(Wv, ctx_g, ctx_b, wvcTh, wvcTl, bVc, cD,
                                    cHHD);
  // launch 3: layer-0 fused ctx K+V projection  << ncu capture slot >>
  fused_kv_bulk<<<kvGridCtx, 512, FB_SMEM>>>(ctxTh, ctxTl, wkcTh, wkcTl, wvcTh,
                                             wvcTl, bKc, bVc, Kp, vhi, vlo, cS,
                                             cT, 0);
  bcast_latents_kernel<<<(cML * cD) / 256, 256>>>(latents, lat);

  for (int i = 0; i < cDEPTH; i++) {
    const float* Wq_i = Wq + (size_t)i * cD * cHHD;
    const float* Wk_i = Wk + (size_t)i * cD * cHHD;
    const float* Wv_i = Wv + (size_t)i * cD * cHHD;
    const float* Wo_i = Wo + (size_t)i * cHHD * cD;
    const float* Wfc_i = Wfc + (size_t)i * cD * cI;
    const float* Wcp_i = Wcp + (size_t)i * cI * cD;
    const float* lg = lat_g + i * cD;
    const float* lb = lat_b + i * cD;

    if (i > 0) {
      wprep_tiled_kernel<<<cHHD, 256>>>(Wk_i, ctx_g + i * cD, ctx_b + i * cD,
                                        wkcTh, wkcTl, bKc, cD, cHHD);
      wprep_tiled_kernel<<<cHHD, 256>>>(Wv_i, ctx_g + i * cD, ctx_b + i * cD,
                                        wvcTh, wvcTl, bVc, cD, cHHD);
      fused_kv_bulk<<<kvGridCtx, 512, FB_SMEM>>>(ctxTh, ctxTl, wkcTh, wkcTl,
                                                 wvcTh, wvcTl, bKc, bVc, Kp,
                                                 vhi, vlo, cS, cT, 0);
    }

    // LN(latents) -> tiled hi/lo (affine folded into weights)
    ln_tiled_kernel<<<cML, 256>>>(lat, lnTh, lnTl);

    wprep_tiled_kernel<<<cHHD, 256>>>(Wq_i, lg, lb, wqTh, wqTl, bQ, cD, cHHD);
    wprep_tiled_kernel<<<cHHD, 256>>>(Wk_i, lg, lb, wklTh, wklTl, bKl, cD,
                                      cHHD);
    wprep_tiled_kernel<<<cHHD, 256>>>(Wv_i, lg, lb, wvlTh, wvlTl, bVl, cD,
                                      cHHD);

    // Q (fp32 out; per-head LN fused into scores)
    mma_gemm_bulk<<<dim3(12, 16), 256, GB_SMEM>>>(
        lnTh, lnTl, wqTh, wqTl, bQ, nullptr, Qp, nullptr, nullptr, cD, cHHD,
        cHHD, 0);
    // latent K+V rows appended at offset cS
    fused_kv_bulk<<<kvGridLat, 512, FB_SMEM>>>(lnTh, lnTl, wklTh, wklTl, wvlTh,
                                               wvlTl, bKl, bVl, Kp, vhi, vlo,
                                               cL, cT, cS);

    // attention: scores with fused per-head Q/K LN; softmax; AV
    attn_scores_fused<<<dim3(cT / 64, cB * cH), 256, SCM_SMEM>>>(
        Qp, Kp, q_g + i * cHD, q_b + i * cHD, k_g + i * cHD, k_b + i * cHD,
        Scp);
    softmax_split_kernel<<<cB * cH * cL, 256>>>(Scp, phi, plo);
    attn_av_mma<<<cB * cH, 256, AV_SMEM>>>(phi, plo, vhi, vlo, attTh, attTl);

    // lat = att @ Wo + lat
    wprep_tiled_kernel<<<cD, 256>>>(Wo_i, nullptr, nullptr, woTh, woTl,
                                    nullptr, cHHD, cD);
    mma_gemm_bulk<<<dim3(10, 16), 256, GB_SMEM>>>(
        attTh, attTl, woTh, woTl, nullptr, lat, lat, nullptr, nullptr, cHHD,
        cD, cD, 0);

    // MLP
    ln_tiled_kernel<<<cML, 256>>>(lat, lnTh, lnTl);
    wprep_tiled_kernel<<<cI, 256>>>(Wfc_i, mlp_g + i * cD, mlp_b + i * cD,
                                    wfcTh, wfcTl, bFc, cD, cI);
    mma_gemm_bulk<<<dim3(40, 16), 256, GB_SMEM>>>(
        lnTh, lnTl, wfcTh, wfcTl, bFc, nullptr, nullptr, mlpTh, mlpTl, cD, cI,
        cI, 1);
    wprep_tiled_kernel<<<cD, 256>>>(Wcp_i, nullptr, nullptr, wcpTh, wcpTl,
                                    nullptr, cI, cD);
    mma_gemm_bulk<<<dim3(10, 16), 256, GB_SMEM>>>(
        mlpTh, mlpTl, wcpTh, wcpTl, nullptr, lat, lat, nullptr, nullptr, cI,
        cD, cD, 0);
  }

  ln_rows_kernel<<<cML, 256>>>(lat, out, f_g, f_b);
}

// round 13
// speedup vs baseline: 1.3747x; 1.1087x over previous
#include <cuda_runtime.h>
#include <cuda_bf16.h>
#include <cstdint>
#include <cstddef>

// ---------------------------------------------------------------------------
// Problem constants
// ---------------------------------------------------------------------------
#define cB 32
#define cS 2304
#define cD 1280
#define cDEPTH 6
#define cH 16
#define cHD 96
#define cL 64
#define cI 5120
#define cT (cS + cL)      /* 2368 */
#define cHHD (cH * cHD)   /* 1536 */
#define cEPS 1e-5f
#define cMCTX (cB * cS)   /* 73728 ctx rows */
#define cML (cB * cL)     /* 2048 latent rows */
#define cMB (cMCTX / 128) /* 576 ctx row-blocks */
#define cNCC (cD / 32)    /* 40 k-chunks for Kdim=1280 */

typedef __nv_bfloat16 bf16;

// Tiled blob: (row>>7, k>>5) chunk of 128 rows x 32 elems, stored 128x40 elems
#define TBE(blocks, nc) ((size_t)(blocks) * (nc) * 5120)

// ---------------------------------------------------------------------------
// Scratch (device globals: allocation-free rule)
// ---------------------------------------------------------------------------
__device__ bf16 g_ctxT_hi[TBE(cMB, 40)], g_ctxT_lo[TBE(cMB, 40)];
__device__ bf16 g_latlnT_hi[TBE(16, 40)], g_latlnT_lo[TBE(16, 40)];
__device__ bf16 g_attT_hi[TBE(16, 48)], g_attT_lo[TBE(16, 48)];
__device__ bf16 g_mlpT_hi[TBE(16, 160)], g_mlpT_lo[TBE(16, 160)];
__device__ bf16 g_wkcT_hi[TBE(12, 40)], g_wkcT_lo[TBE(12, 40)];
__device__ bf16 g_wvcT_hi[TBE(12, 40)], g_wvcT_lo[TBE(12, 40)];
__device__ bf16 g_wqT_hi[TBE(12, 40)],  g_wqT_lo[TBE(12, 40)];
__device__ bf16 g_wklT_hi[TBE(12, 40)], g_wklT_lo[TBE(12, 40)];
__device__ bf16 g_wvlT_hi[TBE(12, 40)], g_wvlT_lo[TBE(12, 40)];
__device__ bf16 g_woT_hi[TBE(10, 48)],  g_woT_lo[TBE(10, 48)];
__device__ bf16 g_wfcT_hi[TBE(40, 40)], g_wfcT_lo[TBE(40, 40)];
__device__ bf16 g_wcpT_hi[TBE(10, 160)], g_wcpT_lo[TBE(10, 160)];
// linear buffers
__device__ bf16 g_V_hi[(size_t)cB * cT * cHHD], g_V_lo[(size_t)cB * cT * cHHD];
__device__ bf16 g_P_hi[(size_t)cB * cH * cL * cT];
__device__ bf16 g_P_lo[(size_t)cB * cH * cL * cT];
__device__ float g_biasQ[cHHD], g_biasKc[cHHD], g_biasKl[cHHD];
__device__ float g_biasVc[cHHD], g_biasVl[cHHD], g_biasFc[cI];
__device__ float g_lat[cML * cD];
__device__ float g_Q[cML * cHHD];
__device__ float g_K[(size_t)cB * cT * cHHD];
__device__ float g_scores[(size_t)cB * cH * cL * cT];

// ---------------------------------------------------------------------------
// PTX helpers (base sm_90 features only)
// ---------------------------------------------------------------------------
__device__ __forceinline__ uint32_t smem_u32(const void* p) {
  uint32_t a;
  asm("{ .reg .u64 t; cvta.to.shared.u64 t, %1; cvt.u32.u64 %0, t; }"
      : "=r"(a) : "l"(p));
  return a;
}
__device__ __forceinline__ void cp_async16(uint32_t saddr, const void* gptr) {
  asm volatile("cp.async.cg.shared.global [%0], [%1], 16;" ::"r"(saddr),
               "l"(gptr)
               : "memory");
}
#define CP_COMMIT() asm volatile("cp.async.commit_group;" ::: "memory")
#define CP_WAIT(N) asm volatile("cp.async.wait_group %0;" ::"n"(N) : "memory")

__device__ __forceinline__ void bulk_g2s(uint32_t dst, const void* src,
                                         uint32_t bytes, uint32_t bar) {
  asm volatile(
      "cp.async.bulk.shared::cta.global.mbarrier::complete_tx::bytes "
      "[%0], [%1], %2, [%3];"
      :: "r"(dst), "l"(src), "r"(bytes), "r"(bar)
      : "memory");
}
#define MBAR_INIT(mb, n)                                                   \
  asm volatile("mbarrier.init.shared.b64 [%0], %1;" ::"r"((uint32_t)(mb)), \
               "r"((uint32_t)(n))                                          \
               : "memory")
#define MBAR_EXPECT_TX(mb, n)                                              \
  asm volatile("mbarrier.arrive.expect_tx.shared.b64 _, [%0], %1;" ::"r"(  \
                   (uint32_t)(mb)),                                        \
               "r"((uint32_t)(n))                                          \
               : "memory")
#define MBAR_ARRIVE(mb)                                                    \
  asm volatile("mbarrier.arrive.shared.b64 _, [%0];" ::"r"((uint32_t)(mb)) \
               : "memory")
#define MBAR_WAIT(mb, par) do {                                              \
  uint32_t _mb = (uint32_t)(mb), _p = (uint32_t)(par), _d;                   \
  asm volatile(                                                              \
      "{\n\t.reg .pred p;\n\t"                                               \
      "mbarrier.try_wait.parity.acquire.cta.shared::cta.b64 p, [%1], %2;\n\t"\
      "selp.b32 %0, 1, 0, p;\n\t}"                                           \
      : "=r"(_d) : "r"(_mb), "r"(_p) : "memory");                            \
  if (!_d) {                                                                 \
    asm volatile(                                                            \
        "{\n\t.reg .pred P1;\n\t"                                            \
        "W1_%=:\n\t"                                                         \
        "mbarrier.try_wait.parity.acquire.cta.shared::cta.b64 P1, [%0], %1, 0x989680;\n\t" \
        "@P1 bra.uni W2_%=;\n\tbra.uni W1_%=;\n\tW2_%=:\n\t}"                \
        :: "r"(_mb), "r"(_p) : "memory");                                    \
  }                                                                          \
} while (0)

__device__ __forceinline__ void ldsm_x4(uint32_t* d, uint32_t addr) {
  asm volatile("ldmatrix.sync.aligned.m8n8.x4.shared.b16 {%0,%1,%2,%3},[%4];"
               : "=r"(d[0]), "=r"(d[1]), "=r"(d[2]), "=r"(d[3])
               : "r"(addr));
}
__device__ __forceinline__ void ldsm_x2(uint32_t* d, uint32_t addr) {
  asm volatile("ldmatrix.sync.aligned.m8n8.x2.shared.b16 {%0,%1},[%2];"
               : "=r"(d[0]), "=r"(d[1])
               : "r"(addr));
}
__device__ __forceinline__ void ldsm_x2_trans(uint32_t* d, uint32_t addr) {
  asm volatile("ldmatrix.sync.aligned.m8n8.x2.trans.shared.b16 {%0,%1},[%2];"
               : "=r"(d[0]), "=r"(d[1])
               : "r"(addr));
}
__device__ __forceinline__ void mma16816(float* c, const uint32_t* a,
                                         const uint32_t* b) {
  asm volatile(
      "mma.sync.aligned.m16n8k16.row.col.f32.bf16.bf16.f32 "
      "{%0,%1,%2,%3},{%4,%5,%6,%7},{%8,%9},{%0,%1,%2,%3};"
      : "+f"(c[0]), "+f"(c[1]), "+f"(c[2]), "+f"(c[3])
      : "r"(a[0]), "r"(a[1]), "r"(a[2]), "r"(a[3]), "r"(b[0]), "r"(b[1]));
}

// Fast exp on the FMA pipe (degree-6 2^f poly; rel err ~8e-6).
__device__ __forceinline__ float fexp(float x) {
  x = fmaxf(x, -87.0f);
  float t = x * 1.4426950408889634f;
  float fi = floorf(t);
  float f = t - fi;
  float p = 1.54035304e-4f;
  p = fmaf(p, f, 1.33335581e-3f);
  p = fmaf(p, f, 9.61812911e-3f);
  p = fmaf(p, f, 5.55041087e-2f);
  p = fmaf(p, f, 2.40226507e-1f);
  p = fmaf(p, f, 6.93147181e-1f);
  p = fmaf(p, f, 1.0f);
  int i = (int)fi;
  return p * __int_as_float((i + 127) << 23);
}

// ---------------------------------------------------------------------------
// Fused K+V GEMM, bulk loader + empty-barrier pipeline (no block syncs in
// the mainloop). full[3] barriers (tx), empty[3] barriers (16 warp arrivals).
// ---------------------------------------------------------------------------
#define FB_STRIDE 40
#define FB_ARR 10240
#define FB_CHUNK (6 * FB_ARR)
#define FB_HDR 1024
#define FB_SMEM (FB_HDR + 3 * FB_CHUNK)

__global__ __launch_bounds__(512) void fused_kv_bulk(
    const bf16* __restrict__ AThi, const bf16* __restrict__ ATlo,
    const bf16* __restrict__ BkThi, const bf16* __restrict__ BkTlo,
    const bf16* __restrict__ BvThi, const bf16* __restrict__ BvTlo,
    const float* __restrict__ biasK, const float* __restrict__ biasV,
    float* __restrict__ Kout, bf16* __restrict__ Vhi, bf16* __restrict__ Vlo,
    int rpbIn, int rpbOut, int rowOff) {
  extern __shared__ char sm[];
  const uint32_t sb = smem_u32(sm);
  const int tid = threadIdx.x, lane = tid & 31, wid = tid >> 5;
  const int grp = wid >> 3;  // 0=K, 1=V
  const int gw = wid & 7;
  const int wm = gw & 1, wn = gw >> 1;
  const int mb = blockIdx.y, nb = blockIdx.x;
  const int m0 = mb * 128, n0 = nb * 128;

  const char* srcs[6];
  srcs[0] = (const char*)AThi + (size_t)mb * cNCC * FB_ARR;
  srcs[1] = (const char*)ATlo + (size_t)mb * cNCC * FB_ARR;
  srcs[2] = (const char*)BkThi + (size_t)nb * cNCC * FB_ARR;
  srcs[3] = (const char*)BkTlo + (size_t)nb * cNCC * FB_ARR;
  srcs[4] = (const char*)BvThi + (size_t)nb * cNCC * FB_ARR;
  srcs[5] = (const char*)BvTlo + (size_t)nb * cNCC * FB_ARR;

  // barriers: full[s] at sb + s*8 (count 1, tx); empty[s] at sb+24+s*8 (16)
  if (tid == 0) {
    MBAR_INIT(sb + 0, 1);
    MBAR_INIT(sb + 8, 1);
    MBAR_INIT(sb + 16, 1);
    MBAR_INIT(sb + 24, 16);
    MBAR_INIT(sb + 32, 16);
    MBAR_INIT(sb + 40, 16);
  }
  __syncthreads();

  auto issue = [&](int c) {
    int s = c % 3;
    uint32_t bar = sb + s * 8;
    MBAR_EXPECT_TX(bar, FB_CHUNK);
    uint32_t dst = sb + FB_HDR + s * FB_CHUNK;
#pragma unroll
    for (int a = 0; a < 6; a++)
      bulk_g2s(dst + a * FB_ARR, srcs[a] + (size_t)c * FB_ARR, FB_ARR, bar);
  };
  if (tid == 0) { issue(0); issue(1); }

  float acc[4][4][4];
#pragma unroll
  for (int mt = 0; mt < 4; mt++)
#pragma unroll
    for (int nt = 0; nt < 4; nt++)
#pragma unroll
      for (int j = 0; j < 4; j++) acc[mt][nt][j] = 0.f;

  const uint32_t aRow = (wm * 64 + (lane & 15)) * (FB_STRIDE * 2);
  const uint32_t aColB = ((lane >> 4) << 3) * 2;
  const uint32_t bRow = (wn * 32 + (lane & 7)) * (FB_STRIDE * 2);
  const uint32_t bColB = (((lane >> 3) & 1) << 3) * 2;
  const uint32_t bOff = (grp ? 4u : 2u) * FB_ARR;

  for (int c = 0; c < cNCC; c++) {
    int s = c % 3;
    MBAR_WAIT(sb + s * 8, (c / 3) & 1);
    if (tid == 0 && c + 2 < cNCC) {
      // stage (c+2)%3 was last read by chunk c-1; wait all 16 warp arrivals
      if (c >= 1) MBAR_WAIT(sb + 24 + ((c + 2) % 3) * 8, ((c - 1) / 3) & 1);
      issue(c + 2);
    }
    uint32_t base = sb + FB_HDR + s * FB_CHUNK;
#pragma unroll
    for (int ks = 0; ks < 2; ks++) {
      uint32_t kb = ks * 32;
      uint32_t ah[4][4], al[4][4];
#pragma unroll
      for (int mt = 0; mt < 4; mt++) {
        uint32_t ad = base + aRow + mt * 16 * (FB_STRIDE * 2) + kb + aColB;
        ldsm_x4(ah[mt], ad);
        ldsm_x4(al[mt], ad + FB_ARR);
      }
#pragma unroll
      for (int nt = 0; nt < 4; nt++) {
        uint32_t bd = base + bOff + bRow + nt * 8 * (FB_STRIDE * 2) + kb + bColB;
        uint32_t bh2[2], bl2[2];
        ldsm_x2(bh2, bd);
        ldsm_x2(bl2, bd + FB_ARR);
#pragma unroll
        for (int mt = 0; mt < 4; mt++) mma16816(acc[mt][nt], ah[mt], bh2);
#pragma unroll
        for (int mt = 0; mt < 4; mt++) mma16816(acc[mt][nt], ah[mt], bl2);
#pragma unroll
        for (int mt = 0; mt < 4; mt++) mma16816(acc[mt][nt], al[mt], bh2);
      }
    }
    if (lane == 0) MBAR_ARRIVE(sb + 24 + s * 8);  // warp done reading stage s
  }

#pragma unroll
  for (int mt = 0; mt < 4; mt++) {
    int mloc = wm * 64 + mt * 16 + (lane >> 2);
#pragma unroll
    for (int half = 0; half < 2; half++) {
      int m = m0 + mloc + half * 8;
      int orow = (m / rpbIn) * rpbOut + rowOff + (m % rpbIn);
#pragma unroll
      for (int nt = 0; nt < 4; nt++) {
        int n = n0 + wn * 32 + nt * 8 + (lane & 3) * 2;
        float v0 = acc[mt][nt][half * 2 + 0];
        float v1 = acc[mt][nt][half * 2 + 1];
        if (grp == 0) {
          v0 += biasK[n]; v1 += biasK[n + 1];
          *(float2*)(Kout + (size_t)orow * cHHD + n) = make_float2(v0, v1);
        } else {
          v0 += biasV[n]; v1 += biasV[n + 1];
          bf16 h0 = __float2bfloat16(v0), h1 = __float2bfloat16(v1);
          *(__nv_bfloat162*)(Vhi + (size_t)orow * cHHD + n) =
              __nv_bfloat162(h0, h1);
          *(__nv_bfloat162*)(Vlo + (size_t)orow * cHHD + n) = __nv_bfloat162(
              __float2bfloat16(v0 - __bfloat162float(h0)),
              __float2bfloat16(v1 - __bfloat162float(h1)));
        }
      }
    }
  }
}

// ---------------------------------------------------------------------------
// Generalized bulk MMA GEMM (Q, Wo, Wfc, Wcp) + empty-barrier pipeline.
// full[2] (tx), empty[2] (8 warp arrivals). 2 CTAs/SM.
// ---------------------------------------------------------------------------
#define GB_ARR 10240
#define GB_CHUNK (4 * GB_ARR)
#define GB_HDR 1024
#define GB_SMEM (GB_HDR + 2 * GB_CHUNK)

__global__ __launch_bounds__(256) void mma_gemm_bulk(
    const bf16* __restrict__ ATh, const bf16* __restrict__ ATl,
    const bf16* __restrict__ BTh, const bf16* __restrict__ BTl,
    const float* __restrict__ bias, const float* __restrict__ R,
    float* __restrict__ C, bf16* __restrict__ ChiT, bf16* __restrict__ CloT,
    int Kdim, int cN, int outKd, int relu) {
  extern __shared__ char sm[];
  const uint32_t sb = smem_u32(sm);
  const int tid = threadIdx.x, lane = tid & 31, wid = tid >> 5;
  const int wm = wid & 1, wn = wid >> 1;
  const int mb = blockIdx.y, nb = blockIdx.x;
  const int m0 = mb * 128, n0 = nb * 128;
  const int nc = Kdim >> 5;

  const char* srcs[4];
  srcs[0] = (const char*)ATh + (size_t)mb * nc * GB_ARR;
  srcs[1] = (const char*)ATl + (size_t)mb * nc * GB_ARR;
  srcs[2] = (const char*)BTh + (size_t)nb * nc * GB_ARR;
  srcs[3] = (const char*)BTl + (size_t)nb * nc * GB_ARR;

  // full[s] at sb + s*8 ; empty[s] at sb + 16 + s*8
  if (tid == 0) {
    MBAR_INIT(sb + 0, 1);
    MBAR_INIT(sb + 8, 1);
    MBAR_INIT(sb + 16, 8);
    MBAR_INIT(sb + 24, 8);
  }
  __syncthreads();

  auto issue = [&](int c) {
    int s = c & 1;
    uint32_t bar = sb + s * 8;
    MBAR_EXPECT_TX(bar, GB_CHUNK);
    uint32_t dst = sb + GB_HDR + s * GB_CHUNK;
#pragma unroll
    for (int a = 0; a < 4; a++)
      bulk_g2s(dst + a * GB_ARR, srcs[a] + (size_t)c * GB_ARR, GB_ARR, bar);
  };
  if (tid == 0) issue(0);

  float acc[4][4][4];
#pragma unroll
  for (int mt = 0; mt < 4; mt++)
#pragma unroll
    for (int nt = 0; nt < 4; nt++)
#pragma unroll
      for (int j = 0; j < 4; j++) acc[mt][nt][j] = 0.f;

  const uint32_t aRow = (wm * 64 + (lane & 15)) * (FB_STRIDE * 2);
  const uint32_t aColB = ((lane >> 4) << 3) * 2;
  const uint32_t bRow = (wn * 32 + (lane & 7)) * (FB_STRIDE * 2);
  const uint32_t bColB = (((lane >> 3) & 1) << 3) * 2;

  for (int c = 0; c < nc; c++) {
    int s = c & 1;
    MBAR_WAIT(sb + s * 8, (c >> 1) & 1);
    if (tid == 0 && c + 1 < nc) {
      // stage (c+1)&1 last read by chunk c-1
      if (c >= 1) MBAR_WAIT(sb + 16 + ((c + 1) & 1) * 8, ((c - 1) >> 1) & 1);
      issue(c + 1);
    }
    uint32_t base = sb + GB_HDR + s * GB_CHUNK;
#pragma unroll
    for (int ks = 0; ks < 2; ks++) {
      uint32_t kb = ks * 32;
      uint32_t ah[4][4], al[4][4];
#pragma unroll
      for (int mt = 0; mt < 4; mt++) {
        uint32_t ad = base + aRow + mt * 16 * (FB_STRIDE * 2) + kb + aColB;
        ldsm_x4(ah[mt], ad);
        ldsm_x4(al[mt], ad + GB_ARR);
      }
#pragma unroll
      for (int nt = 0; nt < 4; nt++) {
        uint32_t bd =
            base + 2 * GB_ARR + bRow + nt * 8 * (FB_STRIDE * 2) + kb + bColB;
        uint32_t bh2[2], bl2[2];
        ldsm_x2(bh2, bd);
        ldsm_x2(bl2, bd + GB_ARR);
#pragma unroll
        for (int mt = 0; mt < 4; mt++) mma16816(acc[mt][nt], ah[mt], bh2);
#pragma unroll
        for (int mt = 0; mt < 4; mt++) mma16816(acc[mt][nt], ah[mt], bl2);
#pragma unroll
        for (int mt = 0; mt < 4; mt++) mma16816(acc[mt][nt], al[mt], bh2);
      }
    }
    if (lane == 0) MBAR_ARRIVE(sb + 16 + s * 8);
  }

  const int ncOut = outKd >> 5;
#pragma unroll
  for (int mt = 0; mt < 4; mt++) {
    int mloc = wm * 64 + mt * 16 + (lane >> 2);
#pragma unroll
    for (int half = 0; half < 2; half++) {
      int orow = m0 + mloc + half * 8;
#pragma unroll
      for (int nt = 0; nt < 4; nt++) {
        int n = n0 + wn * 32 + nt * 8 + (lane & 3) * 2;
        float v0 = acc[mt][nt][half * 2 + 0];
        float v1 = acc[mt][nt][half * 2 + 1];
        if (bias != nullptr) { v0 += bias[n]; v1 += bias[n + 1]; }
        if (R != nullptr) {
          float2 rv = *(const float2*)(R + (size_t)orow * cN + n);
          v0 += rv.x; v1 += rv.y;
        }
        if (relu) { v0 = fmaxf(v0, 0.f); v1 = fmaxf(v1, 0.f); }
        if (C != nullptr)
          *(float2*)(C + (size_t)orow * cN + n) = make_float2(v0, v1);
        if (ChiT != nullptr) {
          size_t off = ((size_t)(orow >> 7) * ncOut + (n >> 5)) * 5120 +
                       (orow & 127) * 40 + (n & 31);
          bf16 h0 = __float2bfloat16(v0);
          bf16 h1 = __float2bfloat16(v1);
          *(__nv_bfloat162*)(ChiT + off) = __nv_bfloat162(h0, h1);
          *(__nv_bfloat162*)(CloT + off) = __nv_bfloat162(
              __float2bfloat16(v0 - __bfloat162float(h0)),
              __float2bfloat16(v1 - __bfloat162float(h1)));
        }
      }
    }
  }
}

// ---------------------------------------------------------------------------
// Attention scores with FUSED per-head LN + hi/lo split (fp32 Q/K inputs).
// ---------------------------------------------------------------------------
#define SCM_STRIDE 104
#define SCM_ARR (64 * SCM_STRIDE * 2)
#define SCM_SMEM (4 * SCM_ARR)
__global__ __launch_bounds__(256) void attn_scores_fused(
    const float* __restrict__ Q, const float* __restrict__ K,
    const float* __restrict__ qg, const float* __restrict__ qb,
    const float* __restrict__ kg, const float* __restrict__ kb,
    float* __restrict__ Sc) {
  extern __shared__ char sm[];
  const uint32_t sb = smem_u32(sm);
  const int tid = threadIdx.x, lane = tid & 31, wid = tid >> 5;
  const int bh = blockIdx.y, b = bh >> 4, h = bh & 15;
  const int t0 = blockIdx.x * 64;

  const float gq0 = qg[lane], gq1 = qg[lane + 32], gq2 = qg[lane + 64];
  const float bq0 = qb[lane], bq1 = qb[lane + 32], bq2 = qb[lane + 64];
  const float gk0 = kg[lane], gk1 = kg[lane + 32], gk2 = kg[lane + 64];
  const float bk0 = kb[lane], bk1 = kb[lane + 32], bk2 = kb[lane + 64];
  bf16* qh = (bf16*)(sm + 0 * SCM_ARR);
  bf16* ql = (bf16*)(sm + 1 * SCM_ARR);
  bf16* kh = (bf16*)(sm + 2 * SCM_ARR);
  bf16* kl = (bf16*)(sm + 3 * SCM_ARR);
#pragma unroll
  for (int rr = 0; rr < 8; rr++) {
    int r = wid + rr * 8;
    {
      const float* xr = Q + (size_t)(b * cL + r) * cHHD + h * cHD;
      float v0 = xr[lane], v1 = xr[lane + 32], v2 = xr[lane + 64];
      float s = v0 + v1 + v2, s2 = v0 * v0 + v1 * v1 + v2 * v2;
      for (int o = 16; o; o >>= 1) {
        s += __shfl_xor_sync(~0u, s, o);
        s2 += __shfl_xor_sync(~0u, s2, o);
      }
      float mean = s * (1.f / 96.f);
      float rstd = rsqrtf(s2 * (1.f / 96.f) - mean * mean + cEPS);
      float y0 = (v0 - mean) * rstd * gq0 + bq0;
      float y1 = (v1 - mean) * rstd * gq1 + bq1;
      float y2 = (v2 - mean) * rstd * gq2 + bq2;
      bf16 h0 = __float2bfloat16(y0), h1 = __float2bfloat16(y1),
           h2 = __float2bfloat16(y2);
      int rb = r * SCM_STRIDE;
      qh[rb + lane] = h0; qh[rb + lane + 32] = h1; qh[rb + lane + 64] = h2;
      ql[rb + lane] = __float2bfloat16(y0 - __bfloat162float(h0));
      ql[rb + lane + 32] = __float2bfloat16(y1 - __bfloat162float(h1));
      ql[rb + lane + 64] = __float2bfloat16(y2 - __bfloat162float(h2));
    }
    {
      const float* xr = K + (size_t)(b * cT + t0 + r) * cHHD + h * cHD;
      float v0 = xr[lane], v1 = xr[lane + 32], v2 = xr[lane + 64];
      float s = v0 + v1 + v2, s2 = v0 * v0 + v1 * v1 + v2 * v2;
      for (int o = 16; o; o >>= 1) {
        s += __shfl_xor_sync(~0u, s, o);
        s2 += __shfl_xor_sync(~0u, s2, o);
      }
      float mean = s * (1.f / 96.f);
      float rstd = rsqrtf(s2 * (1.f / 96.f) - mean * mean + cEPS);
      float y0 = (v0 - mean) * rstd * gk0 + bk0;
      float y1 = (v1 - mean) * rstd * gk1 + bk1;
      float y2 = (v2 - mean) * rstd * gk2 + bk2;
      bf16 h0 = __float2bfloat16(y0), h1 = __float2bfloat16(y1),
           h2 = __float2bfloat16(y2);
      int rb = r * SCM_STRIDE;
      kh[rb + lane] = h0; kh[rb + lane + 32] = h1; kh[rb + lane + 64] = h2;
      kl[rb + lane] = __float2bfloat16(y0 - __bfloat162float(h0));
      kl[rb + lane + 32] = __float2bfloat16(y1 - __bfloat162float(h1));
      kl[rb + lane + 64] = __float2bfloat16(y2 - __bfloat162float(h2));
    }
  }
  __syncthreads();

  const int wm = wid & 1, wn = wid >> 1;
  float acc[2][2][4];
#pragma unroll
  for (int mt = 0; mt < 2; mt++)
#pragma unroll
    for (int nt = 0; nt < 2; nt++)
#pragma unroll
      for (int j = 0; j < 4; j++) acc[mt][nt][j] = 0.f;

#pragma unroll
  for (int ks = 0; ks < 6; ks++) {
    uint32_t kbo = ks * 32;
    uint32_t ah[2][4], al[2][4], bh2[2][2], bl2[2][2];
#pragma unroll
    for (int mt = 0; mt < 2; mt++) {
      uint32_t ad = sb + (wm * 32 + mt * 16 + (lane & 15)) * (SCM_STRIDE * 2) +
                    kbo + (lane >> 4) * 16;
      ldsm_x4(ah[mt], ad);
      ldsm_x4(al[mt], ad + SCM_ARR);
    }
#pragma unroll
    for (int nt = 0; nt < 2; nt++) {
      uint32_t bd = sb + 2 * SCM_ARR +
                    (wn * 16 + nt * 8 + (lane & 7)) * (SCM_STRIDE * 2) + kbo +
                    ((lane >> 3) & 1) * 16;
      ldsm_x2(bh2[nt], bd);
      ldsm_x2(bl2[nt], bd + SCM_ARR);
    }
#pragma unroll
    for (int mt = 0; mt < 2; mt++)
#pragma unroll
      for (int nt = 0; nt < 2; nt++) mma16816(acc[mt][nt], ah[mt], bh2[nt]);
#pragma unroll
    for (int mt = 0; mt < 2; mt++)
#pragma unroll
      for (int nt = 0; nt < 2; nt++) mma16816(acc[mt][nt], ah[mt], bl2[nt]);
#pragma unroll
    for (int mt = 0; mt < 2; mt++)
#pragma unroll
      for (int nt = 0; nt < 2; nt++) mma16816(acc[mt][nt], al[mt], bh2[nt]);
  }

  const float scale = 0.102062072615966f;
#pragma unroll
  for (int mt = 0; mt < 2; mt++)
#pragma unroll
    for (int half = 0; half < 2; half++) {
      int row = wm * 32 + mt * 16 + (lane >> 2) + half * 8;
#pragma unroll
      for (int nt = 0; nt < 2; nt++) {
        int col = t0 + wn * 16 + nt * 8 + (lane & 3) * 2;
        *(float2*)(Sc + ((size_t)bh * cL + row) * cT + col) =
            make_float2(acc[mt][nt][half * 2] * scale,
                        acc[mt][nt][half * 2 + 1] * scale);
      }
    }
}

// ---------------------------------------------------------------------------
// Row softmax -> P bf16 hi/lo. Register-resident, polynomial exp.
// ---------------------------------------------------------------------------
__global__ void softmax_split_kernel(const float* __restrict__ Sc,
                                     bf16* __restrict__ Ph,
                                     bf16* __restrict__ Pl) {
  const float* x = Sc + (size_t)blockIdx.x * cT;
  bf16* ph = Ph + (size_t)blockIdx.x * cT;
  bf16* pl = Pl + (size_t)blockIdx.x * cT;
  int tid = threadIdx.x;
  __shared__ float sh[32];
  __shared__ float bc;
  float v[10];
  float m = -1e30f;
#pragma unroll
  for (int k = 0; k < 10; k++) {
    int c = k * 256 + tid;
    if (c < cT) {
      v[k] = x[c];
      m = fmaxf(m, v[k]);
    } else {
      v[k] = -1e30f;
    }
  }
  for (int o = 16; o; o >>= 1) m = fmaxf(m, __shfl_xor_sync(~0u, m, o));
  int w = tid >> 5, lane = tid & 31;
  if (lane == 0) sh[w] = m;
  __syncthreads();
  if (w == 0) {
    m = (lane < 8) ? sh[lane] : -1e30f;
    for (int o = 16; o; o >>= 1) m = fmaxf(m, __shfl_xor_sync(~0u, m, o));
    if (lane == 0) bc = m;
  }
  __syncthreads();
  m = bc;
  float s = 0.f;
#pragma unroll
  for (int k = 0; k < 10; k++) {
    if (k * 256 + tid < cT) {
      v[k] = fexp(v[k] - m);
      s += v[k];
    }
  }
  for (int o = 16; o; o >>= 1) s += __shfl_xor_sync(~0u, s, o);
  __syncthreads();
  if (lane == 0) sh[w] = s;
  __syncthreads();
  if (w == 0) {
    s = (lane < 8) ? sh[lane] : 0.f;
    for (int o = 16; o; o >>= 1) s += __shfl_xor_sync(~0u, s, o);
    if (lane == 0) bc = 1.f / s;
  }
  __syncthreads();
  float inv = bc;
#pragma unroll
  for (int k = 0; k < 10; k++) {
    int c = k * 256 + tid;
    if (c < cT) {
      float p = v[k] * inv;
      bf16 hh = __float2bfloat16(p);
      ph[c] = hh;
      pl[c] = __float2bfloat16(p - __bfloat162float(hh));
    }
  }
}

// ---------------------------------------------------------------------------
// AV on MMA -> att written TILED (Kd=1536 blob) for the Wo bulk GEMM
// ---------------------------------------------------------------------------
#define AV_PSTR 72
#define AV_VSTR 104
#define AV_PARR (64 * AV_PSTR * 2)
#define AV_VARR (64 * AV_VSTR * 2)
#define AV_STAGE (2 * AV_PARR + 2 * AV_VARR)
#define AV_SMEM (2 * AV_STAGE)
__global__ __launch_bounds__(256) void attn_av_mma(
    const bf16* __restrict__ Ph, const bf16* __restrict__ Pl,
    const bf16* __restrict__ Vh, const bf16* __restrict__ Vl,
    bf16* __restrict__ OhiT, bf16* __restrict__ OloT) {
  extern __shared__ char sm[];
  const uint32_t sb = smem_u32(sm);
  const int tid = threadIdx.x, lane = tid & 31, wid = tid >> 5;
  const int bh = blockIdx.x, b = bh >> 4, h = bh & 15;
  const int wm = wid >> 1, wn = wid & 1;

  auto load_chunk = [&](int ct, int buf) {
    int t0 = ct * 64;
    uint32_t base = sb + buf * AV_STAGE;
#pragma unroll
    for (int it = 0; it < 2; it++) {
      int e = tid + it * 256;
      int r = e >> 3, u = e & 7;
      uint32_t so = r * (AV_PSTR * 2) + u * 16;
      size_t po = (size_t)(bh * cL + r) * cT + t0 + u * 8;
      cp_async16(base + so, Ph + po);
      cp_async16(base + AV_PARR + so, Pl + po);
    }
#pragma unroll
    for (int it = 0; it < 3; it++) {
      int e = tid + it * 256;
      int r = e / 12, u = e % 12;
      uint32_t so = r * (AV_VSTR * 2) + u * 16;
      size_t vo = (size_t)(b * cT + t0 + r) * cHHD + h * cHD + u * 8;
      cp_async16(base + 2 * AV_PARR + so, Vh + vo);
      cp_async16(base + 2 * AV_PARR + AV_VARR + so, Vl + vo);
    }
    CP_COMMIT();
  };

  float acc[6][4];
#pragma unroll
  for (int nt = 0; nt < 6; nt++)
#pragma unroll
    for (int j = 0; j < 4; j++) acc[nt][j] = 0.f;

  load_chunk(0, 0);
  for (int ct = 0; ct < 37; ct++) {
    int buf = ct & 1;
    if (ct + 1 < 37) {
      load_chunk(ct + 1, buf ^ 1);
      CP_WAIT(1);
    } else {
      CP_WAIT(0);
    }
    __syncthreads();
    uint32_t base = sb + buf * AV_STAGE;
#pragma unroll
    for (int ks = 0; ks < 4; ks++) {
      uint32_t kb = ks * 16;
      uint32_t ap[4], al[4];
      uint32_t aa = base + (wm * 16 + (lane & 15)) * (AV_PSTR * 2) + kb * 2 +
                    (lane >> 4) * 16;
      ldsm_x4(ap, aa);
      ldsm_x4(al, aa + AV_PARR);
      uint32_t bv[6][2], blv[6][2];
#pragma unroll
      for (int nt = 0; nt < 6; nt++) {
        uint32_t ba = base + 2 * AV_PARR +
                      (kb + ((lane >> 3) & 1) * 8 + (lane & 7)) * (AV_VSTR * 2) +
                      (wn * 48 + nt * 8) * 2;
        ldsm_x2_trans(bv[nt], ba);
        ldsm_x2_trans(blv[nt], ba + AV_VARR);
      }
#pragma unroll
      for (int nt = 0; nt < 6; nt++) mma16816(acc[nt], ap, bv[nt]);
#pragma unroll
      for (int nt = 0; nt < 6; nt++) mma16816(acc[nt], ap, blv[nt]);
#pragma unroll
      for (int nt = 0; nt < 6; nt++) mma16816(acc[nt], al, bv[nt]);
    }
    __syncthreads();
  }

#pragma unroll
  for (int half = 0; half < 2; half++) {
    int row = b * cL + wm * 16 + (lane >> 2) + half * 8;
#pragma unroll
    for (int nt = 0; nt < 6; nt++) {
      int col = h * cHD + wn * 48 + nt * 8 + (lane & 3) * 2;
      float v0 = acc[nt][half * 2], v1 = acc[nt][half * 2 + 1];
      bf16 h0 = __float2bfloat16(v0), h1 = __float2bfloat16(v1);
      size_t off = ((size_t)(row >> 7) * 48 + (col >> 5)) * 5120 +
                   (row & 127) * 40 + (col & 31);
      *(__nv_bfloat162*)(OhiT + off) = __nv_bfloat162(h0, h1);
      *(__nv_bfloat162*)(OloT + off) = __nv_bfloat162(
          __float2bfloat16(v0 - __bfloat162float(h0)),
          __float2bfloat16(v1 - __bfloat162float(h1)));
    }
  }
}

// ---------------------------------------------------------------------------
// LN (no affine) -> TILED bf16 hi/lo blob (row length cD, nc=40)
// ---------------------------------------------------------------------------
__global__ void ln_tiled_kernel(const float* __restrict__ x,
                                bf16* __restrict__ hi, bf16* __restrict__ lo) {
  int row = blockIdx.x;
  const float* xr = x + (size_t)row * cD;
  float s = 0.f, s2 = 0.f;
  for (int c = threadIdx.x; c < cD; c += 256) {
    float v = xr[c];
    s += v; s2 += v * v;
  }
  __shared__ float sh[64];
  for (int o = 16; o; o >>= 1) {
    s += __shfl_xor_sync(~0u, s, o);
    s2 += __shfl_xor_sync(~0u, s2, o);
  }
  int w = threadIdx.x >> 5, lane = threadIdx.x & 31;
  if (lane == 0) { sh[w] = s; sh[w + 32] = s2; }
  __syncthreads();
  if (w == 0) {
    s = (lane < 8) ? sh[lane] : 0.f;
    s2 = (lane < 8) ? sh[lane + 32] : 0.f;
    for (int o = 16; o; o >>= 1) {
      s += __shfl_xor_sync(~0u, s, o);
      s2 += __shfl_xor_sync(~0u, s2, o);
    }
    if (lane == 0) { sh[0] = s; sh[1] = s2; }
  }
  __syncthreads();
  float mean = sh[0] * (1.f / cD);
  float rstd = rsqrtf(sh[1] * (1.f / cD) - mean * mean + cEPS);
  size_t rowbase = (size_t)(row >> 7) * cNCC * 5120 + (size_t)(row & 127) * 40;
  for (int c = threadIdx.x; c < cD; c += 256) {
    float v = (xr[c] - mean) * rstd;
    bf16 h = __float2bfloat16(v);
    size_t off = rowbase + (size_t)(c >> 5) * 5120 + (c & 31);
    hi[off] = h;
    lo[off] = __float2bfloat16(v - __bfloat162float(h));
  }
}

// ---------------------------------------------------------------------------
// Tiled weight prep (any Kdim/Nw): Wt blob + rank-1 bias
// ---------------------------------------------------------------------------
__global__ void wprep_tiled_kernel(const float* __restrict__ W,
                                   const float* __restrict__ g,
                                   const float* __restrict__ b,
                                   bf16* __restrict__ Whi,
                                   bf16* __restrict__ Wlo,
                                   float* __restrict__ bias, int Kdim, int Nw) {
  int n = blockIdx.x;
  int nc = Kdim >> 5;
  float bs = 0.f;
  size_t rowbase = (size_t)(n >> 7) * nc * 5120 + (size_t)(n & 127) * 40;
  for (int k = threadIdx.x; k < Kdim; k += 256) {
    float w = W[(size_t)k * Nw + n];
    float v = (g != nullptr) ? g[k] * w : w;
    bf16 h = __float2bfloat16(v);
    size_t off = rowbase + (size_t)(k >> 5) * 5120 + (k & 31);
    Whi[off] = h;
    Wlo[off] = __float2bfloat16(v - __bfloat162float(h));
    if (b != nullptr) bs += b[k] * w;
  }
  if (bias != nullptr) {
    __shared__ float sh[8];
    for (int o = 16; o; o >>= 1) bs += __shfl_xor_sync(~0u, bs, o);
    int w8 = threadIdx.x >> 5, lane = threadIdx.x & 31;
    if (lane == 0) sh[w8] = bs;
    __syncthreads();
    if (threadIdx.x == 0) {
      float t = 0.f;
      for (int i = 0; i < 8; i++) t += sh[i];
      bias[n] = t;
    }
  }
}

// ---------------------------------------------------------------------------
// Broadcast latents
// ---------------------------------------------------------------------------
__global__ void bcast_latents_kernel(const float* __restrict__ lat,
                                     float* __restrict__ out) {
  int idx = blockIdx.x * 256 + threadIdx.x;
  out[idx] = lat[idx % (cL * cD)];
}

// ---------------------------------------------------------------------------
// Final LayerNorm with affine
// ---------------------------------------------------------------------------
__global__ void ln_rows_kernel(const float* __restrict__ x,
                               float* __restrict__ y,
                               const float* __restrict__ g,
                               const float* __restrict__ b) {
  int row = blockIdx.x;
  const float* xr = x + (size_t)row * cD;
  float* yr = y + (size_t)row * cD;
  float s = 0.f, s2 = 0.f;
  for (int c = threadIdx.x; c < cD; c += 256) {
    float v = xr[c];
    s += v; s2 += v * v;
  }
  __shared__ float sh[64];
  for (int o = 16; o; o >>= 1) {
    s += __shfl_xor_sync(~0u, s, o);
    s2 += __shfl_xor_sync(~0u, s2, o);
  }
  int w = threadIdx.x >> 5, lane = threadIdx.x & 31;
  if (lane == 0) { sh[w] = s; sh[w + 32] = s2; }
  __syncthreads();
  if (w == 0) {
    s = (lane < 8) ? sh[lane] : 0.f;
    s2 = (lane < 8) ? sh[lane + 32] : 0.f;
    for (int o = 16; o; o >>= 1) {
      s += __shfl_xor_sync(~0u, s, o);
      s2 += __shfl_xor_sync(~0u, s2, o);
    }
    if (lane == 0) { sh[0] = s; sh[1] = s2; }
  }
  __syncthreads();
  float mean = sh[0] * (1.f / cD);
  float rstd = rsqrtf(sh[1] * (1.f / cD) - mean * mean + cEPS);
  for (int c = threadIdx.x; c < cD; c += 256)
    yr[c] = (xr[c] - mean) * rstd * g[c] + b[c];
}

// ---------------------------------------------------------------------------
// Host orchestration
// ---------------------------------------------------------------------------
extern "C" void kernel_launch(void* const* d_in, const int* in_sizes, int n_in,
                              void* d_out, int out_size) {
  (void)in_sizes; (void)n_in; (void)out_size;
  const float* context = (const float*)d_in[0];
  const float* latents = (const float*)d_in[1];
  const float* ctx_g = (const float*)d_in[2];
  const float* ctx_b = (const float*)d_in[3];
  const float* lat_g = (const float*)d_in[4];
  const float* lat_b = (const float*)d_in[5];
  const float* q_g = (const float*)d_in[6];
  const float* q_b = (const float*)d_in[7];
  const float* k_g = (const float*)d_in[8];
  const float* k_b = (const float*)d_in[9];
  const float* Wq = (const float*)d_in[10];
  const float* Wk = (const float*)d_in[11];
  const float* Wv = (const float*)d_in[12];
  const float* Wo = (const float*)d_in[13];
  const float* mlp_g = (const float*)d_in[14];
  const float* mlp_b = (const float*)d_in[15];
  const float* Wfc = (const float*)d_in[16];
  const float* Wcp = (const float*)d_in[17];
  const float* f_g = (const float*)d_in[18];
  const float* f_b = (const float*)d_in[19];
  float* out = (float*)d_out;

#define SYM(var, sym) cudaGetSymbolAddress((void**)&var, sym)
  bf16 *ctxTh, *ctxTl, *lnTh, *lnTl, *attTh, *attTl, *mlpTh, *mlpTl;
  bf16 *vhi, *vlo, *phi, *plo;
  bf16 *wkcTh, *wkcTl, *wvcTh, *wvcTl, *wqTh, *wqTl, *wklTh, *wklTl, *wvlTh,
      *wvlTl, *woTh, *woTl, *wfcTh, *wfcTl, *wcpTh, *wcpTl;
  float *bQ, *bKc, *bKl, *bVc, *bVl, *bFc;
  float *lat, *Qp, *Kp, *Scp;
  SYM(ctxTh, g_ctxT_hi); SYM(ctxTl, g_ctxT_lo);
  SYM(lnTh, g_latlnT_hi); SYM(lnTl, g_latlnT_lo);
  SYM(attTh, g_attT_hi); SYM(attTl, g_attT_lo);
  SYM(mlpTh, g_mlpT_hi); SYM(mlpTl, g_mlpT_lo);
  SYM(vhi, g_V_hi); SYM(vlo, g_V_lo);
  SYM(phi, g_P_hi); SYM(plo, g_P_lo);
  SYM(wkcTh, g_wkcT_hi); SYM(wkcTl, g_wkcT_lo);
  SYM(wvcTh, g_wvcT_hi); SYM(wvcTl, g_wvcT_lo);
  SYM(wqTh, g_wqT_hi); SYM(wqTl, g_wqT_lo);
  SYM(wklTh, g_wklT_hi); SYM(wklTl, g_wklT_lo);
  SYM(wvlTh, g_wvlT_hi); SYM(wvlTl, g_wvlT_lo);
  SYM(woTh, g_woT_hi); SYM(woTl, g_woT_lo);
  SYM(wfcTh, g_wfcT_hi); SYM(wfcTl, g_wfcT_lo);
  SYM(wcpTh, g_wcpT_hi); SYM(wcpTl, g_wcpT_lo);
  SYM(bQ, g_biasQ); SYM(bKc, g_biasKc); SYM(bKl, g_biasKl);
  SYM(bVc, g_biasVc); SYM(bVl, g_biasVl); SYM(bFc, g_biasFc);
  SYM(lat, g_lat); SYM(Qp, g_Q); SYM(Kp, g_K); SYM(Scp, g_scores);
#undef SYM

  cudaFuncSetAttribute(fused_kv_bulk,
                       cudaFuncAttributeMaxDynamicSharedMemorySize, FB_SMEM);
  cudaFuncSetAttribute(mma_gemm_bulk,
                       cudaFuncAttributeMaxDynamicSharedMemorySize, GB_SMEM);
  cudaFuncSetAttribute(attn_scores_fused,
                       cudaFuncAttributeMaxDynamicSharedMemorySize, SCM_SMEM);
  cudaFuncSetAttribute(attn_av_mma,
                       cudaFuncAttributeMaxDynamicSharedMemorySize, AV_SMEM);

  dim3 kvGridCtx(12, cMB);
  dim3 kvGridLat(12, cML / 128);

  // launch 0: LN(context) -> tiled (once)
  ln_tiled_kernel<<<cMCTX, 256>>>(context, ctxTh, ctxTl);
  // launches 1,2: layer-0 ctx weight preps
  wprep_tiled_kernel<<<cHHD, 256>>>(Wk, ctx_g, ctx_b, wkcTh, wkcTl, bKc, cD,
                                    cHHD);
  wprep_tiled_kernel<<<cHHD, 256>>>(Wv, ctx_g, ctx_b, wvcTh, wvcTl, bVc, cD,
                                    cHHD);
  // launch 3: layer-0 fused ctx K+V projection  << ncu capture slot >>
  fused_kv_bulk<<<kvGridCtx, 512, FB_SMEM>>>(ctxTh, ctxTl, wkcTh, wkcTl, wvcTh,
                                             wvcTl, bKc, bVc, Kp, vhi, vlo, cS,
                                             cT, 0);
  bcast_latents_kernel<<<(cML * cD) / 256, 256>>>(latents, lat);

  for (int i = 0; i < cDEPTH; i++) {
    const float* Wq_i = Wq + (size_t)i * cD * cHHD;
    const float* Wk_i = Wk + (size_t)i * cD * cHHD;
    const float* Wv_i = Wv + (size_t)i * cD * cHHD;
    const float* Wo_i = Wo + (size_t)i * cHHD * cD;
    const float* Wfc_i = Wfc + (size_t)i * cD * cI;
    const float* Wcp_i = Wcp + (size_t)i * cI * cD;
    const float* lg = lat_g + i * cD;
    const float* lb = lat_b + i * cD;

    if (i > 0) {
      wprep_tiled_kernel<<<cHHD, 256>>>(Wk_i, ctx_g + i * cD, ctx_b + i * cD,
                                        wkcTh, wkcTl, bKc, cD, cHHD);
      wprep_tiled_kernel<<<cHHD, 256>>>(Wv_i, ctx_g + i * cD, ctx_b + i * cD,
                                        wvcTh, wvcTl, bVc, cD, cHHD);
      fused_kv_bulk<<<kvGridCtx, 512, FB_SMEM>>>(ctxTh, ctxTl, wkcTh, wkcTl,
                                                 wvcTh, wvcTl, bKc, bVc, Kp,
                                                 vhi, vlo, cS, cT, 0);
    }

    // LN(latents) -> tiled hi/lo (affine folded into weights)
    ln_tiled_kernel<<<cML, 256>>>(lat, lnTh, lnTl);

    wprep_tiled_kernel<<<cHHD, 256>>>(Wq_i, lg, lb, wqTh, wqTl, bQ, cD, cHHD);
    wprep_tiled_kernel<<<cHHD, 256>>>(Wk_i, lg, lb, wklTh, wklTl, bKl, cD,
                                      cHHD);
    wprep_tiled_kernel<<<cHHD, 256>>>(Wv_i, lg, lb, wvlTh, wvlTl, bVl, cD,
                                      cHHD);

    // Q (fp32 out; per-head LN fused into scores)
    mma_gemm_bulk<<<dim3(12, 16), 256, GB_SMEM>>>(
        lnTh, lnTl, wqTh, wqTl, bQ, nullptr, Qp, nullptr, nullptr, cD, cHHD,
        cHHD, 0);
    // latent K+V rows appended at offset cS
    fused_kv_bulk<<<kvGridLat, 512, FB_SMEM>>>(lnTh, lnTl, wklTh, wklTl, wvlTh,
                                               wvlTl, bKl, bVl, Kp, vhi, vlo,
                                               cL, cT, cS);

    // attention: scores with fused per-head Q/K LN; softmax; AV
    attn_scores_fused<<<dim3(cT / 64, cB * cH), 256, SCM_SMEM>>>(
        Qp, Kp, q_g + i * cHD, q_b + i * cHD, k_g + i * cHD, k_b + i * cHD,
        Scp);
    softmax_split_kernel<<<cB * cH * cL, 256>>>(Scp, phi, plo);
    attn_av_mma<<<cB * cH, 256, AV_SMEM>>>(phi, plo, vhi, vlo, attTh, attTl);

    // lat = att @ Wo + lat
    wprep_tiled_kernel<<<cD, 256>>>(Wo_i, nullptr, nullptr, woTh, woTl,
                                    nullptr, cHHD, cD);
    mma_gemm_bulk<<<dim3(10, 16), 256, GB_SMEM>>>(
        attTh, attTl, woTh, woTl, nullptr, lat, lat, nullptr, nullptr, cHHD,
        cD, cD, 0);

    // MLP
    ln_tiled_kernel<<<cML, 256>>>(lat, lnTh, lnTl);
    wprep_tiled_kernel<<<cI, 256>>>(Wfc_i, mlp_g + i * cD, mlp_b + i * cD,
                                    wfcTh, wfcTl, bFc, cD, cI);
    mma_gemm_bulk<<<dim3(40, 16), 256, GB_SMEM>>>(
        lnTh, lnTl, wfcTh, wfcTl, bFc, nullptr, nullptr, mlpTh, mlpTl, cD, cI,
        cI, 1);
    wprep_tiled_kernel<<<cD, 256>>>(Wcp_i, nullptr, nullptr, wcpTh, wcpTl,
                                    nullptr, cI, cD);
    mma_gemm_bulk<<<dim3(10, 16), 256, GB_SMEM>>>(
        mlpTh, mlpTl, wcpTh, wcpTl, nullptr, lat, lat, nullptr, nullptr, cI,
        cD, cD, 0);
  }

  ln_rows_kernel<<<cML, 256>>>(lat, out, f_g, f_b);
}